// round 1
// baseline (speedup 1.0000x reference)
#include <cuda_runtime.h>
#include <math.h>

// Problem dims
#define BN 128
#define LN 512
#define DN 256
#define AN 64

// Output layout (concatenated, reference tuple order)
#define OFF_WQ  ((size_t)0)
#define OFF_WK  ((size_t)BN * LN * DN)                   // 16777216
#define OFF_QW  ((size_t)2 * BN * LN * DN)               // 33554432
#define OFF_KW  (OFF_QW + (size_t)BN * LN)               // 33619968

// -------- scratch (device globals; no allocation allowed) --------
__device__ float g_rel[(size_t)BN * LN * LN];    // 134 MB  tanh(Qw @ K^T)
__device__ float g_Qw[(size_t)BN * LN * DN];     // 67 MB   Q @ W_rel
__device__ float g_qproj[(size_t)BN * LN * AN];  // 16.8 MB
__device__ float g_kproj[(size_t)BN * LN * AN];  // 16.8 MB
__device__ float g_logit_q[BN * LN];
__device__ float g_logit_k[BN * LN];

// ============================================================================
// Generic NN GEMM: C[M,N] = A[M,K] @ B[K,N], 64x64 tile, 256 threads, 4x4/thr
// ============================================================================
__global__ void __launch_bounds__(256) gemm_nn_kernel(
    const float* __restrict__ A, const float* __restrict__ Bm,
    float* __restrict__ C, int M, int N, int K)
{
    __shared__ float As[16][65];   // As[k][m], transposed store (pad: conflict-free)
    __shared__ float Bs[16][64];   // Bs[k][n], direct store

    const int m0 = blockIdx.x * 64, n0 = blockIdx.y * 64;
    const int tid = threadIdx.x;
    const int tx = tid & 15, ty = tid >> 4;
    const int ar = tid >> 2,  ac = (tid & 3) * 4;   // A loader: 64 rows x 16 k
    const int br = tid >> 4,  bc = (tid & 15) * 4;  // B loader: 16 k x 64 cols

    float acc[4][4] = {};
    for (int kt = 0; kt < K; kt += 16) {
        float4 av = *(const float4*)(A + (size_t)(m0 + ar) * K + kt + ac);
        As[ac + 0][ar] = av.x; As[ac + 1][ar] = av.y;
        As[ac + 2][ar] = av.z; As[ac + 3][ar] = av.w;
        float4 bv = *(const float4*)(Bm + (size_t)(kt + br) * N + n0 + bc);
        Bs[br][bc + 0] = bv.x; Bs[br][bc + 1] = bv.y;
        Bs[br][bc + 2] = bv.z; Bs[br][bc + 3] = bv.w;
        __syncthreads();
#pragma unroll
        for (int k = 0; k < 16; ++k) {
            float a[4], bb[4];
#pragma unroll
            for (int i = 0; i < 4; ++i) a[i] = As[k][ty * 4 + i];
#pragma unroll
            for (int j = 0; j < 4; ++j) bb[j] = Bs[k][tx + 16 * j];
#pragma unroll
            for (int i = 0; i < 4; ++i)
#pragma unroll
                for (int j = 0; j < 4; ++j)
                    acc[i][j] = fmaf(a[i], bb[j], acc[i][j]);
        }
        __syncthreads();
    }
#pragma unroll
    for (int i = 0; i < 4; ++i)
#pragma unroll
        for (int j = 0; j < 4; ++j)
            C[(size_t)(m0 + ty * 4 + i) * N + n0 + tx + 16 * j] = acc[i][j];
}

// ============================================================================
// rel[b] = tanh(Qw[b] @ K[b]^T)   (NT GEMM, batched, M=N=512, K=256)
// ============================================================================
__global__ void __launch_bounds__(256) rel_kernel(
    const float* __restrict__ Qw, const float* __restrict__ Kmat,
    float* __restrict__ Rel)
{
    __shared__ float As[16][65];
    __shared__ float Bs[16][65];

    const int b = blockIdx.z;
    const float* A  = Qw   + (size_t)b * LN * DN;
    const float* Bg = Kmat + (size_t)b * LN * DN;
    float*       C  = Rel  + (size_t)b * LN * LN;

    const int m0 = blockIdx.x * 64, n0 = blockIdx.y * 64;
    const int tid = threadIdx.x;
    const int tx = tid & 15, ty = tid >> 4;
    const int ar = tid >> 2, ac = (tid & 3) * 4;

    float acc[4][4] = {};
    for (int kt = 0; kt < DN; kt += 16) {
        float4 av = *(const float4*)(A + (size_t)(m0 + ar) * DN + kt + ac);
        As[ac + 0][ar] = av.x; As[ac + 1][ar] = av.y;
        As[ac + 2][ar] = av.z; As[ac + 3][ar] = av.w;
        float4 bv = *(const float4*)(Bg + (size_t)(n0 + ar) * DN + kt + ac);
        Bs[ac + 0][ar] = bv.x; Bs[ac + 1][ar] = bv.y;
        Bs[ac + 2][ar] = bv.z; Bs[ac + 3][ar] = bv.w;
        __syncthreads();
#pragma unroll
        for (int k = 0; k < 16; ++k) {
            float a[4], bb[4];
#pragma unroll
            for (int i = 0; i < 4; ++i) a[i] = As[k][ty * 4 + i];
#pragma unroll
            for (int j = 0; j < 4; ++j) bb[j] = Bs[k][tx + 16 * j];
#pragma unroll
            for (int i = 0; i < 4; ++i)
#pragma unroll
                for (int j = 0; j < 4; ++j)
                    acc[i][j] = fmaf(a[i], bb[j], acc[i][j]);
        }
        __syncthreads();
    }
#pragma unroll
    for (int i = 0; i < 4; ++i)
#pragma unroll
        for (int j = 0; j < 4; ++j)
            C[(size_t)(m0 + ty * 4 + i) * LN + n0 + tx + 16 * j] = tanhf(acc[i][j]);
}

// ============================================================================
// Fused attention-score GEMM + tanh + @W_att + row-reduce:
//   TRANSA=false: logit_q[b,m] = sum_n tanh(q_proj[m,n] + (rel @ k_proj)[m,n]) * Wqa[n]
//   TRANSA=true : logit_k[b,m] = sum_n tanh(k_proj[m,n] + (rel^T @ q_proj)[m,n]) * Wka[n]
// Tile: 64 rows x full N=64, K=512 in chunks of 16.
// ============================================================================
template <bool TRANSA>
__global__ void __launch_bounds__(256) att_kernel(
    const float* __restrict__ Rel, const float* __restrict__ Bproj,
    const float* __restrict__ AddProj, const float* __restrict__ watt,
    float* __restrict__ logit)
{
    __shared__ float As[16][65];
    __shared__ float Bs[16][64];
    __shared__ float red[64][17];

    const int b = blockIdx.y;
    const int m0 = blockIdx.x * 64;
    const float* R  = Rel     + (size_t)b * LN * LN;
    const float* Bp = Bproj   + (size_t)b * LN * AN;
    const float* Ap = AddProj + (size_t)b * LN * AN;

    const int tid = threadIdx.x;
    const int tx = tid & 15, ty = tid >> 4;
    const int ar = tid >> 2, ac = (tid & 3) * 4;
    const int br = tid >> 4, bc = (tid & 15) * 4;

    float acc[4][4] = {};
    for (int kt = 0; kt < LN; kt += 16) {
        if (!TRANSA) {
            // As[k][m] = R[m0+ar][kt+k]
            float4 av = *(const float4*)(R + (size_t)(m0 + ar) * LN + kt + ac);
            As[ac + 0][ar] = av.x; As[ac + 1][ar] = av.y;
            As[ac + 2][ar] = av.z; As[ac + 3][ar] = av.w;
        } else {
            // As[k][m] = R[kt+k][m0+m]
            float4 av = *(const float4*)(R + (size_t)(kt + br) * LN + m0 + bc);
            As[br][bc + 0] = av.x; As[br][bc + 1] = av.y;
            As[br][bc + 2] = av.z; As[br][bc + 3] = av.w;
        }
        float4 bv = *(const float4*)(Bp + (size_t)(kt + br) * AN + bc);
        Bs[br][bc + 0] = bv.x; Bs[br][bc + 1] = bv.y;
        Bs[br][bc + 2] = bv.z; Bs[br][bc + 3] = bv.w;
        __syncthreads();
#pragma unroll
        for (int k = 0; k < 16; ++k) {
            float a[4], bb[4];
#pragma unroll
            for (int i = 0; i < 4; ++i) a[i] = As[k][ty * 4 + i];
#pragma unroll
            for (int j = 0; j < 4; ++j) bb[j] = Bs[k][tx + 16 * j];
#pragma unroll
            for (int i = 0; i < 4; ++i)
#pragma unroll
                for (int j = 0; j < 4; ++j)
                    acc[i][j] = fmaf(a[i], bb[j], acc[i][j]);
        }
        __syncthreads();
    }

    // fused epilogue: tanh(add + acc) dot watt, reduce over n
    const float w0 = watt[tx], w1 = watt[tx + 16], w2 = watt[tx + 32], w3 = watt[tx + 48];
#pragma unroll
    for (int i = 0; i < 4; ++i) {
        const int m = m0 + ty * 4 + i;
        const float* addr = Ap + (size_t)m * AN;
        float s = tanhf(acc[i][0] + addr[tx])      * w0
                + tanhf(acc[i][1] + addr[tx + 16]) * w1
                + tanhf(acc[i][2] + addr[tx + 32]) * w2
                + tanhf(acc[i][3] + addr[tx + 48]) * w3;
        red[ty * 4 + i][tx] = s;
    }
    __syncthreads();
    if (tid < 64) {
        float s = 0.f;
#pragma unroll
        for (int t = 0; t < 16; ++t) s += red[tid][t];
        logit[b * LN + m0 + tid] = s;
    }
}

// ============================================================================
// Softmax over L=512 per batch; writes q_att_w / k_att_w directly into d_out
// ============================================================================
__global__ void __launch_bounds__(512) softmax_kernel(
    const float* __restrict__ lq, const float* __restrict__ lk,
    float* __restrict__ out)
{
    __shared__ float red[512];
    const int b = blockIdx.x, sel = blockIdx.y, t = threadIdx.x;
    const float* l = (sel ? lk : lq) + (size_t)b * LN;
    float* o = out + (sel ? OFF_KW : OFF_QW) + (size_t)b * LN;

    float v = l[t];
    red[t] = v; __syncthreads();
    for (int s = 256; s > 0; s >>= 1) {
        if (t < s) red[t] = fmaxf(red[t], red[t + s]);
        __syncthreads();
    }
    const float mx = red[0];
    __syncthreads();
    const float e = expf(v - mx);
    red[t] = e; __syncthreads();
    for (int s = 256; s > 0; s >>= 1) {
        if (t < s) red[t] += red[t + s];
        __syncthreads();
    }
    o[t] = e / red[0];
}

// ============================================================================
// weighted_queries / weighted_keys (reads weights back from d_out regions)
// ============================================================================
__global__ void __launch_bounds__(256) scale_kernel(
    const float* __restrict__ Q, const float* __restrict__ Kmat,
    float* __restrict__ out)
{
    const int sel = blockIdx.y;
    const size_t i4 = (size_t)blockIdx.x * 256 + threadIdx.x;  // per float4
    const float4* src = (const float4*)(sel ? Kmat : Q);
    const float*  w   = out + (sel ? OFF_KW : OFF_QW);
    float4*       dst = (float4*)(out + (sel ? OFF_WK : OFF_WQ));

    const size_t e = i4 * 4;
    const int b = (int)(e >> 17);          // / (512*256)
    const int l = (int)((e >> 8) & 511);   // / 256 % 512
    const float s = w[b * LN + l];
    float4 v = src[i4];
    v.x *= s; v.y *= s; v.z *= s; v.w *= s;
    dst[i4] = v;
}

// ============================================================================
extern "C" void kernel_launch(void* const* d_in, const int* in_sizes, int n_in,
                              void* d_out, int out_size)
{
    (void)in_sizes; (void)n_in; (void)out_size;
    const float* Q    = (const float*)d_in[0];
    const float* Km   = (const float*)d_in[1];
    const float* Wrel = (const float*)d_in[2];
    const float* Wq   = (const float*)d_in[3];
    const float* Wk   = (const float*)d_in[4];
    const float* Wqa  = (const float*)d_in[5];
    const float* Wka  = (const float*)d_in[6];
    float* out = (float*)d_out;

    float *rel, *qw, *qp, *kp, *lq, *lk;
    cudaGetSymbolAddress((void**)&rel, g_rel);
    cudaGetSymbolAddress((void**)&qw,  g_Qw);
    cudaGetSymbolAddress((void**)&qp,  g_qproj);
    cudaGetSymbolAddress((void**)&kp,  g_kproj);
    cudaGetSymbolAddress((void**)&lq,  g_logit_q);
    cudaGetSymbolAddress((void**)&lk,  g_logit_k);

    const dim3 blk(256);
    // Projections (treat [B,L,*] as [B*L, *])
    gemm_nn_kernel<<<dim3(1024, 4), blk>>>(Q,  Wrel, qw, BN * LN, DN, DN);
    gemm_nn_kernel<<<dim3(1024, 1), blk>>>(Q,  Wq,   qp, BN * LN, AN, DN);
    gemm_nn_kernel<<<dim3(1024, 1), blk>>>(Km, Wk,   kp, BN * LN, AN, DN);
    // rel = tanh(Qw @ K^T)
    rel_kernel<<<dim3(8, 8, BN), blk>>>(qw, Km, rel);
    // fused score GEMMs -> logits
    att_kernel<false><<<dim3(8, BN), blk>>>(rel, kp, qp, Wqa, lq);
    att_kernel<true ><<<dim3(8, BN), blk>>>(rel, qp, kp, Wka, lk);
    // softmax -> weights in d_out
    softmax_kernel<<<dim3(BN, 2), 512>>>(lq, lk, out);
    // weighted outputs
    scale_kernel<<<dim3((BN * LN * DN) / 4 / 256, 2), 256>>>(Q, Km, out);
}

// round 3
// speedup vs baseline: 1.5284x; 1.5284x over previous
#include <cuda_runtime.h>
#include <cuda_bf16.h>
#include <math.h>
#include <stdint.h>

// Problem dims
#define BN 128
#define LN 512
#define DN 256
#define AN 64
#define KP 768   // split-K': [hi | lo | hi] x 256

// Output layout (concatenated, reference tuple order)
#define OFF_WQ  ((size_t)0)
#define OFF_WK  ((size_t)BN * LN * DN)
#define OFF_QW  ((size_t)2 * BN * LN * DN)
#define OFF_KW  (OFF_QW + (size_t)BN * LN)

// -------- scratch (device globals; no allocation allowed) --------
__device__ float g_rel[(size_t)BN * LN * LN];            // 134 MB  tanh(Qw @ K^T)
__device__ __nv_bfloat16 g_Q2 [(size_t)BN * LN * KP];    // 100 MB  [hi|lo|hi] of Q
__device__ __nv_bfloat16 g_K2 [(size_t)BN * LN * KP];    // 100 MB  [hi|hi|lo] of K
__device__ __nv_bfloat16 g_Qw2[(size_t)BN * LN * KP];    // 100 MB  [hi|lo|hi] of Qw
__device__ __nv_bfloat16 g_W2t[(size_t)DN * KP];         // W_rel^T split [hi|hi|lo]
__device__ float g_qproj[(size_t)BN * LN * AN];
__device__ float g_kproj[(size_t)BN * LN * AN];
__device__ float g_logit_q[BN * LN];
__device__ float g_logit_k[BN * LN];

// ======================= helpers (baseline PTX only) =======================
__device__ __forceinline__ uint32_t smem_to_u32(const void* p) {
    uint32_t a;
    asm("{ .reg .u64 t; cvta.to.shared.u64 t, %1; cvt.u32.u64 %0, t; }" : "=r"(a) : "l"(p));
    return a;
}
#define SMEM_SWIZZLE_128B(o) ((o) ^ (((o) >> 3) & 0x70))

__device__ __forceinline__ void cp_async16(uint32_t saddr, const void* g) {
    asm volatile("cp.async.cg.shared.global [%0], [%1], 16;" :: "r"(saddr), "l"(g));
}
#define CP_COMMIT  asm volatile("cp.async.commit_group;" ::: "memory")
#define CP_WAIT(n) asm volatile("cp.async.wait_group %0;" :: "n"(n) : "memory")

__device__ __forceinline__ void ldmatrix_x4(uint32_t& r0, uint32_t& r1, uint32_t& r2,
                                            uint32_t& r3, uint32_t addr) {
    asm volatile("ldmatrix.sync.aligned.m8n8.x4.shared.b16 {%0,%1,%2,%3}, [%4];"
                 : "=r"(r0), "=r"(r1), "=r"(r2), "=r"(r3) : "r"(addr));
}
__device__ __forceinline__ void mma_bf16(float* c, uint32_t a0, uint32_t a1, uint32_t a2,
                                         uint32_t a3, uint32_t b0, uint32_t b1) {
    asm volatile(
        "mma.sync.aligned.m16n8k16.row.col.f32.bf16.bf16.f32 "
        "{%0,%1,%2,%3}, {%4,%5,%6,%7}, {%8,%9}, {%0,%1,%2,%3};"
        : "+f"(c[0]), "+f"(c[1]), "+f"(c[2]), "+f"(c[3])
        : "r"(a0), "r"(a1), "r"(a2), "r"(a3), "r"(b0), "r"(b1));
}

__device__ __forceinline__ void split2(float x, __nv_bfloat16& hi, __nv_bfloat16& lo) {
    hi = __float2bfloat16(x);
    lo = __float2bfloat16(x - __bfloat162float(hi));
}

// ======================= warp-MMA mainloop (128x128 tile) =======================
// A, B row-major [*, KP] bf16 (NT gemm). 256 threads = 8 warps, warp tile 64x32.
// Smem: double-buffered A(16KB)+B(16KB) per stage; KP/64 = 12 stages.
#define NSTAGE  12
#define STAGE_BYTES 32768
#define SMEM_MMA (2 * STAGE_BYTES)

__device__ __forceinline__ void load_stage(uint32_t sbase,
    const __nv_bfloat16* __restrict__ A, const __nv_bfloat16* __restrict__ B,
    int s, int tid)
{
    const __nv_bfloat16* Ak = A + s * 64;
    const __nv_bfloat16* Bk = B + s * 64;
#pragma unroll
    for (int i = 0; i < 4; ++i) {
        const int idx = tid + i * 256;            // 0..1023 16B chunks
        const int r = idx >> 3, c = idx & 7;
        const uint32_t off = SMEM_SWIZZLE_128B((uint32_t)(r * 128 + c * 16));
        cp_async16(sbase + off, Ak + (size_t)r * KP + c * 8);
        cp_async16(sbase + 16384 + off, Bk + (size_t)r * KP + c * 8);
    }
}

__device__ __forceinline__ void warp_mma_main(
    const __nv_bfloat16* __restrict__ A, const __nv_bfloat16* __restrict__ B,
    uint32_t smem_base, int tid, float acc[4][4][4])
{
    const int wid = tid >> 5, lane = tid & 31;
    const int mw = (wid >> 2) * 64, nw = (wid & 3) * 32;

    load_stage(smem_base, A, B, 0, tid);
    CP_COMMIT;

    int buf = 0;
    for (int s = 0; s < NSTAGE; ++s) {
        if (s + 1 < NSTAGE) {
            load_stage(smem_base + (buf ^ 1) * STAGE_BYTES, A, B, s + 1, tid);
            CP_COMMIT;
            CP_WAIT(1);
        } else {
            CP_COMMIT;
            CP_WAIT(0);
        }
        __syncthreads();

        const uint32_t sA = smem_base + buf * STAGE_BYTES;
        const uint32_t sB = sA + 16384;
#pragma unroll
        for (int kk = 0; kk < 64; kk += 16) {
            uint32_t a[4][4], b[4][2];
#pragma unroll
            for (int mf = 0; mf < 4; ++mf) {
                const uint32_t off = SMEM_SWIZZLE_128B((uint32_t)(
                    (mw + mf * 16 + (lane & 15)) * 128 + kk * 2 + ((lane >> 4) << 4)));
                ldmatrix_x4(a[mf][0], a[mf][1], a[mf][2], a[mf][3], sA + off);
            }
#pragma unroll
            for (int nb = 0; nb < 2; ++nb) {
                const int row = nw + nb * 16 + ((lane >> 4) & 1) * 8 + (lane & 7);
                const int kof = kk * 2 + (((lane >> 3) & 1) << 4);
                const uint32_t off = SMEM_SWIZZLE_128B((uint32_t)(row * 128 + kof));
                ldmatrix_x4(b[nb * 2][0], b[nb * 2][1], b[nb * 2 + 1][0], b[nb * 2 + 1][1],
                            sB + off);
            }
#pragma unroll
            for (int mf = 0; mf < 4; ++mf)
#pragma unroll
                for (int nf = 0; nf < 4; ++nf)
                    mma_bf16(acc[mf][nf], a[mf][0], a[mf][1], a[mf][2], a[mf][3],
                             b[nf][0], b[nf][1]);
        }
        __syncthreads();
        buf ^= 1;
    }
}

// ======================= rel = tanh(Qw2 @ K2^T) =======================
__global__ void __launch_bounds__(256, 1) rel_mma_kernel(
    const __nv_bfloat16* __restrict__ Qw2, const __nv_bfloat16* __restrict__ K2,
    float* __restrict__ Rel)
{
    extern __shared__ char smem[];
    const uint32_t smem_base = smem_to_u32(smem);
    const int tid = threadIdx.x;
    const int b = blockIdx.z, m0 = blockIdx.x * 128, n0 = blockIdx.y * 128;
    const __nv_bfloat16* A  = Qw2 + ((size_t)b * LN + m0) * KP;
    const __nv_bfloat16* Bp = K2  + ((size_t)b * LN + n0) * KP;

    float acc[4][4][4] = {};
    warp_mma_main(A, Bp, smem_base, tid, acc);

    const int wid = tid >> 5, lane = tid & 31;
    const int mw = (wid >> 2) * 64, nw = (wid & 3) * 32;
    const int lr = lane >> 2, lc = (lane & 3) * 2;
    float* C = Rel + (size_t)b * LN * LN;
#pragma unroll
    for (int mf = 0; mf < 4; ++mf) {
        const int row = m0 + mw + mf * 16 + lr;
#pragma unroll
        for (int nf = 0; nf < 4; ++nf) {
            const int col = n0 + nw + nf * 8 + lc;
            float2 v0 = { tanhf(acc[mf][nf][0]), tanhf(acc[mf][nf][1]) };
            *(float2*)(C + (size_t)row * LN + col) = v0;
            float2 v1 = { tanhf(acc[mf][nf][2]), tanhf(acc[mf][nf][3]) };
            *(float2*)(C + (size_t)(row + 8) * LN + col) = v1;
        }
    }
}

// ======================= Qw2 = split(Q2 @ W2t^T) =======================
__global__ void __launch_bounds__(256, 1) qw_mma_kernel(
    const __nv_bfloat16* __restrict__ Q2, const __nv_bfloat16* __restrict__ W2t,
    __nv_bfloat16* __restrict__ Qw2)
{
    extern __shared__ char smem[];
    const uint32_t smem_base = smem_to_u32(smem);
    const int tid = threadIdx.x;
    const int m0 = blockIdx.x * 128, n0 = blockIdx.y * 128;
    const __nv_bfloat16* A  = Q2  + (size_t)m0 * KP;
    const __nv_bfloat16* Bp = W2t + (size_t)n0 * KP;

    float acc[4][4][4] = {};
    warp_mma_main(A, Bp, smem_base, tid, acc);

    const int wid = tid >> 5, lane = tid & 31;
    const int mw = (wid >> 2) * 64, nw = (wid & 3) * 32;
    const int lr = lane >> 2, lc = (lane & 3) * 2;
#pragma unroll
    for (int mf = 0; mf < 4; ++mf) {
        const int row = m0 + mw + mf * 16 + lr;
#pragma unroll
        for (int nf = 0; nf < 4; ++nf) {
            const int col = n0 + nw + nf * 8 + lc;
#pragma unroll
            for (int p = 0; p < 2; ++p) {
                const int rr = row + p * 8;
                union { __nv_bfloat16 b[2]; uint32_t u; } H, L;
                split2(acc[mf][nf][2 * p + 0], H.b[0], L.b[0]);
                split2(acc[mf][nf][2 * p + 1], H.b[1], L.b[1]);
                __nv_bfloat16* o = Qw2 + (size_t)rr * KP + col;
                *(uint32_t*)(o)       = H.u;   // hi  @ [0,256)
                *(uint32_t*)(o + 256) = L.u;   // lo  @ [256,512)
                *(uint32_t*)(o + 512) = H.u;   // hi  @ [512,768)
            }
        }
    }
}

// ======================= split / prep kernels =======================
// Q -> [hi|lo|hi], K -> [hi|hi|lo]
__global__ void __launch_bounds__(256) split_kernel(
    const float* __restrict__ Q, const float* __restrict__ Kmat,
    __nv_bfloat16* __restrict__ Q2, __nv_bfloat16* __restrict__ K2)
{
    const int sel = blockIdx.y;
    const float* src = sel ? Kmat : Q;
    __nv_bfloat16* dst = sel ? K2 : Q2;
    const size_t i4 = (size_t)blockIdx.x * 256 + threadIdx.x;
    const size_t row = i4 >> 6;
    const int c = (int)(i4 & 63) * 4;
    float4 v = ((const float4*)src)[i4];
    union { __nv_bfloat16 b[4]; uint2 u; } h, l;
    split2(v.x, h.b[0], l.b[0]); split2(v.y, h.b[1], l.b[1]);
    split2(v.z, h.b[2], l.b[2]); split2(v.w, h.b[3], l.b[3]);
    __nv_bfloat16* o = dst + row * KP + c;
    *(uint2*)(o) = h.u;
    if (sel == 0) { *(uint2*)(o + 256) = l.u; *(uint2*)(o + 512) = h.u; }
    else          { *(uint2*)(o + 256) = h.u; *(uint2*)(o + 512) = l.u; }
}

// W_rel[d][n] -> W2t[n][k'] with pattern [hi|hi|lo]
__global__ void __launch_bounds__(256) prep_w2t(
    const float* __restrict__ Wrel, __nv_bfloat16* __restrict__ W2t)
{
    const int idx = blockIdx.x * 256 + threadIdx.x;   // 65536
    const int d = idx >> 8, n = idx & 255;
    __nv_bfloat16 hi, lo;
    split2(Wrel[d * 256 + n], hi, lo);
    W2t[(size_t)n * KP + d]       = hi;
    W2t[(size_t)n * KP + 256 + d] = hi;
    W2t[(size_t)n * KP + 512 + d] = lo;
}

// ============================================================================
// FFMA NN GEMM (small A=64 projections)
// ============================================================================
__global__ void __launch_bounds__(256) gemm_nn_kernel(
    const float* __restrict__ A, const float* __restrict__ Bm,
    float* __restrict__ C, int M, int N, int K)
{
    __shared__ float As[16][65];
    __shared__ float Bs[16][64];

    const int m0 = blockIdx.x * 64, n0 = blockIdx.y * 64;
    const int tid = threadIdx.x;
    const int tx = tid & 15, ty = tid >> 4;
    const int ar = tid >> 2,  ac = (tid & 3) * 4;
    const int br = tid >> 4,  bc = (tid & 15) * 4;

    float acc[4][4] = {};
    for (int kt = 0; kt < K; kt += 16) {
        float4 av = *(const float4*)(A + (size_t)(m0 + ar) * K + kt + ac);
        As[ac + 0][ar] = av.x; As[ac + 1][ar] = av.y;
        As[ac + 2][ar] = av.z; As[ac + 3][ar] = av.w;
        float4 bv = *(const float4*)(Bm + (size_t)(kt + br) * N + n0 + bc);
        Bs[br][bc + 0] = bv.x; Bs[br][bc + 1] = bv.y;
        Bs[br][bc + 2] = bv.z; Bs[br][bc + 3] = bv.w;
        __syncthreads();
#pragma unroll
        for (int k = 0; k < 16; ++k) {
            float a[4], bb[4];
#pragma unroll
            for (int i = 0; i < 4; ++i) a[i] = As[k][ty * 4 + i];
#pragma unroll
            for (int j = 0; j < 4; ++j) bb[j] = Bs[k][tx + 16 * j];
#pragma unroll
            for (int i = 0; i < 4; ++i)
#pragma unroll
                for (int j = 0; j < 4; ++j)
                    acc[i][j] = fmaf(a[i], bb[j], acc[i][j]);
        }
        __syncthreads();
    }
#pragma unroll
    for (int i = 0; i < 4; ++i)
#pragma unroll
        for (int j = 0; j < 4; ++j)
            C[(size_t)(m0 + ty * 4 + i) * N + n0 + tx + 16 * j] = acc[i][j];
}

// ============================================================================
// Fused attention-score GEMM + tanh + @W_att + row-reduce
// ============================================================================
template <bool TRANSA>
__global__ void __launch_bounds__(256) att_kernel(
    const float* __restrict__ Rel, const float* __restrict__ Bproj,
    const float* __restrict__ AddProj, const float* __restrict__ watt,
    float* __restrict__ logit)
{
    __shared__ float As[16][65];
    __shared__ float Bs[16][64];
    __shared__ float red[64][17];

    const int b = blockIdx.y;
    const int m0 = blockIdx.x * 64;
    const float* R  = Rel     + (size_t)b * LN * LN;
    const float* Bp = Bproj   + (size_t)b * LN * AN;
    const float* Ap = AddProj + (size_t)b * LN * AN;

    const int tid = threadIdx.x;
    const int tx = tid & 15, ty = tid >> 4;
    const int ar = tid >> 2, ac = (tid & 3) * 4;
    const int br = tid >> 4, bc = (tid & 15) * 4;

    float acc[4][4] = {};
    for (int kt = 0; kt < LN; kt += 16) {
        if (!TRANSA) {
            float4 av = *(const float4*)(R + (size_t)(m0 + ar) * LN + kt + ac);
            As[ac + 0][ar] = av.x; As[ac + 1][ar] = av.y;
            As[ac + 2][ar] = av.z; As[ac + 3][ar] = av.w;
        } else {
            float4 av = *(const float4*)(R + (size_t)(kt + br) * LN + m0 + bc);
            As[br][bc + 0] = av.x; As[br][bc + 1] = av.y;
            As[br][bc + 2] = av.z; As[br][bc + 3] = av.w;
        }
        float4 bv = *(const float4*)(Bp + (size_t)(kt + br) * AN + bc);
        Bs[br][bc + 0] = bv.x; Bs[br][bc + 1] = bv.y;
        Bs[br][bc + 2] = bv.z; Bs[br][bc + 3] = bv.w;
        __syncthreads();
#pragma unroll
        for (int k = 0; k < 16; ++k) {
            float a[4], bb[4];
#pragma unroll
            for (int i = 0; i < 4; ++i) a[i] = As[k][ty * 4 + i];
#pragma unroll
            for (int j = 0; j < 4; ++j) bb[j] = Bs[k][tx + 16 * j];
#pragma unroll
            for (int i = 0; i < 4; ++i)
#pragma unroll
                for (int j = 0; j < 4; ++j)
                    acc[i][j] = fmaf(a[i], bb[j], acc[i][j]);
        }
        __syncthreads();
    }

    const float w0 = watt[tx], w1 = watt[tx + 16], w2 = watt[tx + 32], w3 = watt[tx + 48];
#pragma unroll
    for (int i = 0; i < 4; ++i) {
        const int m = m0 + ty * 4 + i;
        const float* addr = Ap + (size_t)m * AN;
        float s = tanhf(acc[i][0] + addr[tx])      * w0
                + tanhf(acc[i][1] + addr[tx + 16]) * w1
                + tanhf(acc[i][2] + addr[tx + 32]) * w2
                + tanhf(acc[i][3] + addr[tx + 48]) * w3;
        red[ty * 4 + i][tx] = s;
    }
    __syncthreads();
    if (tid < 64) {
        float s = 0.f;
#pragma unroll
        for (int t = 0; t < 16; ++t) s += red[tid][t];
        logit[b * LN + m0 + tid] = s;
    }
}

// ============================================================================
__global__ void __launch_bounds__(512) softmax_kernel(
    const float* __restrict__ lq, const float* __restrict__ lk,
    float* __restrict__ out)
{
    __shared__ float red[512];
    const int b = blockIdx.x, sel = blockIdx.y, t = threadIdx.x;
    const float* l = (sel ? lk : lq) + (size_t)b * LN;
    float* o = out + (sel ? OFF_KW : OFF_QW) + (size_t)b * LN;

    float v = l[t];
    red[t] = v; __syncthreads();
    for (int s = 256; s > 0; s >>= 1) {
        if (t < s) red[t] = fmaxf(red[t], red[t + s]);
        __syncthreads();
    }
    const float mx = red[0];
    __syncthreads();
    const float e = expf(v - mx);
    red[t] = e; __syncthreads();
    for (int s = 256; s > 0; s >>= 1) {
        if (t < s) red[t] += red[t + s];
        __syncthreads();
    }
    o[t] = e / red[0];
}

__global__ void __launch_bounds__(256) scale_kernel(
    const float* __restrict__ Q, const float* __restrict__ Kmat,
    float* __restrict__ out)
{
    const int sel = blockIdx.y;
    const size_t i4 = (size_t)blockIdx.x * 256 + threadIdx.x;
    const float4* src = (const float4*)(sel ? Kmat : Q);
    const float*  w   = out + (sel ? OFF_KW : OFF_QW);
    float4*       dst = (float4*)(out + (sel ? OFF_WK : OFF_WQ));

    const size_t e = i4 * 4;
    const int b = (int)(e >> 17);
    const int l = (int)((e >> 8) & 511);
    const float s = w[b * LN + l];
    float4 v = src[i4];
    v.x *= s; v.y *= s; v.z *= s; v.w *= s;
    dst[i4] = v;
}

// ============================================================================
extern "C" void kernel_launch(void* const* d_in, const int* in_sizes, int n_in,
                              void* d_out, int out_size)
{
    (void)in_sizes; (void)n_in; (void)out_size;
    const float* Q    = (const float*)d_in[0];
    const float* Km   = (const float*)d_in[1];
    const float* Wrel = (const float*)d_in[2];
    const float* Wq   = (const float*)d_in[3];
    const float* Wk   = (const float*)d_in[4];
    const float* Wqa  = (const float*)d_in[5];
    const float* Wka  = (const float*)d_in[6];
    float* out = (float*)d_out;

    float *rel, *qp, *kp, *lq, *lk;
    __nv_bfloat16 *q2, *k2, *qw2, *w2t;
    cudaGetSymbolAddress((void**)&rel, g_rel);
    cudaGetSymbolAddress((void**)&q2,  g_Q2);
    cudaGetSymbolAddress((void**)&k2,  g_K2);
    cudaGetSymbolAddress((void**)&qw2, g_Qw2);
    cudaGetSymbolAddress((void**)&w2t, g_W2t);
    cudaGetSymbolAddress((void**)&qp,  g_qproj);
    cudaGetSymbolAddress((void**)&kp,  g_kproj);
    cudaGetSymbolAddress((void**)&lq,  g_logit_q);
    cudaGetSymbolAddress((void**)&lk,  g_logit_k);

    cudaFuncSetAttribute(rel_mma_kernel, cudaFuncAttributeMaxDynamicSharedMemorySize, SMEM_MMA);
    cudaFuncSetAttribute(qw_mma_kernel,  cudaFuncAttributeMaxDynamicSharedMemorySize, SMEM_MMA);

    const dim3 blk(256);
    // bf16 hi/lo splits of inputs + W_rel^T
    split_kernel<<<dim3((BN * LN * DN) / 4 / 256, 2), blk>>>(Q, Km, q2, k2);
    prep_w2t<<<256, blk>>>(Wrel, w2t);
    // small projections (FFMA)
    gemm_nn_kernel<<<dim3(1024, 1), blk>>>(Q,  Wq, qp, BN * LN, AN, DN);
    gemm_nn_kernel<<<dim3(1024, 1), blk>>>(Km, Wk, kp, BN * LN, AN, DN);
    // Qw (warp MMA, epilogue re-splits to bf16 hi/lo)
    qw_mma_kernel<<<dim3(512, 2), 256, SMEM_MMA>>>(q2, w2t, qw2);
    // rel = tanh(Qw @ K^T) (warp MMA)
    rel_mma_kernel<<<dim3(4, 4, BN), 256, SMEM_MMA>>>(qw2, k2, rel);
    // fused score GEMMs -> logits
    att_kernel<false><<<dim3(8, BN), blk>>>(rel, kp, qp, Wqa, lq);
    att_kernel<true ><<<dim3(8, BN), blk>>>(rel, qp, kp, Wka, lk);
    // softmax -> weights in d_out
    softmax_kernel<<<dim3(BN, 2), 512>>>(lq, lk, out);
    // weighted outputs
    scale_kernel<<<dim3((BN * LN * DN) / 4 / 256, 2), 256>>>(Q, Km, out);
}

// round 7
// speedup vs baseline: 2.0508x; 1.3418x over previous
#include <cuda_runtime.h>
#include <cuda_bf16.h>
#include <math.h>
#include <stdint.h>

// Problem dims
#define BN 128
#define LN 512
#define DN 256
#define AN 64
#define KP 768   // split-K': 3 x 256  (A [hi|lo|hi] x B [hi|hi|lo])

// Output layout (concatenated, reference tuple order)
#define OFF_WQ  ((size_t)0)
#define OFF_WK  ((size_t)BN * LN * DN)
#define OFF_QW  ((size_t)2 * BN * LN * DN)
#define OFF_KW  (OFF_QW + (size_t)BN * LN)

// -------- scratch (device globals; no allocation allowed) --------
__device__ __nv_bfloat16 g_Q2 [(size_t)BN * LN * KP];    // [hi|lo|hi] of Q
__device__ __nv_bfloat16 g_K2 [(size_t)BN * LN * KP];    // [hi|hi|lo] of K
__device__ __nv_bfloat16 g_Qw2[(size_t)BN * LN * KP];    // [hi|lo|hi] of Qw
__device__ __nv_bfloat16 g_W2t[(size_t)DN * KP];         // W_rel^T split [hi|hi|lo]
__device__ __nv_bfloat16 g_Wp2t[2 * 128 * KP];           // padded Wq^T / Wk^T splits (zero-init)
__device__ float g_qpf[(size_t)BN * LN * AN];            // q_proj fp32
__device__ float g_kpf[(size_t)BN * LN * AN];            // k_proj fp32
__device__ __nv_bfloat16 g_qph[(size_t)BN * LN * AN], g_qpl[(size_t)BN * LN * AN];
__device__ __nv_bfloat16 g_kph[(size_t)BN * LN * AN], g_kpl[(size_t)BN * LN * AN];
__device__ float g_partQ[(size_t)4 * BN * LN * AN];      // rel@kp partials (per n-tile)
__device__ float g_partK[(size_t)4 * BN * LN * AN];      // relT@qp partials (per m-tile)
__device__ float g_logit_q[BN * LN];
__device__ float g_logit_k[BN * LN];

// ======================= helpers (baseline PTX only) =======================
__device__ __forceinline__ uint32_t smem_to_u32(const void* p) {
    uint32_t a;
    asm("{ .reg .u64 t; cvta.to.shared.u64 t, %1; cvt.u32.u64 %0, t; }" : "=r"(a) : "l"(p));
    return a;
}
#define SMEM_SWIZZLE_128B(o) ((o) ^ (((o) >> 3) & 0x70))

__device__ __forceinline__ void cp_async16(uint32_t saddr, const void* g) {
    asm volatile("cp.async.cg.shared.global [%0], [%1], 16;" :: "r"(saddr), "l"(g));
}
#define CP_COMMIT  asm volatile("cp.async.commit_group;" ::: "memory")
#define CP_WAIT(n) asm volatile("cp.async.wait_group %0;" :: "n"(n) : "memory")

__device__ __forceinline__ void ldmatrix_x4(uint32_t& r0, uint32_t& r1, uint32_t& r2,
                                            uint32_t& r3, uint32_t addr) {
    asm volatile("ldmatrix.sync.aligned.m8n8.x4.shared.b16 {%0,%1,%2,%3}, [%4];"
                 : "=r"(r0), "=r"(r1), "=r"(r2), "=r"(r3) : "r"(addr));
}
__device__ __forceinline__ void ldmatrix_x4_trans(uint32_t& r0, uint32_t& r1, uint32_t& r2,
                                                  uint32_t& r3, uint32_t addr) {
    asm volatile("ldmatrix.sync.aligned.m8n8.x4.trans.shared.b16 {%0,%1,%2,%3}, [%4];"
                 : "=r"(r0), "=r"(r1), "=r"(r2), "=r"(r3) : "r"(addr));
}
__device__ __forceinline__ void mma_bf16(float* c, uint32_t a0, uint32_t a1, uint32_t a2,
                                         uint32_t a3, uint32_t b0, uint32_t b1) {
    asm volatile(
        "mma.sync.aligned.m16n8k16.row.col.f32.bf16.bf16.f32 "
        "{%0,%1,%2,%3}, {%4,%5,%6,%7}, {%8,%9}, {%0,%1,%2,%3};"
        : "+f"(c[0]), "+f"(c[1]), "+f"(c[2]), "+f"(c[3])
        : "r"(a0), "r"(a1), "r"(a2), "r"(a3), "r"(b0), "r"(b1));
}

__device__ __forceinline__ void split2(float x, __nv_bfloat16& hi, __nv_bfloat16& lo) {
    hi = __float2bfloat16(x);
    lo = __float2bfloat16(x - __bfloat162float(hi));
}
union BF2 { __nv_bfloat16 h[2]; uint32_t u; };

// ======================= warp-MMA mainloop (128x128 tile) =======================
#define NSTAGE  12
#define STAGE_BYTES 32768
#define SMEM_MMA (2 * STAGE_BYTES)

__device__ __forceinline__ void load_stage(uint32_t sbase,
    const __nv_bfloat16* __restrict__ A, const __nv_bfloat16* __restrict__ B,
    int s, int tid)
{
    const __nv_bfloat16* Ak = A + s * 64;
    const __nv_bfloat16* Bk = B + s * 64;
#pragma unroll
    for (int i = 0; i < 4; ++i) {
        const int idx = tid + i * 256;            // 0..1023 16B chunks
        const int r = idx >> 3, c = idx & 7;
        const uint32_t off = SMEM_SWIZZLE_128B((uint32_t)(r * 128 + c * 16));
        cp_async16(sbase + off, Ak + (size_t)r * KP + c * 8);
        cp_async16(sbase + 16384 + off, Bk + (size_t)r * KP + c * 8);
    }
}

__device__ __forceinline__ void warp_mma_main(
    const __nv_bfloat16* __restrict__ A, const __nv_bfloat16* __restrict__ B,
    uint32_t smem_base, int tid, float acc[4][4][4])
{
    const int wid = tid >> 5, lane = tid & 31;
    const int mw = (wid >> 2) * 64, nw = (wid & 3) * 32;

    load_stage(smem_base, A, B, 0, tid);
    CP_COMMIT;

    int buf = 0;
    for (int s = 0; s < NSTAGE; ++s) {
        if (s + 1 < NSTAGE) {
            load_stage(smem_base + (buf ^ 1) * STAGE_BYTES, A, B, s + 1, tid);
            CP_COMMIT;
            CP_WAIT(1);
        } else {
            CP_COMMIT;
            CP_WAIT(0);
        }
        __syncthreads();

        const uint32_t sA = smem_base + buf * STAGE_BYTES;
        const uint32_t sB = sA + 16384;
#pragma unroll
        for (int kk = 0; kk < 64; kk += 16) {
            uint32_t a[4][4], b[4][2];
#pragma unroll
            for (int mf = 0; mf < 4; ++mf) {
                const uint32_t off = SMEM_SWIZZLE_128B((uint32_t)(
                    (mw + mf * 16 + (lane & 15)) * 128 + kk * 2 + ((lane >> 4) << 4)));
                ldmatrix_x4(a[mf][0], a[mf][1], a[mf][2], a[mf][3], sA + off);
            }
#pragma unroll
            for (int nb = 0; nb < 2; ++nb) {
                const int row = nw + nb * 16 + ((lane >> 4) & 1) * 8 + (lane & 7);
                const int kof = kk * 2 + (((lane >> 3) & 1) << 4);
                const uint32_t off = SMEM_SWIZZLE_128B((uint32_t)(row * 128 + kof));
                ldmatrix_x4(b[nb * 2][0], b[nb * 2][1], b[nb * 2 + 1][0], b[nb * 2 + 1][1],
                            sB + off);
            }
#pragma unroll
            for (int mf = 0; mf < 4; ++mf)
#pragma unroll
                for (int nf = 0; nf < 4; ++nf)
                    mma_bf16(acc[mf][nf], a[mf][0], a[mf][1], a[mf][2], a[mf][3],
                             b[nf][0], b[nf][1]);
        }
        __syncthreads();
        buf ^= 1;
    }
}

// ======================= fused rel + att-score kernel =======================
#define R_PITCH  272          // 128 cols bf16 (256B) + 16B pad
#define P_PITCH  144          // 64 cols bf16 (128B) + 16B pad
#define RH_OFF   0
#define RL_OFF   34816
#define PJH_OFF  69632
#define PJL_OFF  88064
#define SMEM_FUSED 106496

__global__ void __launch_bounds__(256, 1) rel_fused_kernel(
    const __nv_bfloat16* __restrict__ Qw2, const __nv_bfloat16* __restrict__ K2,
    const __nv_bfloat16* __restrict__ kph, const __nv_bfloat16* __restrict__ kpl,
    const __nv_bfloat16* __restrict__ qph, const __nv_bfloat16* __restrict__ qpl,
    float* __restrict__ partQ, float* __restrict__ partK)
{
    extern __shared__ char smem[];
    const uint32_t sb = smem_to_u32(smem);
    const int tid = threadIdx.x, wid = tid >> 5, lane = tid & 31;
    const int mt = blockIdx.x, nt = blockIdx.y, b = blockIdx.z;
    const int m0 = mt * 128, n0 = nt * 128;

    float acc[4][4][4] = {};
    warp_mma_main(Qw2 + ((size_t)b * LN + m0) * KP,
                  K2  + ((size_t)b * LN + n0) * KP, sb, tid, acc);

    // prefetch kp hi/lo tiles (rows n0..n0+127) while storing rel to smem
    {
        const __nv_bfloat16* kh = kph + ((size_t)b * LN + n0) * AN;
        const __nv_bfloat16* kl = kpl + ((size_t)b * LN + n0) * AN;
#pragma unroll
        for (int i = 0; i < 4; ++i) {
            const int idx = tid + i * 256, r = idx >> 3, c = idx & 7;
            cp_async16(sb + PJH_OFF + r * P_PITCH + c * 16, kh + (size_t)r * AN + c * 8);
            cp_async16(sb + PJL_OFF + r * P_PITCH + c * 16, kl + (size_t)r * AN + c * 8);
        }
        CP_COMMIT;
    }

    // tanh + hi/lo split -> smem rel tiles
    const int mw = (wid >> 2) * 64, nw = (wid & 3) * 32;
    const int lr = lane >> 2, lc = (lane & 3) * 2;
#pragma unroll
    for (int mf = 0; mf < 4; ++mf)
#pragma unroll
        for (int nf = 0; nf < 4; ++nf)
#pragma unroll
            for (int p = 0; p < 2; ++p) {
                const int rr = mw + mf * 16 + lr + p * 8;
                const int cc = nw + nf * 8 + lc;
                BF2 H, L;
                split2(tanhf(acc[mf][nf][2 * p + 0]), H.h[0], L.h[0]);
                split2(tanhf(acc[mf][nf][2 * p + 1]), H.h[1], L.h[1]);
                *(uint32_t*)(smem + RH_OFF + rr * R_PITCH + cc * 2) = H.u;
                *(uint32_t*)(smem + RL_OFF + rr * R_PITCH + cc * 2) = L.u;
            }
    CP_WAIT(0);
    __syncthreads();

    // ---- C2[m][a] = sum_n rel[m][n] * kp[n0+n][a]  (warp w: m rows 16w..16w+16)
    float c2[8][4] = {};
#pragma unroll
    for (int term = 0; term < 3; ++term) {
        const uint32_t As = sb + (term == 1 ? RL_OFF : RH_OFF);
        const uint32_t Bs = sb + (term == 2 ? PJL_OFF : PJH_OFF);
#pragma unroll
        for (int kk = 0; kk < 128; kk += 16) {
            uint32_t a0, a1, a2, a3;
            ldmatrix_x4(a0, a1, a2, a3,
                As + (16 * wid + (lane & 15)) * R_PITCH + (kk + ((lane >> 4) << 3)) * 2);
#pragma unroll
            for (int ab = 0; ab < 4; ++ab) {
                uint32_t t0, t1, t2, t3;
                ldmatrix_x4_trans(t0, t1, t2, t3,
                    Bs + (kk + (lane & 15)) * P_PITCH + (ab * 16 + ((lane >> 4) << 3)) * 2);
                mma_bf16(c2[2 * ab],     a0, a1, a2, a3, t0, t1);
                mma_bf16(c2[2 * ab + 1], a0, a1, a2, a3, t2, t3);
            }
        }
    }
    {
        float* base = partQ + ((size_t)(nt * BN + b) * LN + m0 + 16 * wid) * AN;
#pragma unroll
        for (int j = 0; j < 8; ++j) {
            const int col = j * 8 + lc;
            *(float2*)(base + (size_t)lr * AN + col)       = make_float2(c2[j][0], c2[j][1]);
            *(float2*)(base + (size_t)(lr + 8) * AN + col) = make_float2(c2[j][2], c2[j][3]);
        }
    }
    __syncthreads();   // all warps done reading kp tiles

    // load qp hi/lo tiles (rows m0..m0+127) into same region
    {
        const __nv_bfloat16* qh = qph + ((size_t)b * LN + m0) * AN;
        const __nv_bfloat16* ql = qpl + ((size_t)b * LN + m0) * AN;
#pragma unroll
        for (int i = 0; i < 4; ++i) {
            const int idx = tid + i * 256, r = idx >> 3, c = idx & 7;
            cp_async16(sb + PJH_OFF + r * P_PITCH + c * 16, qh + (size_t)r * AN + c * 8);
            cp_async16(sb + PJL_OFF + r * P_PITCH + c * 16, ql + (size_t)r * AN + c * 8);
        }
        CP_COMMIT; CP_WAIT(0);
    }
    __syncthreads();

    // ---- C3[n][a] = sum_m rel[m][n] * qp[m0+m][a]  (A = rel^T via ldmatrix.trans)
    float c3[8][4] = {};
    const int g = lane >> 3;
#pragma unroll
    for (int term = 0; term < 3; ++term) {
        const uint32_t As = sb + (term == 1 ? RL_OFF : RH_OFF);
        const uint32_t Bs = sb + (term == 2 ? PJL_OFF : PJH_OFF);
#pragma unroll
        for (int kk = 0; kk < 128; kk += 16) {
            uint32_t a0, a1, a2, a3;
            ldmatrix_x4_trans(a0, a1, a2, a3,
                As + (kk + ((g >> 1) << 3) + (lane & 7)) * R_PITCH
                   + (16 * wid + ((g & 1) << 3)) * 2);
#pragma unroll
            for (int ab = 0; ab < 4; ++ab) {
                uint32_t t0, t1, t2, t3;
                ldmatrix_x4_trans(t0, t1, t2, t3,
                    Bs + (kk + (lane & 15)) * P_PITCH + (ab * 16 + ((lane >> 4) << 3)) * 2);
                mma_bf16(c3[2 * ab],     a0, a1, a2, a3, t0, t1);
                mma_bf16(c3[2 * ab + 1], a0, a1, a2, a3, t2, t3);
            }
        }
    }
    {
        float* base = partK + ((size_t)(mt * BN + b) * LN + n0 + 16 * wid) * AN;
#pragma unroll
        for (int j = 0; j < 8; ++j) {
            const int col = j * 8 + lc;
            *(float2*)(base + (size_t)lr * AN + col)       = make_float2(c3[j][0], c3[j][1]);
            *(float2*)(base + (size_t)(lr + 8) * AN + col) = make_float2(c3[j][2], c3[j][3]);
        }
    }
}

// ======================= Qw2 = split(Q2 @ W2t^T) =======================
__global__ void __launch_bounds__(256, 1) qw_mma_kernel(
    const __nv_bfloat16* __restrict__ Q2, const __nv_bfloat16* __restrict__ W2t,
    __nv_bfloat16* __restrict__ Qw2)
{
    extern __shared__ char smem[];
    const uint32_t smem_base = smem_to_u32(smem);
    const int tid = threadIdx.x;
    const int m0 = blockIdx.x * 128, n0 = blockIdx.y * 128;

    float acc[4][4][4] = {};
    warp_mma_main(Q2 + (size_t)m0 * KP, W2t + (size_t)n0 * KP, smem_base, tid, acc);

    const int wid = tid >> 5, lane = tid & 31;
    const int mw = (wid >> 2) * 64, nw = (wid & 3) * 32;
    const int lr = lane >> 2, lc = (lane & 3) * 2;
#pragma unroll
    for (int mf = 0; mf < 4; ++mf) {
        const int row = m0 + mw + mf * 16 + lr;
#pragma unroll
        for (int nf = 0; nf < 4; ++nf) {
            const int col = n0 + nw + nf * 8 + lc;
#pragma unroll
            for (int p = 0; p < 2; ++p) {
                const int rr = row + p * 8;
                BF2 H, L;
                split2(acc[mf][nf][2 * p + 0], H.h[0], L.h[0]);
                split2(acc[mf][nf][2 * p + 1], H.h[1], L.h[1]);
                __nv_bfloat16* o = Qw2 + (size_t)rr * KP + col;
                *(uint32_t*)(o)       = H.u;
                *(uint32_t*)(o + 256) = L.u;
                *(uint32_t*)(o + 512) = H.u;
            }
        }
    }
}

// ======================= projections via MMA (N padded to 128) ==============
__global__ void __launch_bounds__(256, 1) proj_mma_kernel(
    const __nv_bfloat16* __restrict__ A2, const __nv_bfloat16* __restrict__ Wp2t,
    float* __restrict__ pf, __nv_bfloat16* __restrict__ ph, __nv_bfloat16* __restrict__ pl)
{
    extern __shared__ char smem[];
    const uint32_t smem_base = smem_to_u32(smem);
    const int tid = threadIdx.x;
    const int m0 = blockIdx.x * 128;

    float acc[4][4][4] = {};
    warp_mma_main(A2 + (size_t)m0 * KP, Wp2t, smem_base, tid, acc);

    const int wid = tid >> 5, lane = tid & 31;
    const int mw = (wid >> 2) * 64, nw = (wid & 3) * 32;
    if (nw >= AN) return;   // cols 64..127 are zero padding
    const int lr = lane >> 2, lc = (lane & 3) * 2;
#pragma unroll
    for (int mf = 0; mf < 4; ++mf) {
#pragma unroll
        for (int nf = 0; nf < 4; ++nf) {
            const int col = nw + nf * 8 + lc;
#pragma unroll
            for (int p = 0; p < 2; ++p) {
                const int row = m0 + mw + mf * 16 + lr + p * 8;
                const float v0 = acc[mf][nf][2 * p + 0];
                const float v1 = acc[mf][nf][2 * p + 1];
                *(float2*)(pf + (size_t)row * AN + col) = make_float2(v0, v1);
                BF2 H, L;
                split2(v0, H.h[0], L.h[0]);
                split2(v1, H.h[1], L.h[1]);
                *(uint32_t*)(ph + (size_t)row * AN + col) = H.u;
                *(uint32_t*)(pl + (size_t)row * AN + col) = L.u;
            }
        }
    }
}

// ======================= split / prep kernels =======================
__global__ void __launch_bounds__(256) split_kernel(
    const float* __restrict__ Q, const float* __restrict__ Kmat,
    __nv_bfloat16* __restrict__ Q2, __nv_bfloat16* __restrict__ K2)
{
    const int sel = blockIdx.y;
    const float* src = sel ? Kmat : Q;
    __nv_bfloat16* dst = sel ? K2 : Q2;
    const size_t i4 = (size_t)blockIdx.x * 256 + threadIdx.x;
    const size_t row = i4 >> 6;
    const int c = (int)(i4 & 63) * 4;
    float4 v = ((const float4*)src)[i4];
    union { __nv_bfloat16 b[4]; uint2 u; } h, l;
    split2(v.x, h.b[0], l.b[0]); split2(v.y, h.b[1], l.b[1]);
    split2(v.z, h.b[2], l.b[2]); split2(v.w, h.b[3], l.b[3]);
    __nv_bfloat16* o = dst + row * KP + c;
    *(uint2*)(o) = h.u;
    if (sel == 0) { *(uint2*)(o + 256) = l.u; *(uint2*)(o + 512) = h.u; }   // A pattern
    else          { *(uint2*)(o + 256) = h.u; *(uint2*)(o + 512) = l.u; }   // B pattern
}

__global__ void __launch_bounds__(256) prep_w2t(
    const float* __restrict__ Wrel, __nv_bfloat16* __restrict__ W2t)
{
    const int idx = blockIdx.x * 256 + threadIdx.x;   // 65536
    const int d = idx >> 8, n = idx & 255;
    __nv_bfloat16 hi, lo;
    split2(Wrel[d * 256 + n], hi, lo);
    W2t[(size_t)n * KP + d]       = hi;
    W2t[(size_t)n * KP + 256 + d] = hi;
    W2t[(size_t)n * KP + 512 + d] = lo;
}

// Wq/Wk [256][64] -> padded [128 rows][768] slabs.
// THE FIX: slab pattern depends on the A operand's split pattern.
//   side 0 (Wq, against Q2 [hi|lo|hi]) -> B pattern [hi|hi|lo]
//   side 1 (Wk, against K2 [hi|hi|lo]) -> A pattern [hi|lo|hi]
// (previous rounds used [hi|hi|lo] for BOTH -> k_proj = 2*hi*hi + lo*lo, ~2x)
__global__ void __launch_bounds__(256) prep_wp(
    const float* __restrict__ Wq, const float* __restrict__ Wk,
    __nv_bfloat16* __restrict__ Wp2t)
{
    const int idx = blockIdx.x * 256 + threadIdx.x;   // 32768
    const int side = idx >> 14;
    const int d = (idx >> 6) & 255, a = idx & 63;
    const float* W = side ? Wk : Wq;
    __nv_bfloat16 hi, lo;
    split2(W[d * 64 + a], hi, lo);
    __nv_bfloat16* slab = Wp2t + (size_t)side * 128 * KP;
    slab[(size_t)a * KP + d]       = hi;
    slab[(size_t)a * KP + 256 + d] = side ? lo : hi;
    slab[(size_t)a * KP + 512 + d] = side ? hi : lo;
}

// ======================= partial-sum + tanh + dot reduce ====================
__global__ void __launch_bounds__(256) att_reduce_kernel(
    const float* __restrict__ qpf, const float* __restrict__ kpf,
    const float* __restrict__ partQ, const float* __restrict__ partK,
    const float* __restrict__ Wqa, const float* __restrict__ Wka,
    float* __restrict__ lq, float* __restrict__ lk)
{
    const int side = blockIdx.y;
    const int wid = threadIdx.x >> 5, lane = threadIdx.x & 31;
    const size_t gm = (size_t)blockIdx.x * 8 + wid;   // b*LN + m
    const float* pf   = side ? kpf   : qpf;
    const float* part = side ? partK : partQ;
    const float* w    = side ? Wka   : Wqa;
    float* out        = side ? lk    : lq;

    float s = 0.f;
#pragma unroll
    for (int h = 0; h < 2; ++h) {
        const int a = lane + h * 32;
        float v = pf[gm * AN + a];
#pragma unroll
        for (int t = 0; t < 4; ++t)
            v += part[((size_t)t * BN * LN + gm) * AN + a];
        s += tanhf(v) * w[a];
    }
#pragma unroll
    for (int o = 16; o; o >>= 1) s += __shfl_xor_sync(0xFFFFFFFFu, s, o);
    if (lane == 0) out[gm] = s;
}

// ============================================================================
__global__ void __launch_bounds__(512) softmax_kernel(
    const float* __restrict__ lq, const float* __restrict__ lk,
    float* __restrict__ out)
{
    __shared__ float red[512];
    const int b = blockIdx.x, sel = blockIdx.y, t = threadIdx.x;
    const float* l = (sel ? lk : lq) + (size_t)b * LN;
    float* o = out + (sel ? OFF_KW : OFF_QW) + (size_t)b * LN;

    float v = l[t];
    red[t] = v; __syncthreads();
    for (int s = 256; s > 0; s >>= 1) {
        if (t < s) red[t] = fmaxf(red[t], red[t + s]);
        __syncthreads();
    }
    const float mx = red[0];
    __syncthreads();
    const float e = expf(v - mx);
    red[t] = e; __syncthreads();
    for (int s = 256; s > 0; s >>= 1) {
        if (t < s) red[t] += red[t + s];
        __syncthreads();
    }
    o[t] = e / red[0];
}

__global__ void __launch_bounds__(256) scale_kernel(
    const float* __restrict__ Q, const float* __restrict__ Kmat,
    float* __restrict__ out)
{
    const int sel = blockIdx.y;
    const size_t i4 = (size_t)blockIdx.x * 256 + threadIdx.x;
    const float4* src = (const float4*)(sel ? Kmat : Q);
    const float*  w   = out + (sel ? OFF_KW : OFF_QW);
    float4*       dst = (float4*)(out + (sel ? OFF_WK : OFF_WQ));

    const size_t e = i4 * 4;
    const int b = (int)(e >> 17);
    const int l = (int)((e >> 8) & 511);
    const float s = w[b * LN + l];
    float4 v = src[i4];
    v.x *= s; v.y *= s; v.z *= s; v.w *= s;
    dst[i4] = v;
}

// ============================================================================
extern "C" void kernel_launch(void* const* d_in, const int* in_sizes, int n_in,
                              void* d_out, int out_size)
{
    (void)in_sizes; (void)n_in; (void)out_size;
    const float* Q    = (const float*)d_in[0];
    const float* Km   = (const float*)d_in[1];
    const float* Wrel = (const float*)d_in[2];
    const float* Wq   = (const float*)d_in[3];
    const float* Wk   = (const float*)d_in[4];
    const float* Wqa  = (const float*)d_in[5];
    const float* Wka  = (const float*)d_in[6];
    float* out = (float*)d_out;

    __nv_bfloat16 *q2, *k2, *qw2, *w2t, *wp2t, *qph, *qpl, *kph, *kpl;
    float *qpf, *kpf, *pQ, *pK, *lq, *lk;
    cudaGetSymbolAddress((void**)&q2,   g_Q2);
    cudaGetSymbolAddress((void**)&k2,   g_K2);
    cudaGetSymbolAddress((void**)&qw2,  g_Qw2);
    cudaGetSymbolAddress((void**)&w2t,  g_W2t);
    cudaGetSymbolAddress((void**)&wp2t, g_Wp2t);
    cudaGetSymbolAddress((void**)&qpf,  g_qpf);
    cudaGetSymbolAddress((void**)&kpf,  g_kpf);
    cudaGetSymbolAddress((void**)&qph,  g_qph);
    cudaGetSymbolAddress((void**)&qpl,  g_qpl);
    cudaGetSymbolAddress((void**)&kph,  g_kph);
    cudaGetSymbolAddress((void**)&kpl,  g_kpl);
    cudaGetSymbolAddress((void**)&pQ,   g_partQ);
    cudaGetSymbolAddress((void**)&pK,   g_partK);
    cudaGetSymbolAddress((void**)&lq,   g_logit_q);
    cudaGetSymbolAddress((void**)&lk,   g_logit_k);

    cudaFuncSetAttribute(qw_mma_kernel,    cudaFuncAttributeMaxDynamicSharedMemorySize, SMEM_MMA);
    cudaFuncSetAttribute(proj_mma_kernel,  cudaFuncAttributeMaxDynamicSharedMemorySize, SMEM_MMA);
    cudaFuncSetAttribute(rel_fused_kernel, cudaFuncAttributeMaxDynamicSharedMemorySize, SMEM_FUSED);

    const dim3 blk(256);
    // bf16 hi/lo splits of inputs + weight transposes
    split_kernel<<<dim3((BN * LN * DN) / 4 / 256, 2), blk>>>(Q, Km, q2, k2);
    prep_w2t<<<256, blk>>>(Wrel, w2t);
    prep_wp<<<128, blk>>>(Wq, Wk, wp2t);
    // projections via MMA (fp32 + hi/lo bf16 outputs)
    proj_mma_kernel<<<512, blk, SMEM_MMA>>>(q2, wp2t, qpf, qph, qpl);
    proj_mma_kernel<<<512, blk, SMEM_MMA>>>(k2, wp2t + (size_t)128 * KP, kpf, kph, kpl);
    // Qw (MMA, epilogue re-splits to bf16 hi/lo)
    qw_mma_kernel<<<dim3(512, 2), blk, SMEM_MMA>>>(q2, w2t, qw2);
    // fused rel + both score GEMMs -> partial buffers
    rel_fused_kernel<<<dim3(4, 4, BN), blk, SMEM_FUSED>>>(qw2, k2, kph, kpl, qph, qpl, pQ, pK);
    // partial reduce + tanh + @W_att -> logits
    att_reduce_kernel<<<dim3(BN * LN / 8, 2), blk>>>(qpf, kpf, pQ, pK, Wqa, Wka, lq, lk);
    // softmax -> weights in d_out
    softmax_kernel<<<dim3(BN, 2), 512>>>(lq, lk, out);
    // weighted outputs
    scale_kernel<<<dim3((BN * LN * DN) / 4 / 256, 2), 256>>>(Q, Km, out);
}

// round 8
// speedup vs baseline: 2.3213x; 1.1319x over previous
#include <cuda_runtime.h>
#include <cuda_bf16.h>
#include <math.h>
#include <stdint.h>

// Problem dims
#define BN 128
#define LN 512
#define DN 256
#define AN 64
#define KP 768   // split-K': 3 x 256  (A [hi|lo|hi] x B [hi|hi|lo])

// Output layout (concatenated, reference tuple order)
#define OFF_WQ  ((size_t)0)
#define OFF_WK  ((size_t)BN * LN * DN)
#define OFF_QW  ((size_t)2 * BN * LN * DN)
#define OFF_KW  (OFF_QW + (size_t)BN * LN)

// -------- scratch (device globals; no allocation allowed) --------
__device__ __nv_bfloat16 g_Q2 [(size_t)BN * LN * KP];    // [hi|lo|hi] of Q
__device__ __nv_bfloat16 g_K2 [(size_t)BN * LN * KP];    // [hi|hi|lo] of K
__device__ __nv_bfloat16 g_Qw2[(size_t)BN * LN * KP];    // [hi|lo|hi] of Qw
__device__ __nv_bfloat16 g_W2t[(size_t)DN * KP];         // W_rel^T split [hi|hi|lo]
__device__ __nv_bfloat16 g_Wp2t[2 * 128 * KP];           // Wq^T [hi|hi|lo] / Wk^T [hi|lo|hi]
__device__ float g_qpf[(size_t)BN * LN * AN];            // q_proj fp32
__device__ float g_kpf[(size_t)BN * LN * AN];            // k_proj fp32
__device__ __nv_bfloat16 g_qph[(size_t)BN * LN * AN], g_qpl[(size_t)BN * LN * AN];
__device__ __nv_bfloat16 g_kph[(size_t)BN * LN * AN], g_kpl[(size_t)BN * LN * AN];
__device__ float g_partQ[(size_t)4 * BN * LN * AN];      // rel@kp partials (per n-tile)
__device__ float g_partK[(size_t)4 * BN * LN * AN];      // relT@qp partials (per m-tile)
__device__ float g_logit_q[BN * LN];
__device__ float g_logit_k[BN * LN];

// ======================= helpers (baseline PTX only) =======================
__device__ __forceinline__ uint32_t smem_to_u32(const void* p) {
    uint32_t a;
    asm("{ .reg .u64 t; cvta.to.shared.u64 t, %1; cvt.u32.u64 %0, t; }" : "=r"(a) : "l"(p));
    return a;
}
#define SMEM_SWIZZLE_128B(o) ((o) ^ (((o) >> 3) & 0x70))

__device__ __forceinline__ void cp_async16(uint32_t saddr, const void* g) {
    asm volatile("cp.async.cg.shared.global [%0], [%1], 16;" :: "r"(saddr), "l"(g));
}
#define CP_COMMIT  asm volatile("cp.async.commit_group;" ::: "memory")
#define CP_WAIT(n) asm volatile("cp.async.wait_group %0;" :: "n"(n) : "memory")

__device__ __forceinline__ void ldmatrix_x4(uint32_t& r0, uint32_t& r1, uint32_t& r2,
                                            uint32_t& r3, uint32_t addr) {
    asm volatile("ldmatrix.sync.aligned.m8n8.x4.shared.b16 {%0,%1,%2,%3}, [%4];"
                 : "=r"(r0), "=r"(r1), "=r"(r2), "=r"(r3) : "r"(addr));
}
__device__ __forceinline__ void ldmatrix_x4_trans(uint32_t& r0, uint32_t& r1, uint32_t& r2,
                                                  uint32_t& r3, uint32_t addr) {
    asm volatile("ldmatrix.sync.aligned.m8n8.x4.trans.shared.b16 {%0,%1,%2,%3}, [%4];"
                 : "=r"(r0), "=r"(r1), "=r"(r2), "=r"(r3) : "r"(addr));
}
__device__ __forceinline__ void mma_bf16(float* c, uint32_t a0, uint32_t a1, uint32_t a2,
                                         uint32_t a3, uint32_t b0, uint32_t b1) {
    asm volatile(
        "mma.sync.aligned.m16n8k16.row.col.f32.bf16.bf16.f32 "
        "{%0,%1,%2,%3}, {%4,%5,%6,%7}, {%8,%9}, {%0,%1,%2,%3};"
        : "+f"(c[0]), "+f"(c[1]), "+f"(c[2]), "+f"(c[3])
        : "r"(a0), "r"(a1), "r"(a2), "r"(a3), "r"(b0), "r"(b1));
}

__device__ __forceinline__ void split2(float x, __nv_bfloat16& hi, __nv_bfloat16& lo) {
    hi = __float2bfloat16(x);
    lo = __float2bfloat16(x - __bfloat162float(hi));
}
union BF2 { __nv_bfloat16 h[2]; uint32_t u; };

// ======================= warp-MMA mainloop (128x128 tile) =======================
#define NSTAGE  12
#define STAGE_BYTES 32768
#define SMEM_MMA (2 * STAGE_BYTES)

__device__ __forceinline__ void load_stage(uint32_t sbase,
    const __nv_bfloat16* __restrict__ A, const __nv_bfloat16* __restrict__ B,
    int s, int tid)
{
    const __nv_bfloat16* Ak = A + s * 64;
    const __nv_bfloat16* Bk = B + s * 64;
#pragma unroll
    for (int i = 0; i < 4; ++i) {
        const int idx = tid + i * 256;            // 0..1023 16B chunks
        const int r = idx >> 3, c = idx & 7;
        const uint32_t off = SMEM_SWIZZLE_128B((uint32_t)(r * 128 + c * 16));
        cp_async16(sbase + off, Ak + (size_t)r * KP + c * 8);
        cp_async16(sbase + 16384 + off, Bk + (size_t)r * KP + c * 8);
    }
}

__device__ __forceinline__ void warp_mma_main(
    const __nv_bfloat16* __restrict__ A, const __nv_bfloat16* __restrict__ B,
    uint32_t smem_base, int tid, float acc[4][4][4])
{
    const int wid = tid >> 5, lane = tid & 31;
    const int mw = (wid >> 2) * 64, nw = (wid & 3) * 32;

    load_stage(smem_base, A, B, 0, tid);
    CP_COMMIT;

    int buf = 0;
    for (int s = 0; s < NSTAGE; ++s) {
        if (s + 1 < NSTAGE) {
            load_stage(smem_base + (buf ^ 1) * STAGE_BYTES, A, B, s + 1, tid);
            CP_COMMIT;
            CP_WAIT(1);
        } else {
            CP_COMMIT;
            CP_WAIT(0);
        }
        __syncthreads();

        const uint32_t sA = smem_base + buf * STAGE_BYTES;
        const uint32_t sB = sA + 16384;
#pragma unroll
        for (int kk = 0; kk < 64; kk += 16) {
            uint32_t a[4][4], b[4][2];
#pragma unroll
            for (int mf = 0; mf < 4; ++mf) {
                const uint32_t off = SMEM_SWIZZLE_128B((uint32_t)(
                    (mw + mf * 16 + (lane & 15)) * 128 + kk * 2 + ((lane >> 4) << 4)));
                ldmatrix_x4(a[mf][0], a[mf][1], a[mf][2], a[mf][3], sA + off);
            }
#pragma unroll
            for (int nb = 0; nb < 2; ++nb) {
                const int row = nw + nb * 16 + ((lane >> 4) & 1) * 8 + (lane & 7);
                const int kof = kk * 2 + (((lane >> 3) & 1) << 4);
                const uint32_t off = SMEM_SWIZZLE_128B((uint32_t)(row * 128 + kof));
                ldmatrix_x4(b[nb * 2][0], b[nb * 2][1], b[nb * 2 + 1][0], b[nb * 2 + 1][1],
                            sB + off);
            }
#pragma unroll
            for (int mf = 0; mf < 4; ++mf)
#pragma unroll
                for (int nf = 0; nf < 4; ++nf)
                    mma_bf16(acc[mf][nf], a[mf][0], a[mf][1], a[mf][2], a[mf][3],
                             b[nf][0], b[nf][1]);
        }
        __syncthreads();
        buf ^= 1;
    }
}

// ======================= fused rel + att-score kernel =======================
#define R_PITCH  272          // 128 cols bf16 (256B) + 16B pad
#define P_PITCH  144          // 64 cols bf16 (128B) + 16B pad
#define RH_OFF   0
#define RL_OFF   34816
#define PJH_OFF  69632
#define PJL_OFF  88064
#define SMEM_FUSED 106496

__global__ void __launch_bounds__(256, 2) rel_fused_kernel(
    const __nv_bfloat16* __restrict__ Qw2, const __nv_bfloat16* __restrict__ K2,
    const __nv_bfloat16* __restrict__ kph, const __nv_bfloat16* __restrict__ kpl,
    const __nv_bfloat16* __restrict__ qph, const __nv_bfloat16* __restrict__ qpl,
    float* __restrict__ partQ, float* __restrict__ partK)
{
    extern __shared__ char smem[];
    const uint32_t sb = smem_to_u32(smem);
    const int tid = threadIdx.x, wid = tid >> 5, lane = tid & 31;
    const int mt = blockIdx.x, nt = blockIdx.y, b = blockIdx.z;
    const int m0 = mt * 128, n0 = nt * 128;

    float acc[4][4][4] = {};
    warp_mma_main(Qw2 + ((size_t)b * LN + m0) * KP,
                  K2  + ((size_t)b * LN + n0) * KP, sb, tid, acc);

    // prefetch kp hi/lo tiles (rows n0..n0+127) while storing rel to smem
    {
        const __nv_bfloat16* kh = kph + ((size_t)b * LN + n0) * AN;
        const __nv_bfloat16* kl = kpl + ((size_t)b * LN + n0) * AN;
#pragma unroll
        for (int i = 0; i < 4; ++i) {
            const int idx = tid + i * 256, r = idx >> 3, c = idx & 7;
            cp_async16(sb + PJH_OFF + r * P_PITCH + c * 16, kh + (size_t)r * AN + c * 8);
            cp_async16(sb + PJL_OFF + r * P_PITCH + c * 16, kl + (size_t)r * AN + c * 8);
        }
        CP_COMMIT;
    }

    // tanh + hi/lo split -> smem rel tiles
    const int mw = (wid >> 2) * 64, nw = (wid & 3) * 32;
    const int lr = lane >> 2, lc = (lane & 3) * 2;
#pragma unroll
    for (int mf = 0; mf < 4; ++mf)
#pragma unroll
        for (int nf = 0; nf < 4; ++nf)
#pragma unroll
            for (int p = 0; p < 2; ++p) {
                const int rr = mw + mf * 16 + lr + p * 8;
                const int cc = nw + nf * 8 + lc;
                BF2 H, L;
                split2(tanhf(acc[mf][nf][2 * p + 0]), H.h[0], L.h[0]);
                split2(tanhf(acc[mf][nf][2 * p + 1]), H.h[1], L.h[1]);
                *(uint32_t*)(smem + RH_OFF + rr * R_PITCH + cc * 2) = H.u;
                *(uint32_t*)(smem + RL_OFF + rr * R_PITCH + cc * 2) = L.u;
            }
    CP_WAIT(0);
    __syncthreads();

    // ---- C2[m][a] = sum_n rel[m][n] * kp[n0+n][a]  (warp w: m rows 16w..16w+16)
    float c2[8][4] = {};
#pragma unroll
    for (int term = 0; term < 3; ++term) {
        const uint32_t As = sb + (term == 1 ? RL_OFF : RH_OFF);
        const uint32_t Bs = sb + (term == 2 ? PJL_OFF : PJH_OFF);
#pragma unroll
        for (int kk = 0; kk < 128; kk += 16) {
            uint32_t a0, a1, a2, a3;
            ldmatrix_x4(a0, a1, a2, a3,
                As + (16 * wid + (lane & 15)) * R_PITCH + (kk + ((lane >> 4) << 3)) * 2);
#pragma unroll
            for (int ab = 0; ab < 4; ++ab) {
                uint32_t t0, t1, t2, t3;
                ldmatrix_x4_trans(t0, t1, t2, t3,
                    Bs + (kk + (lane & 15)) * P_PITCH + (ab * 16 + ((lane >> 4) << 3)) * 2);
                mma_bf16(c2[2 * ab],     a0, a1, a2, a3, t0, t1);
                mma_bf16(c2[2 * ab + 1], a0, a1, a2, a3, t2, t3);
            }
        }
    }
    {
        float* base = partQ + ((size_t)(nt * BN + b) * LN + m0 + 16 * wid) * AN;
#pragma unroll
        for (int j = 0; j < 8; ++j) {
            const int col = j * 8 + lc;
            *(float2*)(base + (size_t)lr * AN + col)       = make_float2(c2[j][0], c2[j][1]);
            *(float2*)(base + (size_t)(lr + 8) * AN + col) = make_float2(c2[j][2], c2[j][3]);
        }
    }
    __syncthreads();   // all warps done reading kp tiles

    // load qp hi/lo tiles (rows m0..m0+127) into same region
    {
        const __nv_bfloat16* qh = qph + ((size_t)b * LN + m0) * AN;
        const __nv_bfloat16* ql = qpl + ((size_t)b * LN + m0) * AN;
#pragma unroll
        for (int i = 0; i < 4; ++i) {
            const int idx = tid + i * 256, r = idx >> 3, c = idx & 7;
            cp_async16(sb + PJH_OFF + r * P_PITCH + c * 16, qh + (size_t)r * AN + c * 8);
            cp_async16(sb + PJL_OFF + r * P_PITCH + c * 16, ql + (size_t)r * AN + c * 8);
        }
        CP_COMMIT; CP_WAIT(0);
    }
    __syncthreads();

    // ---- C3[n][a] = sum_m rel[m][n] * qp[m0+m][a]  (A = rel^T via ldmatrix.trans)
    float c3[8][4] = {};
    const int g = lane >> 3;
#pragma unroll
    for (int term = 0; term < 3; ++term) {
        const uint32_t As = sb + (term == 1 ? RL_OFF : RH_OFF);
        const uint32_t Bs = sb + (term == 2 ? PJL_OFF : PJH_OFF);
#pragma unroll
        for (int kk = 0; kk < 128; kk += 16) {
            uint32_t a0, a1, a2, a3;
            ldmatrix_x4_trans(a0, a1, a2, a3,
                As + (kk + ((g >> 1) << 3) + (lane & 7)) * R_PITCH
                   + (16 * wid + ((g & 1) << 3)) * 2);
#pragma unroll
            for (int ab = 0; ab < 4; ++ab) {
                uint32_t t0, t1, t2, t3;
                ldmatrix_x4_trans(t0, t1, t2, t3,
                    Bs + (kk + (lane & 15)) * P_PITCH + (ab * 16 + ((lane >> 4) << 3)) * 2);
                mma_bf16(c3[2 * ab],     a0, a1, a2, a3, t0, t1);
                mma_bf16(c3[2 * ab + 1], a0, a1, a2, a3, t2, t3);
            }
        }
    }
    {
        float* base = partK + ((size_t)(mt * BN + b) * LN + n0 + 16 * wid) * AN;
#pragma unroll
        for (int j = 0; j < 8; ++j) {
            const int col = j * 8 + lc;
            *(float2*)(base + (size_t)lr * AN + col)       = make_float2(c3[j][0], c3[j][1]);
            *(float2*)(base + (size_t)(lr + 8) * AN + col) = make_float2(c3[j][2], c3[j][3]);
        }
    }
}

// ======================= Qw2 = split(Q2 @ W2t^T) =======================
__global__ void __launch_bounds__(256, 2) qw_mma_kernel(
    const __nv_bfloat16* __restrict__ Q2, const __nv_bfloat16* __restrict__ W2t,
    __nv_bfloat16* __restrict__ Qw2)
{
    extern __shared__ char smem[];
    const uint32_t smem_base = smem_to_u32(smem);
    const int tid = threadIdx.x;
    const int m0 = blockIdx.x * 128, n0 = blockIdx.y * 128;

    float acc[4][4][4] = {};
    warp_mma_main(Q2 + (size_t)m0 * KP, W2t + (size_t)n0 * KP, smem_base, tid, acc);

    const int wid = tid >> 5, lane = tid & 31;
    const int mw = (wid >> 2) * 64, nw = (wid & 3) * 32;
    const int lr = lane >> 2, lc = (lane & 3) * 2;
#pragma unroll
    for (int mf = 0; mf < 4; ++mf) {
        const int row = m0 + mw + mf * 16 + lr;
#pragma unroll
        for (int nf = 0; nf < 4; ++nf) {
            const int col = n0 + nw + nf * 8 + lc;
#pragma unroll
            for (int p = 0; p < 2; ++p) {
                const int rr = row + p * 8;
                BF2 H, L;
                split2(acc[mf][nf][2 * p + 0], H.h[0], L.h[0]);
                split2(acc[mf][nf][2 * p + 1], H.h[1], L.h[1]);
                __nv_bfloat16* o = Qw2 + (size_t)rr * KP + col;
                *(uint32_t*)(o)       = H.u;
                *(uint32_t*)(o + 256) = L.u;
                *(uint32_t*)(o + 512) = H.u;
            }
        }
    }
}

// ======================= slim projection kernel (N=64, no padding) ==========
// CTA: 128 m-rows x 64 a-cols, K=768. Stage = A(16KB) + W(8KB) = 24KB, x2 buf.
// 8 warps as 4m x 2n, warp tile 32x32 -> acc[2][4][4] = 32 regs.
#define SLIM_STAGE 24576
#define SMEM_SLIM  (2 * SLIM_STAGE)

__device__ __forceinline__ void load_stage_slim(uint32_t sbase,
    const __nv_bfloat16* __restrict__ A, const __nv_bfloat16* __restrict__ W,
    int s, int tid)
{
    const __nv_bfloat16* Ak = A + s * 64;
    const __nv_bfloat16* Wk = W + s * 64;
#pragma unroll
    for (int i = 0; i < 4; ++i) {
        const int idx = tid + i * 256;            // 1024 chunks: A 128 rows x 8
        const int r = idx >> 3, c = idx & 7;
        const uint32_t off = SMEM_SWIZZLE_128B((uint32_t)(r * 128 + c * 16));
        cp_async16(sbase + off, Ak + (size_t)r * KP + c * 8);
    }
#pragma unroll
    for (int i = 0; i < 2; ++i) {
        const int idx = tid + i * 256;            // 512 chunks: W 64 rows x 8
        const int r = idx >> 3, c = idx & 7;
        const uint32_t off = SMEM_SWIZZLE_128B((uint32_t)(r * 128 + c * 16));
        cp_async16(sbase + 16384 + off, Wk + (size_t)r * KP + c * 8);
    }
}

__global__ void __launch_bounds__(256, 2) proj_slim_kernel(
    const __nv_bfloat16* __restrict__ Q2, const __nv_bfloat16* __restrict__ K2,
    const __nv_bfloat16* __restrict__ Wp2t,
    float* __restrict__ qpf, float* __restrict__ kpf,
    __nv_bfloat16* __restrict__ qph, __nv_bfloat16* __restrict__ qpl,
    __nv_bfloat16* __restrict__ kph, __nv_bfloat16* __restrict__ kpl)
{
    extern __shared__ char smem[];
    const uint32_t sb = smem_to_u32(smem);
    const int tid = threadIdx.x, wid = tid >> 5, lane = tid & 31;
    const int side = blockIdx.y;
    const int m0 = blockIdx.x * 128;
    const __nv_bfloat16* A = (side ? K2 : Q2) + (size_t)m0 * KP;
    const __nv_bfloat16* W = Wp2t + (size_t)side * 128 * KP;
    float* pf = side ? kpf : qpf;
    __nv_bfloat16* ph = side ? kph : qph;
    __nv_bfloat16* pl = side ? kpl : qpl;

    const int mw = (wid >> 1) * 32, nw = (wid & 1) * 32;

    float acc[2][4][4] = {};
    load_stage_slim(sb, A, W, 0, tid);
    CP_COMMIT;

    int buf = 0;
    for (int s = 0; s < NSTAGE; ++s) {
        if (s + 1 < NSTAGE) {
            load_stage_slim(sb + (buf ^ 1) * SLIM_STAGE, A, W, s + 1, tid);
            CP_COMMIT;
            CP_WAIT(1);
        } else {
            CP_COMMIT;
            CP_WAIT(0);
        }
        __syncthreads();

        const uint32_t sA = sb + buf * SLIM_STAGE;
        const uint32_t sW = sA + 16384;
#pragma unroll
        for (int kk = 0; kk < 64; kk += 16) {
            uint32_t a[2][4], b[4][2];
#pragma unroll
            for (int mf = 0; mf < 2; ++mf) {
                const uint32_t off = SMEM_SWIZZLE_128B((uint32_t)(
                    (mw + mf * 16 + (lane & 15)) * 128 + kk * 2 + ((lane >> 4) << 4)));
                ldmatrix_x4(a[mf][0], a[mf][1], a[mf][2], a[mf][3], sA + off);
            }
#pragma unroll
            for (int nb = 0; nb < 2; ++nb) {
                const int row = nw + nb * 16 + ((lane >> 4) & 1) * 8 + (lane & 7);
                const int kof = kk * 2 + (((lane >> 3) & 1) << 4);
                const uint32_t off = SMEM_SWIZZLE_128B((uint32_t)(row * 128 + kof));
                ldmatrix_x4(b[nb * 2][0], b[nb * 2][1], b[nb * 2 + 1][0], b[nb * 2 + 1][1],
                            sW + off);
            }
#pragma unroll
            for (int mf = 0; mf < 2; ++mf)
#pragma unroll
                for (int nf = 0; nf < 4; ++nf)
                    mma_bf16(acc[mf][nf], a[mf][0], a[mf][1], a[mf][2], a[mf][3],
                             b[nf][0], b[nf][1]);
        }
        __syncthreads();
        buf ^= 1;
    }

    const int lr = lane >> 2, lc = (lane & 3) * 2;
#pragma unroll
    for (int mf = 0; mf < 2; ++mf) {
#pragma unroll
        for (int nf = 0; nf < 4; ++nf) {
            const int col = nw + nf * 8 + lc;
#pragma unroll
            for (int p = 0; p < 2; ++p) {
                const int row = m0 + mw + mf * 16 + lr + p * 8;
                const float v0 = acc[mf][nf][2 * p + 0];
                const float v1 = acc[mf][nf][2 * p + 1];
                *(float2*)(pf + (size_t)row * AN + col) = make_float2(v0, v1);
                BF2 H, L;
                split2(v0, H.h[0], L.h[0]);
                split2(v1, H.h[1], L.h[1]);
                *(uint32_t*)(ph + (size_t)row * AN + col) = H.u;
                *(uint32_t*)(pl + (size_t)row * AN + col) = L.u;
            }
        }
    }
}

// ======================= split / prep kernels =======================
__global__ void __launch_bounds__(256) split_kernel(
    const float* __restrict__ Q, const float* __restrict__ Kmat,
    __nv_bfloat16* __restrict__ Q2, __nv_bfloat16* __restrict__ K2)
{
    const int sel = blockIdx.y;
    const float* src = sel ? Kmat : Q;
    __nv_bfloat16* dst = sel ? K2 : Q2;
    const size_t i4 = (size_t)blockIdx.x * 256 + threadIdx.x;
    const size_t row = i4 >> 6;
    const int c = (int)(i4 & 63) * 4;
    float4 v = ((const float4*)src)[i4];
    union { __nv_bfloat16 b[4]; uint2 u; } h, l;
    split2(v.x, h.b[0], l.b[0]); split2(v.y, h.b[1], l.b[1]);
    split2(v.z, h.b[2], l.b[2]); split2(v.w, h.b[3], l.b[3]);
    __nv_bfloat16* o = dst + row * KP + c;
    *(uint2*)(o) = h.u;
    if (sel == 0) { *(uint2*)(o + 256) = l.u; *(uint2*)(o + 512) = h.u; }   // A pattern
    else          { *(uint2*)(o + 256) = h.u; *(uint2*)(o + 512) = l.u; }   // B pattern
}

__global__ void __launch_bounds__(256) prep_w2t(
    const float* __restrict__ Wrel, __nv_bfloat16* __restrict__ W2t)
{
    const int idx = blockIdx.x * 256 + threadIdx.x;   // 65536
    const int d = idx >> 8, n = idx & 255;
    __nv_bfloat16 hi, lo;
    split2(Wrel[d * 256 + n], hi, lo);
    W2t[(size_t)n * KP + d]       = hi;
    W2t[(size_t)n * KP + 256 + d] = hi;
    W2t[(size_t)n * KP + 512 + d] = lo;
}

// Wq/Wk [256][64] -> [128 rows][768] slabs (rows 64..127 zero, unused by slim).
//   side 0 (Wq, against Q2 [hi|lo|hi]) -> B pattern [hi|hi|lo]
//   side 1 (Wk, against K2 [hi|hi|lo]) -> A pattern [hi|lo|hi]
__global__ void __launch_bounds__(256) prep_wp(
    const float* __restrict__ Wq, const float* __restrict__ Wk,
    __nv_bfloat16* __restrict__ Wp2t)
{
    const int idx = blockIdx.x * 256 + threadIdx.x;   // 32768
    const int side = idx >> 14;
    const int d = (idx >> 6) & 255, a = idx & 63;
    const float* W = side ? Wk : Wq;
    __nv_bfloat16 hi, lo;
    split2(W[d * 64 + a], hi, lo);
    __nv_bfloat16* slab = Wp2t + (size_t)side * 128 * KP;
    slab[(size_t)a * KP + d]       = hi;
    slab[(size_t)a * KP + 256 + d] = side ? lo : hi;
    slab[(size_t)a * KP + 512 + d] = side ? hi : lo;
}

// ======================= partial-sum + tanh + dot reduce ====================
__global__ void __launch_bounds__(256) att_reduce_kernel(
    const float* __restrict__ qpf, const float* __restrict__ kpf,
    const float* __restrict__ partQ, const float* __restrict__ partK,
    const float* __restrict__ Wqa, const float* __restrict__ Wka,
    float* __restrict__ lq, float* __restrict__ lk)
{
    const int side = blockIdx.y;
    const int wid = threadIdx.x >> 5, lane = threadIdx.x & 31;
    const size_t gm = (size_t)blockIdx.x * 8 + wid;   // b*LN + m
    const float* pf   = side ? kpf   : qpf;
    const float* part = side ? partK : partQ;
    const float* w    = side ? Wka   : Wqa;
    float* out        = side ? lk    : lq;

    float s = 0.f;
#pragma unroll
    for (int h = 0; h < 2; ++h) {
        const int a = lane + h * 32;
        float v = pf[gm * AN + a];
#pragma unroll
        for (int t = 0; t < 4; ++t)
            v += part[((size_t)t * BN * LN + gm) * AN + a];
        s += tanhf(v) * w[a];
    }
#pragma unroll
    for (int o = 16; o; o >>= 1) s += __shfl_xor_sync(0xFFFFFFFFu, s, o);
    if (lane == 0) out[gm] = s;
}

// ============================================================================
__global__ void __launch_bounds__(512) softmax_kernel(
    const float* __restrict__ lq, const float* __restrict__ lk,
    float* __restrict__ out)
{
    __shared__ float red[512];
    const int b = blockIdx.x, sel = blockIdx.y, t = threadIdx.x;
    const float* l = (sel ? lk : lq) + (size_t)b * LN;
    float* o = out + (sel ? OFF_KW : OFF_QW) + (size_t)b * LN;

    float v = l[t];
    red[t] = v; __syncthreads();
    for (int s = 256; s > 0; s >>= 1) {
        if (t < s) red[t] = fmaxf(red[t], red[t + s]);
        __syncthreads();
    }
    const float mx = red[0];
    __syncthreads();
    const float e = expf(v - mx);
    red[t] = e; __syncthreads();
    for (int s = 256; s > 0; s >>= 1) {
        if (t < s) red[t] += red[t + s];
        __syncthreads();
    }
    o[t] = e / red[0];
}

__global__ void __launch_bounds__(256) scale_kernel(
    const float* __restrict__ Q, const float* __restrict__ Kmat,
    float* __restrict__ out)
{
    const int sel = blockIdx.y;
    const size_t i4 = (size_t)blockIdx.x * 256 + threadIdx.x;
    const float4* src = (const float4*)(sel ? Kmat : Q);
    const float*  w   = out + (sel ? OFF_KW : OFF_QW);
    float4*       dst = (float4*)(out + (sel ? OFF_WK : OFF_WQ));

    const size_t e = i4 * 4;
    const int b = (int)(e >> 17);
    const int l = (int)((e >> 8) & 511);
    const float s = w[b * LN + l];
    float4 v = src[i4];
    v.x *= s; v.y *= s; v.z *= s; v.w *= s;
    dst[i4] = v;
}

// ============================================================================
extern "C" void kernel_launch(void* const* d_in, const int* in_sizes, int n_in,
                              void* d_out, int out_size)
{
    (void)in_sizes; (void)n_in; (void)out_size;
    const float* Q    = (const float*)d_in[0];
    const float* Km   = (const float*)d_in[1];
    const float* Wrel = (const float*)d_in[2];
    const float* Wq   = (const float*)d_in[3];
    const float* Wk   = (const float*)d_in[4];
    const float* Wqa  = (const float*)d_in[5];
    const float* Wka  = (const float*)d_in[6];
    float* out = (float*)d_out;

    __nv_bfloat16 *q2, *k2, *qw2, *w2t, *wp2t, *qph, *qpl, *kph, *kpl;
    float *qpf, *kpf, *pQ, *pK, *lq, *lk;
    cudaGetSymbolAddress((void**)&q2,   g_Q2);
    cudaGetSymbolAddress((void**)&k2,   g_K2);
    cudaGetSymbolAddress((void**)&qw2,  g_Qw2);
    cudaGetSymbolAddress((void**)&w2t,  g_W2t);
    cudaGetSymbolAddress((void**)&wp2t, g_Wp2t);
    cudaGetSymbolAddress((void**)&qpf,  g_qpf);
    cudaGetSymbolAddress((void**)&kpf,  g_kpf);
    cudaGetSymbolAddress((void**)&qph,  g_qph);
    cudaGetSymbolAddress((void**)&qpl,  g_qpl);
    cudaGetSymbolAddress((void**)&kph,  g_kph);
    cudaGetSymbolAddress((void**)&kpl,  g_kpl);
    cudaGetSymbolAddress((void**)&pQ,   g_partQ);
    cudaGetSymbolAddress((void**)&pK,   g_partK);
    cudaGetSymbolAddress((void**)&lq,   g_logit_q);
    cudaGetSymbolAddress((void**)&lk,   g_logit_k);

    cudaFuncSetAttribute(qw_mma_kernel,    cudaFuncAttributeMaxDynamicSharedMemorySize, SMEM_MMA);
    cudaFuncSetAttribute(proj_slim_kernel, cudaFuncAttributeMaxDynamicSharedMemorySize, SMEM_SLIM);
    cudaFuncSetAttribute(rel_fused_kernel, cudaFuncAttributeMaxDynamicSharedMemorySize, SMEM_FUSED);

    const dim3 blk(256);
    // bf16 hi/lo splits of inputs + weight transposes
    split_kernel<<<dim3((BN * LN * DN) / 4 / 256, 2), blk>>>(Q, Km, q2, k2);
    prep_w2t<<<256, blk>>>(Wrel, w2t);
    prep_wp<<<128, blk>>>(Wq, Wk, wp2t);
    // projections (slim, both sides in one launch)
    proj_slim_kernel<<<dim3(512, 2), blk, SMEM_SLIM>>>(
        q2, k2, wp2t, qpf, kpf, qph, qpl, kph, kpl);
    // Qw (MMA, epilogue re-splits to bf16 hi/lo)
    qw_mma_kernel<<<dim3(512, 2), blk, SMEM_MMA>>>(q2, w2t, qw2);
    // fused rel + both score GEMMs -> partial buffers
    rel_fused_kernel<<<dim3(4, 4, BN), blk, SMEM_FUSED>>>(qw2, k2, kph, kpl, qph, qpl, pQ, pK);
    // partial reduce + tanh + @W_att -> logits
    att_reduce_kernel<<<dim3(BN * LN / 8, 2), blk>>>(qpf, kpf, pQ, pK, Wqa, Wka, lq, lk);
    // softmax -> weights in d_out
    softmax_kernel<<<dim3(BN, 2), 512>>>(lq, lk, out);
    // weighted outputs
    scale_kernel<<<dim3((BN * LN * DN) / 4 / 256, 2), 256>>>(Q, Km, out);
}

// round 9
// speedup vs baseline: 2.5377x; 1.0933x over previous
#include <cuda_runtime.h>
#include <cuda_bf16.h>
#include <math.h>
#include <stdint.h>

// Problem dims
#define BN 128
#define LN 512
#define DN 256
#define AN 64
#define KS 512   // compact split storage: [hi | lo] x 256; 12-stage schedule via maps

// Output layout (concatenated, reference tuple order)
#define OFF_WQ  ((size_t)0)
#define OFF_WK  ((size_t)BN * LN * DN)
#define OFF_QW  ((size_t)2 * BN * LN * DN)
#define OFF_KW  (OFF_QW + (size_t)BN * LN)

// -------- scratch (device globals; no allocation allowed) --------
__device__ __nv_bfloat16 g_Q2 [(size_t)BN * LN * KS];    // [hi|lo] of Q
__device__ __nv_bfloat16 g_K2 [(size_t)BN * LN * KS];    // [hi|lo] of K
__device__ __nv_bfloat16 g_Qw2[(size_t)BN * LN * KS];    // [hi|lo] of Qw
__device__ __nv_bfloat16 g_W2t[(size_t)DN * KS];         // W_rel^T [hi|lo]
__device__ __nv_bfloat16 g_Wp2t[2 * 64 * KS];            // Wq^T / Wk^T [hi|lo]
__device__ float g_qpf[(size_t)BN * LN * AN];            // q_proj fp32
__device__ float g_kpf[(size_t)BN * LN * AN];            // k_proj fp32
__device__ __nv_bfloat16 g_qph[(size_t)BN * LN * AN], g_qpl[(size_t)BN * LN * AN];
__device__ __nv_bfloat16 g_kph[(size_t)BN * LN * AN], g_kpl[(size_t)BN * LN * AN];
__device__ float g_partQ[(size_t)4 * BN * LN * AN];      // rel@kp partials (per n-tile)
__device__ float g_partK[(size_t)4 * BN * LN * AN];      // relT@qp partials (per m-tile)
__device__ float g_logit_q[BN * LN];
__device__ float g_logit_k[BN * LN];

// ======================= helpers (baseline PTX only) =======================
__device__ __forceinline__ uint32_t smem_to_u32(const void* p) {
    uint32_t a;
    asm("{ .reg .u64 t; cvta.to.shared.u64 t, %1; cvt.u32.u64 %0, t; }" : "=r"(a) : "l"(p));
    return a;
}
#define SMEM_SWIZZLE_128B(o) ((o) ^ (((o) >> 3) & 0x70))

__device__ __forceinline__ void cp_async16(uint32_t saddr, const void* g) {
    asm volatile("cp.async.cg.shared.global [%0], [%1], 16;" :: "r"(saddr), "l"(g));
}
#define CP_COMMIT  asm volatile("cp.async.commit_group;" ::: "memory")
#define CP_WAIT(n) asm volatile("cp.async.wait_group %0;" :: "n"(n) : "memory")

__device__ __forceinline__ void ldmatrix_x4(uint32_t& r0, uint32_t& r1, uint32_t& r2,
                                            uint32_t& r3, uint32_t addr) {
    asm volatile("ldmatrix.sync.aligned.m8n8.x4.shared.b16 {%0,%1,%2,%3}, [%4];"
                 : "=r"(r0), "=r"(r1), "=r"(r2), "=r"(r3) : "r"(addr));
}
__device__ __forceinline__ void ldmatrix_x4_trans(uint32_t& r0, uint32_t& r1, uint32_t& r2,
                                                  uint32_t& r3, uint32_t addr) {
    asm volatile("ldmatrix.sync.aligned.m8n8.x4.trans.shared.b16 {%0,%1,%2,%3}, [%4];"
                 : "=r"(r0), "=r"(r1), "=r"(r2), "=r"(r3) : "r"(addr));
}
__device__ __forceinline__ void mma_bf16(float* c, uint32_t a0, uint32_t a1, uint32_t a2,
                                         uint32_t a3, uint32_t b0, uint32_t b1) {
    asm volatile(
        "mma.sync.aligned.m16n8k16.row.col.f32.bf16.bf16.f32 "
        "{%0,%1,%2,%3}, {%4,%5,%6,%7}, {%8,%9}, {%0,%1,%2,%3};"
        : "+f"(c[0]), "+f"(c[1]), "+f"(c[2]), "+f"(c[3])
        : "r"(a0), "r"(a1), "r"(a2), "r"(a3), "r"(b0), "r"(b1));
}

__device__ __forceinline__ void split2(float x, __nv_bfloat16& hi, __nv_bfloat16& lo) {
    hi = __float2bfloat16(x);
    lo = __float2bfloat16(x - __bfloat162float(hi));
}
union BF2 { __nv_bfloat16 h[2]; uint32_t u; };

// Stage maps: logical stage s (0..11) -> physical 64-col chunk in [hi|lo] storage.
// Pairing: s 0-3 hi*hi, 4-7 lo*hi, 8-11 hi*lo.
__device__ __forceinline__ int amap(int s) { return s < 8 ? s : s - 8; }
__device__ __forceinline__ int bmap(int s) { return s < 4 ? s : s - 4; }

// ======================= warp-MMA mainloop (128x128 tile) =======================
#define NSTAGE  12
#define STAGE_BYTES 32768
#define SMEM_MMA (2 * STAGE_BYTES)

__device__ __forceinline__ void load_stage(uint32_t sbase,
    const __nv_bfloat16* __restrict__ A, const __nv_bfloat16* __restrict__ B,
    int s, int tid)
{
    const __nv_bfloat16* Ak = A + amap(s) * 64;
    const __nv_bfloat16* Bk = B + bmap(s) * 64;
#pragma unroll
    for (int i = 0; i < 4; ++i) {
        const int idx = tid + i * 256;            // 0..1023 16B chunks
        const int r = idx >> 3, c = idx & 7;
        const uint32_t off = SMEM_SWIZZLE_128B((uint32_t)(r * 128 + c * 16));
        cp_async16(sbase + off, Ak + (size_t)r * KS + c * 8);
        cp_async16(sbase + 16384 + off, Bk + (size_t)r * KS + c * 8);
    }
}

__device__ __forceinline__ void warp_mma_main(
    const __nv_bfloat16* __restrict__ A, const __nv_bfloat16* __restrict__ B,
    uint32_t smem_base, int tid, float acc[4][4][4])
{
    const int wid = tid >> 5, lane = tid & 31;
    const int mw = (wid >> 2) * 64, nw = (wid & 3) * 32;

    load_stage(smem_base, A, B, 0, tid);
    CP_COMMIT;

    int buf = 0;
    for (int s = 0; s < NSTAGE; ++s) {
        if (s + 1 < NSTAGE) {
            load_stage(smem_base + (buf ^ 1) * STAGE_BYTES, A, B, s + 1, tid);
            CP_COMMIT;
            CP_WAIT(1);
        } else {
            CP_COMMIT;
            CP_WAIT(0);
        }
        __syncthreads();

        const uint32_t sA = smem_base + buf * STAGE_BYTES;
        const uint32_t sB = sA + 16384;
#pragma unroll
        for (int kk = 0; kk < 64; kk += 16) {
            uint32_t a[4][4], b[4][2];
#pragma unroll
            for (int mf = 0; mf < 4; ++mf) {
                const uint32_t off = SMEM_SWIZZLE_128B((uint32_t)(
                    (mw + mf * 16 + (lane & 15)) * 128 + kk * 2 + ((lane >> 4) << 4)));
                ldmatrix_x4(a[mf][0], a[mf][1], a[mf][2], a[mf][3], sA + off);
            }
#pragma unroll
            for (int nb = 0; nb < 2; ++nb) {
                const int row = nw + nb * 16 + ((lane >> 4) & 1) * 8 + (lane & 7);
                const int kof = kk * 2 + (((lane >> 3) & 1) << 4);
                const uint32_t off = SMEM_SWIZZLE_128B((uint32_t)(row * 128 + kof));
                ldmatrix_x4(b[nb * 2][0], b[nb * 2][1], b[nb * 2 + 1][0], b[nb * 2 + 1][1],
                            sB + off);
            }
#pragma unroll
            for (int mf = 0; mf < 4; ++mf)
#pragma unroll
                for (int nf = 0; nf < 4; ++nf)
                    mma_bf16(acc[mf][nf], a[mf][0], a[mf][1], a[mf][2], a[mf][3],
                             b[nf][0], b[nf][1]);
        }
        __syncthreads();
        buf ^= 1;
    }
}

// ======================= fused rel + att-score kernel =======================
#define R_PITCH  272          // 128 cols bf16 (256B) + 16B pad
#define P_PITCH  144          // 64 cols bf16 (128B) + 16B pad
#define RH_OFF   0
#define RL_OFF   34816
#define PJH_OFF  69632
#define PJL_OFF  88064
#define SMEM_FUSED 106496

__global__ void __launch_bounds__(256, 2) rel_fused_kernel(
    const __nv_bfloat16* __restrict__ Qw2, const __nv_bfloat16* __restrict__ K2,
    const __nv_bfloat16* __restrict__ kph, const __nv_bfloat16* __restrict__ kpl,
    const __nv_bfloat16* __restrict__ qph, const __nv_bfloat16* __restrict__ qpl,
    float* __restrict__ partQ, float* __restrict__ partK)
{
    extern __shared__ char smem[];
    const uint32_t sb = smem_to_u32(smem);
    const int tid = threadIdx.x, wid = tid >> 5, lane = tid & 31;
    const int mt = blockIdx.x, nt = blockIdx.y, b = blockIdx.z;
    const int m0 = mt * 128, n0 = nt * 128;

    float acc[4][4][4] = {};
    warp_mma_main(Qw2 + ((size_t)b * LN + m0) * KS,
                  K2  + ((size_t)b * LN + n0) * KS, sb, tid, acc);

    // prefetch kp hi/lo tiles (rows n0..n0+127) while storing rel to smem
    {
        const __nv_bfloat16* kh = kph + ((size_t)b * LN + n0) * AN;
        const __nv_bfloat16* kl = kpl + ((size_t)b * LN + n0) * AN;
#pragma unroll
        for (int i = 0; i < 4; ++i) {
            const int idx = tid + i * 256, r = idx >> 3, c = idx & 7;
            cp_async16(sb + PJH_OFF + r * P_PITCH + c * 16, kh + (size_t)r * AN + c * 8);
            cp_async16(sb + PJL_OFF + r * P_PITCH + c * 16, kl + (size_t)r * AN + c * 8);
        }
        CP_COMMIT;
    }

    // tanh + hi/lo split -> smem rel tiles
    const int mw = (wid >> 2) * 64, nw = (wid & 3) * 32;
    const int lr = lane >> 2, lc = (lane & 3) * 2;
#pragma unroll
    for (int mf = 0; mf < 4; ++mf)
#pragma unroll
        for (int nf = 0; nf < 4; ++nf)
#pragma unroll
            for (int p = 0; p < 2; ++p) {
                const int rr = mw + mf * 16 + lr + p * 8;
                const int cc = nw + nf * 8 + lc;
                BF2 H, L;
                split2(tanhf(acc[mf][nf][2 * p + 0]), H.h[0], L.h[0]);
                split2(tanhf(acc[mf][nf][2 * p + 1]), H.h[1], L.h[1]);
                *(uint32_t*)(smem + RH_OFF + rr * R_PITCH + cc * 2) = H.u;
                *(uint32_t*)(smem + RL_OFF + rr * R_PITCH + cc * 2) = L.u;
            }
    CP_WAIT(0);
    __syncthreads();

    // ---- C2[m][a] = sum_n rel[m][n] * kp[n0+n][a]  (warp w: m rows 16w..16w+16)
    float c2[8][4] = {};
#pragma unroll
    for (int term = 0; term < 3; ++term) {
        const uint32_t As = sb + (term == 1 ? RL_OFF : RH_OFF);
        const uint32_t Bs = sb + (term == 2 ? PJL_OFF : PJH_OFF);
#pragma unroll
        for (int kk = 0; kk < 128; kk += 16) {
            uint32_t a0, a1, a2, a3;
            ldmatrix_x4(a0, a1, a2, a3,
                As + (16 * wid + (lane & 15)) * R_PITCH + (kk + ((lane >> 4) << 3)) * 2);
#pragma unroll
            for (int ab = 0; ab < 4; ++ab) {
                uint32_t t0, t1, t2, t3;
                ldmatrix_x4_trans(t0, t1, t2, t3,
                    Bs + (kk + (lane & 15)) * P_PITCH + (ab * 16 + ((lane >> 4) << 3)) * 2);
                mma_bf16(c2[2 * ab],     a0, a1, a2, a3, t0, t1);
                mma_bf16(c2[2 * ab + 1], a0, a1, a2, a3, t2, t3);
            }
        }
    }
    {
        float* base = partQ + ((size_t)(nt * BN + b) * LN + m0 + 16 * wid) * AN;
#pragma unroll
        for (int j = 0; j < 8; ++j) {
            const int col = j * 8 + lc;
            *(float2*)(base + (size_t)lr * AN + col)       = make_float2(c2[j][0], c2[j][1]);
            *(float2*)(base + (size_t)(lr + 8) * AN + col) = make_float2(c2[j][2], c2[j][3]);
        }
    }
    __syncthreads();   // all warps done reading kp tiles

    // load qp hi/lo tiles (rows m0..m0+127) into same region
    {
        const __nv_bfloat16* qh = qph + ((size_t)b * LN + m0) * AN;
        const __nv_bfloat16* ql = qpl + ((size_t)b * LN + m0) * AN;
#pragma unroll
        for (int i = 0; i < 4; ++i) {
            const int idx = tid + i * 256, r = idx >> 3, c = idx & 7;
            cp_async16(sb + PJH_OFF + r * P_PITCH + c * 16, qh + (size_t)r * AN + c * 8);
            cp_async16(sb + PJL_OFF + r * P_PITCH + c * 16, ql + (size_t)r * AN + c * 8);
        }
        CP_COMMIT; CP_WAIT(0);
    }
    __syncthreads();

    // ---- C3[n][a] = sum_m rel[m][n] * qp[m0+m][a]  (A = rel^T via ldmatrix.trans)
    float c3[8][4] = {};
    const int g = lane >> 3;
#pragma unroll
    for (int term = 0; term < 3; ++term) {
        const uint32_t As = sb + (term == 1 ? RL_OFF : RH_OFF);
        const uint32_t Bs = sb + (term == 2 ? PJL_OFF : PJH_OFF);
#pragma unroll
        for (int kk = 0; kk < 128; kk += 16) {
            uint32_t a0, a1, a2, a3;
            ldmatrix_x4_trans(a0, a1, a2, a3,
                As + (kk + ((g >> 1) << 3) + (lane & 7)) * R_PITCH
                   + (16 * wid + ((g & 1) << 3)) * 2);
#pragma unroll
            for (int ab = 0; ab < 4; ++ab) {
                uint32_t t0, t1, t2, t3;
                ldmatrix_x4_trans(t0, t1, t2, t3,
                    Bs + (kk + (lane & 15)) * P_PITCH + (ab * 16 + ((lane >> 4) << 3)) * 2);
                mma_bf16(c3[2 * ab],     a0, a1, a2, a3, t0, t1);
                mma_bf16(c3[2 * ab + 1], a0, a1, a2, a3, t2, t3);
            }
        }
    }
    {
        float* base = partK + ((size_t)(mt * BN + b) * LN + n0 + 16 * wid) * AN;
#pragma unroll
        for (int j = 0; j < 8; ++j) {
            const int col = j * 8 + lc;
            *(float2*)(base + (size_t)lr * AN + col)       = make_float2(c3[j][0], c3[j][1]);
            *(float2*)(base + (size_t)(lr + 8) * AN + col) = make_float2(c3[j][2], c3[j][3]);
        }
    }
}

// ======================= Qw2 = split(Q2 @ W2t^T) =======================
__global__ void __launch_bounds__(256, 2) qw_mma_kernel(
    const __nv_bfloat16* __restrict__ Q2, const __nv_bfloat16* __restrict__ W2t,
    __nv_bfloat16* __restrict__ Qw2)
{
    extern __shared__ char smem[];
    const uint32_t smem_base = smem_to_u32(smem);
    const int tid = threadIdx.x;
    const int m0 = blockIdx.x * 128, n0 = blockIdx.y * 128;

    float acc[4][4][4] = {};
    warp_mma_main(Q2 + (size_t)m0 * KS, W2t + (size_t)n0 * KS, smem_base, tid, acc);

    const int wid = tid >> 5, lane = tid & 31;
    const int mw = (wid >> 2) * 64, nw = (wid & 3) * 32;
    const int lr = lane >> 2, lc = (lane & 3) * 2;
#pragma unroll
    for (int mf = 0; mf < 4; ++mf) {
        const int row = m0 + mw + mf * 16 + lr;
#pragma unroll
        for (int nf = 0; nf < 4; ++nf) {
            const int col = n0 + nw + nf * 8 + lc;
#pragma unroll
            for (int p = 0; p < 2; ++p) {
                const int rr = row + p * 8;
                BF2 H, L;
                split2(acc[mf][nf][2 * p + 0], H.h[0], L.h[0]);
                split2(acc[mf][nf][2 * p + 1], H.h[1], L.h[1]);
                __nv_bfloat16* o = Qw2 + (size_t)rr * KS + col;
                *(uint32_t*)(o)       = H.u;
                *(uint32_t*)(o + 256) = L.u;
            }
        }
    }
}

// ======================= slim projection kernel (N=64) ======================
// CTA: 128 m-rows x 64 a-cols, 12 stages. Stage = A(16KB) + W(8KB) = 24KB, x2.
#define SLIM_STAGE 24576
#define SMEM_SLIM  (2 * SLIM_STAGE)

__device__ __forceinline__ void load_stage_slim(uint32_t sbase,
    const __nv_bfloat16* __restrict__ A, const __nv_bfloat16* __restrict__ W,
    int s, int tid)
{
    const __nv_bfloat16* Ak = A + amap(s) * 64;
    const __nv_bfloat16* Wk = W + bmap(s) * 64;
#pragma unroll
    for (int i = 0; i < 4; ++i) {
        const int idx = tid + i * 256;            // 1024 chunks: A 128 rows x 8
        const int r = idx >> 3, c = idx & 7;
        const uint32_t off = SMEM_SWIZZLE_128B((uint32_t)(r * 128 + c * 16));
        cp_async16(sbase + off, Ak + (size_t)r * KS + c * 8);
    }
#pragma unroll
    for (int i = 0; i < 2; ++i) {
        const int idx = tid + i * 256;            // 512 chunks: W 64 rows x 8
        const int r = idx >> 3, c = idx & 7;
        const uint32_t off = SMEM_SWIZZLE_128B((uint32_t)(r * 128 + c * 16));
        cp_async16(sbase + 16384 + off, Wk + (size_t)r * KS + c * 8);
    }
}

__global__ void __launch_bounds__(256, 3) proj_slim_kernel(
    const __nv_bfloat16* __restrict__ Q2, const __nv_bfloat16* __restrict__ K2,
    const __nv_bfloat16* __restrict__ Wp2t,
    float* __restrict__ qpf, float* __restrict__ kpf,
    __nv_bfloat16* __restrict__ qph, __nv_bfloat16* __restrict__ qpl,
    __nv_bfloat16* __restrict__ kph, __nv_bfloat16* __restrict__ kpl)
{
    extern __shared__ char smem[];
    const uint32_t sb = smem_to_u32(smem);
    const int tid = threadIdx.x, wid = tid >> 5, lane = tid & 31;
    const int side = blockIdx.y;
    const int m0 = blockIdx.x * 128;
    const __nv_bfloat16* A = (side ? K2 : Q2) + (size_t)m0 * KS;
    const __nv_bfloat16* W = Wp2t + (size_t)side * 64 * KS;
    float* pf = side ? kpf : qpf;
    __nv_bfloat16* ph = side ? kph : qph;
    __nv_bfloat16* pl = side ? kpl : qpl;

    const int mw = (wid >> 1) * 32, nw = (wid & 1) * 32;

    float acc[2][4][4] = {};
    load_stage_slim(sb, A, W, 0, tid);
    CP_COMMIT;

    int buf = 0;
    for (int s = 0; s < NSTAGE; ++s) {
        if (s + 1 < NSTAGE) {
            load_stage_slim(sb + (buf ^ 1) * SLIM_STAGE, A, W, s + 1, tid);
            CP_COMMIT;
            CP_WAIT(1);
        } else {
            CP_COMMIT;
            CP_WAIT(0);
        }
        __syncthreads();

        const uint32_t sA = sb + buf * SLIM_STAGE;
        const uint32_t sW = sA + 16384;
#pragma unroll
        for (int kk = 0; kk < 64; kk += 16) {
            uint32_t a[2][4], b[4][2];
#pragma unroll
            for (int mf = 0; mf < 2; ++mf) {
                const uint32_t off = SMEM_SWIZZLE_128B((uint32_t)(
                    (mw + mf * 16 + (lane & 15)) * 128 + kk * 2 + ((lane >> 4) << 4)));
                ldmatrix_x4(a[mf][0], a[mf][1], a[mf][2], a[mf][3], sA + off);
            }
#pragma unroll
            for (int nb = 0; nb < 2; ++nb) {
                const int row = nw + nb * 16 + ((lane >> 4) & 1) * 8 + (lane & 7);
                const int kof = kk * 2 + (((lane >> 3) & 1) << 4);
                const uint32_t off = SMEM_SWIZZLE_128B((uint32_t)(row * 128 + kof));
                ldmatrix_x4(b[nb * 2][0], b[nb * 2][1], b[nb * 2 + 1][0], b[nb * 2 + 1][1],
                            sW + off);
            }
#pragma unroll
            for (int mf = 0; mf < 2; ++mf)
#pragma unroll
                for (int nf = 0; nf < 4; ++nf)
                    mma_bf16(acc[mf][nf], a[mf][0], a[mf][1], a[mf][2], a[mf][3],
                             b[nf][0], b[nf][1]);
        }
        __syncthreads();
        buf ^= 1;
    }

    const int lr = lane >> 2, lc = (lane & 3) * 2;
#pragma unroll
    for (int mf = 0; mf < 2; ++mf) {
#pragma unroll
        for (int nf = 0; nf < 4; ++nf) {
            const int col = nw + nf * 8 + lc;
#pragma unroll
            for (int p = 0; p < 2; ++p) {
                const int row = m0 + mw + mf * 16 + lr + p * 8;
                const float v0 = acc[mf][nf][2 * p + 0];
                const float v1 = acc[mf][nf][2 * p + 1];
                *(float2*)(pf + (size_t)row * AN + col) = make_float2(v0, v1);
                BF2 H, L;
                split2(v0, H.h[0], L.h[0]);
                split2(v1, H.h[1], L.h[1]);
                *(uint32_t*)(ph + (size_t)row * AN + col) = H.u;
                *(uint32_t*)(pl + (size_t)row * AN + col) = L.u;
            }
        }
    }
}

// ======================= split / prep kernels =======================
// Both Q and K stored compact [hi|lo]; A/B pairing handled by stage maps.
__global__ void __launch_bounds__(256) split_kernel(
    const float* __restrict__ Q, const float* __restrict__ Kmat,
    __nv_bfloat16* __restrict__ Q2, __nv_bfloat16* __restrict__ K2)
{
    const int sel = blockIdx.y;
    const float* src = sel ? Kmat : Q;
    __nv_bfloat16* dst = sel ? K2 : Q2;
    const size_t i4 = (size_t)blockIdx.x * 256 + threadIdx.x;
    const size_t row = i4 >> 6;
    const int c = (int)(i4 & 63) * 4;
    float4 v = ((const float4*)src)[i4];
    union { __nv_bfloat16 b[4]; uint2 u; } h, l;
    split2(v.x, h.b[0], l.b[0]); split2(v.y, h.b[1], l.b[1]);
    split2(v.z, h.b[2], l.b[2]); split2(v.w, h.b[3], l.b[3]);
    __nv_bfloat16* o = dst + row * KS + c;
    *(uint2*)(o)       = h.u;
    *(uint2*)(o + 256) = l.u;
}

__global__ void __launch_bounds__(256) prep_w2t(
    const float* __restrict__ Wrel, __nv_bfloat16* __restrict__ W2t)
{
    const int idx = blockIdx.x * 256 + threadIdx.x;   // 65536
    const int d = idx >> 8, n = idx & 255;
    __nv_bfloat16 hi, lo;
    split2(Wrel[d * 256 + n], hi, lo);
    W2t[(size_t)n * KS + d]       = hi;
    W2t[(size_t)n * KS + 256 + d] = lo;
}

// Wq/Wk [256][64] -> [64 rows][512] slabs, compact [hi|lo] (same for both sides)
__global__ void __launch_bounds__(256) prep_wp(
    const float* __restrict__ Wq, const float* __restrict__ Wk,
    __nv_bfloat16* __restrict__ Wp2t)
{
    const int idx = blockIdx.x * 256 + threadIdx.x;   // 32768
    const int side = idx >> 14;
    const int d = (idx >> 6) & 255, a = idx & 63;
    const float* W = side ? Wk : Wq;
    __nv_bfloat16 hi, lo;
    split2(W[d * 64 + a], hi, lo);
    __nv_bfloat16* slab = Wp2t + (size_t)side * 64 * KS;
    slab[(size_t)a * KS + d]       = hi;
    slab[(size_t)a * KS + 256 + d] = lo;
}

// ======================= partial-sum + tanh + dot reduce ====================
__global__ void __launch_bounds__(256) att_reduce_kernel(
    const float* __restrict__ qpf, const float* __restrict__ kpf,
    const float* __restrict__ partQ, const float* __restrict__ partK,
    const float* __restrict__ Wqa, const float* __restrict__ Wka,
    float* __restrict__ lq, float* __restrict__ lk)
{
    const int side = blockIdx.y;
    const int wid = threadIdx.x >> 5, lane = threadIdx.x & 31;
    const size_t gm = (size_t)blockIdx.x * 8 + wid;   // b*LN + m
    const float* pf   = side ? kpf   : qpf;
    const float* part = side ? partK : partQ;
    const float* w    = side ? Wka   : Wqa;
    float* out        = side ? lk    : lq;

    float s = 0.f;
#pragma unroll
    for (int h = 0; h < 2; ++h) {
        const int a = lane + h * 32;
        float v = pf[gm * AN + a];
#pragma unroll
        for (int t = 0; t < 4; ++t)
            v += part[((size_t)t * BN * LN + gm) * AN + a];
        s += tanhf(v) * w[a];
    }
#pragma unroll
    for (int o = 16; o; o >>= 1) s += __shfl_xor_sync(0xFFFFFFFFu, s, o);
    if (lane == 0) out[gm] = s;
}

// ============================================================================
__global__ void __launch_bounds__(512) softmax_kernel(
    const float* __restrict__ lq, const float* __restrict__ lk,
    float* __restrict__ out)
{
    __shared__ float red[512];
    const int b = blockIdx.x, sel = blockIdx.y, t = threadIdx.x;
    const float* l = (sel ? lk : lq) + (size_t)b * LN;
    float* o = out + (sel ? OFF_KW : OFF_QW) + (size_t)b * LN;

    float v = l[t];
    red[t] = v; __syncthreads();
    for (int s = 256; s > 0; s >>= 1) {
        if (t < s) red[t] = fmaxf(red[t], red[t + s]);
        __syncthreads();
    }
    const float mx = red[0];
    __syncthreads();
    const float e = expf(v - mx);
    red[t] = e; __syncthreads();
    for (int s = 256; s > 0; s >>= 1) {
        if (t < s) red[t] += red[t + s];
        __syncthreads();
    }
    o[t] = e / red[0];
}

__global__ void __launch_bounds__(256) scale_kernel(
    const float* __restrict__ Q, const float* __restrict__ Kmat,
    float* __restrict__ out)
{
    const int sel = blockIdx.y;
    const size_t i4 = (size_t)blockIdx.x * 256 + threadIdx.x;
    const float4* src = (const float4*)(sel ? Kmat : Q);
    const float*  w   = out + (sel ? OFF_KW : OFF_QW);
    float4*       dst = (float4*)(out + (sel ? OFF_WK : OFF_WQ));

    const size_t e = i4 * 4;
    const int b = (int)(e >> 17);
    const int l = (int)((e >> 8) & 511);
    const float s = w[b * LN + l];
    float4 v = src[i4];
    v.x *= s; v.y *= s; v.z *= s; v.w *= s;
    dst[i4] = v;
}

// ============================================================================
extern "C" void kernel_launch(void* const* d_in, const int* in_sizes, int n_in,
                              void* d_out, int out_size)
{
    (void)in_sizes; (void)n_in; (void)out_size;
    const float* Q    = (const float*)d_in[0];
    const float* Km   = (const float*)d_in[1];
    const float* Wrel = (const float*)d_in[2];
    const float* Wq   = (const float*)d_in[3];
    const float* Wk   = (const float*)d_in[4];
    const float* Wqa  = (const float*)d_in[5];
    const float* Wka  = (const float*)d_in[6];
    float* out = (float*)d_out;

    __nv_bfloat16 *q2, *k2, *qw2, *w2t, *wp2t, *qph, *qpl, *kph, *kpl;
    float *qpf, *kpf, *pQ, *pK, *lq, *lk;
    cudaGetSymbolAddress((void**)&q2,   g_Q2);
    cudaGetSymbolAddress((void**)&k2,   g_K2);
    cudaGetSymbolAddress((void**)&qw2,  g_Qw2);
    cudaGetSymbolAddress((void**)&w2t,  g_W2t);
    cudaGetSymbolAddress((void**)&wp2t, g_Wp2t);
    cudaGetSymbolAddress((void**)&qpf,  g_qpf);
    cudaGetSymbolAddress((void**)&kpf,  g_kpf);
    cudaGetSymbolAddress((void**)&qph,  g_qph);
    cudaGetSymbolAddress((void**)&qpl,  g_qpl);
    cudaGetSymbolAddress((void**)&kph,  g_kph);
    cudaGetSymbolAddress((void**)&kpl,  g_kpl);
    cudaGetSymbolAddress((void**)&pQ,   g_partQ);
    cudaGetSymbolAddress((void**)&pK,   g_partK);
    cudaGetSymbolAddress((void**)&lq,   g_logit_q);
    cudaGetSymbolAddress((void**)&lk,   g_logit_k);

    cudaFuncSetAttribute(qw_mma_kernel,    cudaFuncAttributeMaxDynamicSharedMemorySize, SMEM_MMA);
    cudaFuncSetAttribute(proj_slim_kernel, cudaFuncAttributeMaxDynamicSharedMemorySize, SMEM_SLIM);
    cudaFuncSetAttribute(rel_fused_kernel, cudaFuncAttributeMaxDynamicSharedMemorySize, SMEM_FUSED);

    const dim3 blk(256);
    // compact [hi|lo] splits of inputs + weight transposes
    split_kernel<<<dim3((BN * LN * DN) / 4 / 256, 2), blk>>>(Q, Km, q2, k2);
    prep_w2t<<<256, blk>>>(Wrel, w2t);
    prep_wp<<<128, blk>>>(Wq, Wk, wp2t);
    // projections (slim, both sides in one launch)
    proj_slim_kernel<<<dim3(512, 2), blk, SMEM_SLIM>>>(
        q2, k2, wp2t, qpf, kpf, qph, qpl, kph, kpl);
    // Qw (MMA, epilogue re-splits to compact bf16 hi/lo)
    qw_mma_kernel<<<dim3(512, 2), blk, SMEM_MMA>>>(q2, w2t, qw2);
    // fused rel + both score GEMMs -> partial buffers
    rel_fused_kernel<<<dim3(4, 4, BN), blk, SMEM_FUSED>>>(qw2, k2, kph, kpl, qph, qpl, pQ, pK);
    // partial reduce + tanh + @W_att -> logits
    att_reduce_kernel<<<dim3(BN * LN / 8, 2), blk>>>(qpf, kpf, pQ, pK, Wqa, Wka, lq, lk);
    // softmax -> weights in d_out
    softmax_kernel<<<dim3(BN, 2), 512>>>(lq, lk, out);
    // weighted outputs
    scale_kernel<<<dim3((BN * LN * DN) / 4 / 256, 2), 256>>>(Q, Km, out);
}

// round 10
// speedup vs baseline: 2.5708x; 1.0130x over previous
#include <cuda_runtime.h>
#include <cuda_bf16.h>
#include <math.h>
#include <stdint.h>

// Problem dims
#define BN 128
#define LN 512
#define DN 256
#define AN 64
#define KS 512   // compact split storage: [hi | lo] x 256; 12-stage schedule via maps

// Output layout (concatenated, reference tuple order)
#define OFF_WQ  ((size_t)0)
#define OFF_WK  ((size_t)BN * LN * DN)
#define OFF_QW  ((size_t)2 * BN * LN * DN)
#define OFF_KW  (OFF_QW + (size_t)BN * LN)

// -------- scratch (device globals; no allocation allowed) --------
__device__ __nv_bfloat16 g_Q2 [(size_t)BN * LN * KS];    // [hi|lo] of Q
__device__ __nv_bfloat16 g_K2 [(size_t)BN * LN * KS];    // [hi|lo] of K
__device__ __nv_bfloat16 g_Qw2[(size_t)BN * LN * KS];    // [hi|lo] of Qw
__device__ __nv_bfloat16 g_W2t[(size_t)DN * KS];         // W_rel^T [hi|lo]
__device__ __nv_bfloat16 g_Wp2t[2 * 64 * KS];            // Wq^T / Wk^T [hi|lo]
// accumulators: proj writes base value; rel_fused REDs score-GEMM terms on top
__device__ float g_accQ[(size_t)BN * LN * AN];           // q_proj + rel@kp
__device__ float g_accK[(size_t)BN * LN * AN];           // k_proj + relT@qp
__device__ __nv_bfloat16 g_qph[(size_t)BN * LN * AN], g_qpl[(size_t)BN * LN * AN];
__device__ __nv_bfloat16 g_kph[(size_t)BN * LN * AN], g_kpl[(size_t)BN * LN * AN];
__device__ float g_logit_q[BN * LN];
__device__ float g_logit_k[BN * LN];

// ======================= helpers (baseline PTX only) =======================
__device__ __forceinline__ uint32_t smem_to_u32(const void* p) {
    uint32_t a;
    asm("{ .reg .u64 t; cvta.to.shared.u64 t, %1; cvt.u32.u64 %0, t; }" : "=r"(a) : "l"(p));
    return a;
}
#define SMEM_SWIZZLE_128B(o) ((o) ^ (((o) >> 3) & 0x70))

__device__ __forceinline__ void cp_async16(uint32_t saddr, const void* g) {
    asm volatile("cp.async.cg.shared.global [%0], [%1], 16;" :: "r"(saddr), "l"(g));
}
#define CP_COMMIT  asm volatile("cp.async.commit_group;" ::: "memory")
#define CP_WAIT(n) asm volatile("cp.async.wait_group %0;" :: "n"(n) : "memory")

__device__ __forceinline__ void ldmatrix_x4(uint32_t& r0, uint32_t& r1, uint32_t& r2,
                                            uint32_t& r3, uint32_t addr) {
    asm volatile("ldmatrix.sync.aligned.m8n8.x4.shared.b16 {%0,%1,%2,%3}, [%4];"
                 : "=r"(r0), "=r"(r1), "=r"(r2), "=r"(r3) : "r"(addr));
}
__device__ __forceinline__ void ldmatrix_x4_trans(uint32_t& r0, uint32_t& r1, uint32_t& r2,
                                                  uint32_t& r3, uint32_t addr) {
    asm volatile("ldmatrix.sync.aligned.m8n8.x4.trans.shared.b16 {%0,%1,%2,%3}, [%4];"
                 : "=r"(r0), "=r"(r1), "=r"(r2), "=r"(r3) : "r"(addr));
}
__device__ __forceinline__ void mma_bf16(float* c, uint32_t a0, uint32_t a1, uint32_t a2,
                                         uint32_t a3, uint32_t b0, uint32_t b1) {
    asm volatile(
        "mma.sync.aligned.m16n8k16.row.col.f32.bf16.bf16.f32 "
        "{%0,%1,%2,%3}, {%4,%5,%6,%7}, {%8,%9}, {%0,%1,%2,%3};"
        : "+f"(c[0]), "+f"(c[1]), "+f"(c[2]), "+f"(c[3])
        : "r"(a0), "r"(a1), "r"(a2), "r"(a3), "r"(b0), "r"(b1));
}

__device__ __forceinline__ void split2(float x, __nv_bfloat16& hi, __nv_bfloat16& lo) {
    hi = __float2bfloat16(x);
    lo = __float2bfloat16(x - __bfloat162float(hi));
}
union BF2 { __nv_bfloat16 h[2]; uint32_t u; };

// Stage maps: logical stage s (0..11) -> physical 64-col chunk in [hi|lo] storage.
// Pairing: s 0-3 hi*hi, 4-7 lo*hi, 8-11 hi*lo.
__device__ __forceinline__ int amap(int s) { return s < 8 ? s : s - 8; }
__device__ __forceinline__ int bmap(int s) { return s < 4 ? s : s - 4; }

// ======================= warp-MMA mainloop (128x128 tile) =======================
// 3-stage cp.async ring, ONE __syncthreads per stage.
#define NSTAGE  12
#define STAGE_BYTES 32768
#define SMEM_MMA (3 * STAGE_BYTES)

__device__ __forceinline__ void load_stage(uint32_t sbase,
    const __nv_bfloat16* __restrict__ A, const __nv_bfloat16* __restrict__ B,
    int s, int tid)
{
    const __nv_bfloat16* Ak = A + amap(s) * 64;
    const __nv_bfloat16* Bk = B + bmap(s) * 64;
#pragma unroll
    for (int i = 0; i < 4; ++i) {
        const int idx = tid + i * 256;            // 0..1023 16B chunks
        const int r = idx >> 3, c = idx & 7;
        const uint32_t off = SMEM_SWIZZLE_128B((uint32_t)(r * 128 + c * 16));
        cp_async16(sbase + off, Ak + (size_t)r * KS + c * 8);
        cp_async16(sbase + 16384 + off, Bk + (size_t)r * KS + c * 8);
    }
}

__device__ __forceinline__ void warp_mma_main(
    const __nv_bfloat16* __restrict__ A, const __nv_bfloat16* __restrict__ B,
    uint32_t smem_base, int tid, float acc[4][4][4])
{
    const int wid = tid >> 5, lane = tid & 31;
    const int mw = (wid >> 2) * 64, nw = (wid & 3) * 32;

    load_stage(smem_base + 0 * STAGE_BYTES, A, B, 0, tid); CP_COMMIT;
    load_stage(smem_base + 1 * STAGE_BYTES, A, B, 1, tid); CP_COMMIT;

    for (int s = 0; s < NSTAGE; ++s) {
        CP_WAIT(1);            // stage s group complete (groups retire in order)
        __syncthreads();       // publish stage s; fences reuse of buf[(s+2)%3]
        if (s + 2 < NSTAGE)
            load_stage(smem_base + ((s + 2) % 3) * STAGE_BYTES, A, B, s + 2, tid);
        CP_COMMIT;

        const uint32_t sA = smem_base + (s % 3) * STAGE_BYTES;
        const uint32_t sB = sA + 16384;
#pragma unroll
        for (int kk = 0; kk < 64; kk += 16) {
            uint32_t a[4][4], b[4][2];
#pragma unroll
            for (int mf = 0; mf < 4; ++mf) {
                const uint32_t off = SMEM_SWIZZLE_128B((uint32_t)(
                    (mw + mf * 16 + (lane & 15)) * 128 + kk * 2 + ((lane >> 4) << 4)));
                ldmatrix_x4(a[mf][0], a[mf][1], a[mf][2], a[mf][3], sA + off);
            }
#pragma unroll
            for (int nb = 0; nb < 2; ++nb) {
                const int row = nw + nb * 16 + ((lane >> 4) & 1) * 8 + (lane & 7);
                const int kof = kk * 2 + (((lane >> 3) & 1) << 4);
                const uint32_t off = SMEM_SWIZZLE_128B((uint32_t)(row * 128 + kof));
                ldmatrix_x4(b[nb * 2][0], b[nb * 2][1], b[nb * 2 + 1][0], b[nb * 2 + 1][1],
                            sB + off);
            }
#pragma unroll
            for (int mf = 0; mf < 4; ++mf)
#pragma unroll
                for (int nf = 0; nf < 4; ++nf)
                    mma_bf16(acc[mf][nf], a[mf][0], a[mf][1], a[mf][2], a[mf][3],
                             b[nf][0], b[nf][1]);
        }
    }
    __syncthreads();   // all warps done with ring before caller reuses smem
}

// ======================= fused rel + att-score kernel =======================
#define R_PITCH  272          // 128 cols bf16 (256B) + 16B pad
#define P_PITCH  144          // 64 cols bf16 (128B) + 16B pad
#define RH_OFF   0
#define RL_OFF   34816
#define PJH_OFF  69632
#define PJL_OFF  88064
#define SMEM_FUSED 106496     // >= 3*STAGE_BYTES mainloop ring

__global__ void __launch_bounds__(256, 2) rel_fused_kernel(
    const __nv_bfloat16* __restrict__ Qw2, const __nv_bfloat16* __restrict__ K2,
    const __nv_bfloat16* __restrict__ kph, const __nv_bfloat16* __restrict__ kpl,
    const __nv_bfloat16* __restrict__ qph, const __nv_bfloat16* __restrict__ qpl,
    float* __restrict__ accQ, float* __restrict__ accK)
{
    extern __shared__ char smem[];
    const uint32_t sb = smem_to_u32(smem);
    const int tid = threadIdx.x, wid = tid >> 5, lane = tid & 31;
    const int mt = blockIdx.x, nt = blockIdx.y, b = blockIdx.z;
    const int m0 = mt * 128, n0 = nt * 128;

    float acc[4][4][4] = {};
    warp_mma_main(Qw2 + ((size_t)b * LN + m0) * KS,
                  K2  + ((size_t)b * LN + n0) * KS, sb, tid, acc);

    // prefetch kp hi/lo tiles (rows n0..n0+127) while storing rel to smem
    {
        const __nv_bfloat16* kh = kph + ((size_t)b * LN + n0) * AN;
        const __nv_bfloat16* kl = kpl + ((size_t)b * LN + n0) * AN;
#pragma unroll
        for (int i = 0; i < 4; ++i) {
            const int idx = tid + i * 256, r = idx >> 3, c = idx & 7;
            cp_async16(sb + PJH_OFF + r * P_PITCH + c * 16, kh + (size_t)r * AN + c * 8);
            cp_async16(sb + PJL_OFF + r * P_PITCH + c * 16, kl + (size_t)r * AN + c * 8);
        }
        CP_COMMIT;
    }

    // tanh + hi/lo split -> smem rel tiles
    const int mw = (wid >> 2) * 64, nw = (wid & 3) * 32;
    const int lr = lane >> 2, lc = (lane & 3) * 2;
#pragma unroll
    for (int mf = 0; mf < 4; ++mf)
#pragma unroll
        for (int nf = 0; nf < 4; ++nf)
#pragma unroll
            for (int p = 0; p < 2; ++p) {
                const int rr = mw + mf * 16 + lr + p * 8;
                const int cc = nw + nf * 8 + lc;
                BF2 H, L;
                split2(tanhf(acc[mf][nf][2 * p + 0]), H.h[0], L.h[0]);
                split2(tanhf(acc[mf][nf][2 * p + 1]), H.h[1], L.h[1]);
                *(uint32_t*)(smem + RH_OFF + rr * R_PITCH + cc * 2) = H.u;
                *(uint32_t*)(smem + RL_OFF + rr * R_PITCH + cc * 2) = L.u;
            }
    CP_WAIT(0);
    __syncthreads();

    // ---- C2[m][a] = sum_n rel[m][n] * kp[n0+n][a]  (warp w: m rows 16w..16w+16)
    float c2[8][4] = {};
#pragma unroll
    for (int term = 0; term < 3; ++term) {
        const uint32_t As = sb + (term == 1 ? RL_OFF : RH_OFF);
        const uint32_t Bs = sb + (term == 2 ? PJL_OFF : PJH_OFF);
#pragma unroll
        for (int kk = 0; kk < 128; kk += 16) {
            uint32_t a0, a1, a2, a3;
            ldmatrix_x4(a0, a1, a2, a3,
                As + (16 * wid + (lane & 15)) * R_PITCH + (kk + ((lane >> 4) << 3)) * 2);
#pragma unroll
            for (int ab = 0; ab < 4; ++ab) {
                uint32_t t0, t1, t2, t3;
                ldmatrix_x4_trans(t0, t1, t2, t3,
                    Bs + (kk + (lane & 15)) * P_PITCH + (ab * 16 + ((lane >> 4) << 3)) * 2);
                mma_bf16(c2[2 * ab],     a0, a1, a2, a3, t0, t1);
                mma_bf16(c2[2 * ab + 1], a0, a1, a2, a3, t2, t3);
            }
        }
    }
    {
        float* base = accQ + ((size_t)b * LN + m0 + 16 * wid) * AN;
#pragma unroll
        for (int j = 0; j < 8; ++j) {
            const int col = j * 8 + lc;
            atomicAdd(base + (size_t)lr * AN + col,           c2[j][0]);
            atomicAdd(base + (size_t)lr * AN + col + 1,       c2[j][1]);
            atomicAdd(base + (size_t)(lr + 8) * AN + col,     c2[j][2]);
            atomicAdd(base + (size_t)(lr + 8) * AN + col + 1, c2[j][3]);
        }
    }
    __syncthreads();   // all warps done reading kp tiles

    // load qp hi/lo tiles (rows m0..m0+127) into same region
    {
        const __nv_bfloat16* qh = qph + ((size_t)b * LN + m0) * AN;
        const __nv_bfloat16* ql = qpl + ((size_t)b * LN + m0) * AN;
#pragma unroll
        for (int i = 0; i < 4; ++i) {
            const int idx = tid + i * 256, r = idx >> 3, c = idx & 7;
            cp_async16(sb + PJH_OFF + r * P_PITCH + c * 16, qh + (size_t)r * AN + c * 8);
            cp_async16(sb + PJL_OFF + r * P_PITCH + c * 16, ql + (size_t)r * AN + c * 8);
        }
        CP_COMMIT; CP_WAIT(0);
    }
    __syncthreads();

    // ---- C3[n][a] = sum_m rel[m][n] * qp[m0+m][a]  (A = rel^T via ldmatrix.trans)
    float c3[8][4] = {};
    const int g = lane >> 3;
#pragma unroll
    for (int term = 0; term < 3; ++term) {
        const uint32_t As = sb + (term == 1 ? RL_OFF : RH_OFF);
        const uint32_t Bs = sb + (term == 2 ? PJL_OFF : PJH_OFF);
#pragma unroll
        for (int kk = 0; kk < 128; kk += 16) {
            uint32_t a0, a1, a2, a3;
            ldmatrix_x4_trans(a0, a1, a2, a3,
                As + (kk + ((g >> 1) << 3) + (lane & 7)) * R_PITCH
                   + (16 * wid + ((g & 1) << 3)) * 2);
#pragma unroll
            for (int ab = 0; ab < 4; ++ab) {
                uint32_t t0, t1, t2, t3;
                ldmatrix_x4_trans(t0, t1, t2, t3,
                    Bs + (kk + (lane & 15)) * P_PITCH + (ab * 16 + ((lane >> 4) << 3)) * 2);
                mma_bf16(c3[2 * ab],     a0, a1, a2, a3, t0, t1);
                mma_bf16(c3[2 * ab + 1], a0, a1, a2, a3, t2, t3);
            }
        }
    }
    {
        float* base = accK + ((size_t)b * LN + n0 + 16 * wid) * AN;
#pragma unroll
        for (int j = 0; j < 8; ++j) {
            const int col = j * 8 + lc;
            atomicAdd(base + (size_t)lr * AN + col,           c3[j][0]);
            atomicAdd(base + (size_t)lr * AN + col + 1,       c3[j][1]);
            atomicAdd(base + (size_t)(lr + 8) * AN + col,     c3[j][2]);
            atomicAdd(base + (size_t)(lr + 8) * AN + col + 1, c3[j][3]);
        }
    }
}

// ======================= Qw2 = split(Q2 @ W2t^T) =======================
__global__ void __launch_bounds__(256, 2) qw_mma_kernel(
    const __nv_bfloat16* __restrict__ Q2, const __nv_bfloat16* __restrict__ W2t,
    __nv_bfloat16* __restrict__ Qw2)
{
    extern __shared__ char smem[];
    const uint32_t smem_base = smem_to_u32(smem);
    const int tid = threadIdx.x;
    const int m0 = blockIdx.x * 128, n0 = blockIdx.y * 128;

    float acc[4][4][4] = {};
    warp_mma_main(Q2 + (size_t)m0 * KS, W2t + (size_t)n0 * KS, smem_base, tid, acc);

    const int wid = tid >> 5, lane = tid & 31;
    const int mw = (wid >> 2) * 64, nw = (wid & 3) * 32;
    const int lr = lane >> 2, lc = (lane & 3) * 2;
#pragma unroll
    for (int mf = 0; mf < 4; ++mf) {
        const int row = m0 + mw + mf * 16 + lr;
#pragma unroll
        for (int nf = 0; nf < 4; ++nf) {
            const int col = n0 + nw + nf * 8 + lc;
#pragma unroll
            for (int p = 0; p < 2; ++p) {
                const int rr = row + p * 8;
                BF2 H, L;
                split2(acc[mf][nf][2 * p + 0], H.h[0], L.h[0]);
                split2(acc[mf][nf][2 * p + 1], H.h[1], L.h[1]);
                __nv_bfloat16* o = Qw2 + (size_t)rr * KS + col;
                *(uint32_t*)(o)       = H.u;
                *(uint32_t*)(o + 256) = L.u;
            }
        }
    }
}

// ======================= slim projection kernel (N=64) ======================
// 3-stage ring. Stage = A(16KB) + W(8KB) = 24KB.
#define SLIM_STAGE 24576
#define SMEM_SLIM  (3 * SLIM_STAGE)

__device__ __forceinline__ void load_stage_slim(uint32_t sbase,
    const __nv_bfloat16* __restrict__ A, const __nv_bfloat16* __restrict__ W,
    int s, int tid)
{
    const __nv_bfloat16* Ak = A + amap(s) * 64;
    const __nv_bfloat16* Wk = W + bmap(s) * 64;
#pragma unroll
    for (int i = 0; i < 4; ++i) {
        const int idx = tid + i * 256;            // 1024 chunks: A 128 rows x 8
        const int r = idx >> 3, c = idx & 7;
        const uint32_t off = SMEM_SWIZZLE_128B((uint32_t)(r * 128 + c * 16));
        cp_async16(sbase + off, Ak + (size_t)r * KS + c * 8);
    }
#pragma unroll
    for (int i = 0; i < 2; ++i) {
        const int idx = tid + i * 256;            // 512 chunks: W 64 rows x 8
        const int r = idx >> 3, c = idx & 7;
        const uint32_t off = SMEM_SWIZZLE_128B((uint32_t)(r * 128 + c * 16));
        cp_async16(sbase + 16384 + off, Wk + (size_t)r * KS + c * 8);
    }
}

__global__ void __launch_bounds__(256, 3) proj_slim_kernel(
    const __nv_bfloat16* __restrict__ Q2, const __nv_bfloat16* __restrict__ K2,
    const __nv_bfloat16* __restrict__ Wp2t,
    float* __restrict__ accQ, float* __restrict__ accK,
    __nv_bfloat16* __restrict__ qph, __nv_bfloat16* __restrict__ qpl,
    __nv_bfloat16* __restrict__ kph, __nv_bfloat16* __restrict__ kpl)
{
    extern __shared__ char smem[];
    const uint32_t sb = smem_to_u32(smem);
    const int tid = threadIdx.x, wid = tid >> 5, lane = tid & 31;
    const int side = blockIdx.y;
    const int m0 = blockIdx.x * 128;
    const __nv_bfloat16* A = (side ? K2 : Q2) + (size_t)m0 * KS;
    const __nv_bfloat16* W = Wp2t + (size_t)side * 64 * KS;
    float* pf = side ? accK : accQ;
    __nv_bfloat16* ph = side ? kph : qph;
    __nv_bfloat16* pl = side ? kpl : qpl;

    const int mw = (wid >> 1) * 32, nw = (wid & 1) * 32;

    float acc[2][4][4] = {};
    load_stage_slim(sb + 0 * SLIM_STAGE, A, W, 0, tid); CP_COMMIT;
    load_stage_slim(sb + 1 * SLIM_STAGE, A, W, 1, tid); CP_COMMIT;

    for (int s = 0; s < NSTAGE; ++s) {
        CP_WAIT(1);
        __syncthreads();
        if (s + 2 < NSTAGE)
            load_stage_slim(sb + ((s + 2) % 3) * SLIM_STAGE, A, W, s + 2, tid);
        CP_COMMIT;

        const uint32_t sA = sb + (s % 3) * SLIM_STAGE;
        const uint32_t sW = sA + 16384;
#pragma unroll
        for (int kk = 0; kk < 64; kk += 16) {
            uint32_t a[2][4], b[4][2];
#pragma unroll
            for (int mf = 0; mf < 2; ++mf) {
                const uint32_t off = SMEM_SWIZZLE_128B((uint32_t)(
                    (mw + mf * 16 + (lane & 15)) * 128 + kk * 2 + ((lane >> 4) << 4)));
                ldmatrix_x4(a[mf][0], a[mf][1], a[mf][2], a[mf][3], sA + off);
            }
#pragma unroll
            for (int nb = 0; nb < 2; ++nb) {
                const int row = nw + nb * 16 + ((lane >> 4) & 1) * 8 + (lane & 7);
                const int kof = kk * 2 + (((lane >> 3) & 1) << 4);
                const uint32_t off = SMEM_SWIZZLE_128B((uint32_t)(row * 128 + kof));
                ldmatrix_x4(b[nb * 2][0], b[nb * 2][1], b[nb * 2 + 1][0], b[nb * 2 + 1][1],
                            sW + off);
            }
#pragma unroll
            for (int mf = 0; mf < 2; ++mf)
#pragma unroll
                for (int nf = 0; nf < 4; ++nf)
                    mma_bf16(acc[mf][nf], a[mf][0], a[mf][1], a[mf][2], a[mf][3],
                             b[nf][0], b[nf][1]);
        }
    }

    const int lr = lane >> 2, lc = (lane & 3) * 2;
#pragma unroll
    for (int mf = 0; mf < 2; ++mf) {
#pragma unroll
        for (int nf = 0; nf < 4; ++nf) {
            const int col = nw + nf * 8 + lc;
#pragma unroll
            for (int p = 0; p < 2; ++p) {
                const int row = m0 + mw + mf * 16 + lr + p * 8;
                const float v0 = acc[mf][nf][2 * p + 0];
                const float v1 = acc[mf][nf][2 * p + 1];
                *(float2*)(pf + (size_t)row * AN + col) = make_float2(v0, v1);
                BF2 H, L;
                split2(v0, H.h[0], L.h[0]);
                split2(v1, H.h[1], L.h[1]);
                *(uint32_t*)(ph + (size_t)row * AN + col) = H.u;
                *(uint32_t*)(pl + (size_t)row * AN + col) = L.u;
            }
        }
    }
}

// ======================= split / prep kernels =======================
__global__ void __launch_bounds__(256) split_kernel(
    const float* __restrict__ Q, const float* __restrict__ Kmat,
    __nv_bfloat16* __restrict__ Q2, __nv_bfloat16* __restrict__ K2)
{
    const int sel = blockIdx.y;
    const float* src = sel ? Kmat : Q;
    __nv_bfloat16* dst = sel ? K2 : Q2;
    const size_t i4 = (size_t)blockIdx.x * 256 + threadIdx.x;
    const size_t row = i4 >> 6;
    const int c = (int)(i4 & 63) * 4;
    float4 v = ((const float4*)src)[i4];
    union { __nv_bfloat16 b[4]; uint2 u; } h, l;
    split2(v.x, h.b[0], l.b[0]); split2(v.y, h.b[1], l.b[1]);
    split2(v.z, h.b[2], l.b[2]); split2(v.w, h.b[3], l.b[3]);
    __nv_bfloat16* o = dst + row * KS + c;
    *(uint2*)(o)       = h.u;
    *(uint2*)(o + 256) = l.u;
}

__global__ void __launch_bounds__(256) prep_w2t(
    const float* __restrict__ Wrel, __nv_bfloat16* __restrict__ W2t)
{
    const int idx = blockIdx.x * 256 + threadIdx.x;   // 65536
    const int d = idx >> 8, n = idx & 255;
    __nv_bfloat16 hi, lo;
    split2(Wrel[d * 256 + n], hi, lo);
    W2t[(size_t)n * KS + d]       = hi;
    W2t[(size_t)n * KS + 256 + d] = lo;
}

__global__ void __launch_bounds__(256) prep_wp(
    const float* __restrict__ Wq, const float* __restrict__ Wk,
    __nv_bfloat16* __restrict__ Wp2t)
{
    const int idx = blockIdx.x * 256 + threadIdx.x;   // 32768
    const int side = idx >> 14;
    const int d = (idx >> 6) & 255, a = idx & 63;
    const float* W = side ? Wk : Wq;
    __nv_bfloat16 hi, lo;
    split2(W[d * 64 + a], hi, lo);
    __nv_bfloat16* slab = Wp2t + (size_t)side * 64 * KS;
    slab[(size_t)a * KS + d]       = hi;
    slab[(size_t)a * KS + 256 + d] = lo;
}

// ======================= tanh + dot reduce (reads accumulators) =============
__global__ void __launch_bounds__(256) att_reduce_kernel(
    const float* __restrict__ accQ, const float* __restrict__ accK,
    const float* __restrict__ Wqa, const float* __restrict__ Wka,
    float* __restrict__ lq, float* __restrict__ lk)
{
    const int side = blockIdx.y;
    const int wid = threadIdx.x >> 5, lane = threadIdx.x & 31;
    const size_t gm = (size_t)blockIdx.x * 8 + wid;   // b*LN + m
    const float* acc = side ? accK : accQ;
    const float* w   = side ? Wka  : Wqa;
    float* out       = side ? lk   : lq;

    float s = 0.f;
#pragma unroll
    for (int h = 0; h < 2; ++h) {
        const int a = lane + h * 32;
        s += tanhf(acc[gm * AN + a]) * w[a];
    }
#pragma unroll
    for (int o = 16; o; o >>= 1) s += __shfl_xor_sync(0xFFFFFFFFu, s, o);
    if (lane == 0) out[gm] = s;
}

// ============================================================================
__global__ void __launch_bounds__(512) softmax_kernel(
    const float* __restrict__ lq, const float* __restrict__ lk,
    float* __restrict__ out)
{
    __shared__ float red[512];
    const int b = blockIdx.x, sel = blockIdx.y, t = threadIdx.x;
    const float* l = (sel ? lk : lq) + (size_t)b * LN;
    float* o = out + (sel ? OFF_KW : OFF_QW) + (size_t)b * LN;

    float v = l[t];
    red[t] = v; __syncthreads();
    for (int s = 256; s > 0; s >>= 1) {
        if (t < s) red[t] = fmaxf(red[t], red[t + s]);
        __syncthreads();
    }
    const float mx = red[0];
    __syncthreads();
    const float e = expf(v - mx);
    red[t] = e; __syncthreads();
    for (int s = 256; s > 0; s >>= 1) {
        if (t < s) red[t] += red[t + s];
        __syncthreads();
    }
    o[t] = e / red[0];
}

__global__ void __launch_bounds__(256) scale_kernel(
    const float* __restrict__ Q, const float* __restrict__ Kmat,
    float* __restrict__ out)
{
    const int sel = blockIdx.y;
    const size_t i4 = (size_t)blockIdx.x * 256 + threadIdx.x;
    const float4* src = (const float4*)(sel ? Kmat : Q);
    const float*  w   = out + (sel ? OFF_KW : OFF_QW);
    float4*       dst = (float4*)(out + (sel ? OFF_WK : OFF_WQ));

    const size_t e = i4 * 4;
    const int b = (int)(e >> 17);
    const int l = (int)((e >> 8) & 511);
    const float s = w[b * LN + l];
    float4 v = src[i4];
    v.x *= s; v.y *= s; v.z *= s; v.w *= s;
    dst[i4] = v;
}

// ============================================================================
extern "C" void kernel_launch(void* const* d_in, const int* in_sizes, int n_in,
                              void* d_out, int out_size)
{
    (void)in_sizes; (void)n_in; (void)out_size;
    const float* Q    = (const float*)d_in[0];
    const float* Km   = (const float*)d_in[1];
    const float* Wrel = (const float*)d_in[2];
    const float* Wq   = (const float*)d_in[3];
    const float* Wk   = (const float*)d_in[4];
    const float* Wqa  = (const float*)d_in[5];
    const float* Wka  = (const float*)d_in[6];
    float* out = (float*)d_out;

    __nv_bfloat16 *q2, *k2, *qw2, *w2t, *wp2t, *qph, *qpl, *kph, *kpl;
    float *aQ, *aK, *lq, *lk;
    cudaGetSymbolAddress((void**)&q2,   g_Q2);
    cudaGetSymbolAddress((void**)&k2,   g_K2);
    cudaGetSymbolAddress((void**)&qw2,  g_Qw2);
    cudaGetSymbolAddress((void**)&w2t,  g_W2t);
    cudaGetSymbolAddress((void**)&wp2t, g_Wp2t);
    cudaGetSymbolAddress((void**)&aQ,   g_accQ);
    cudaGetSymbolAddress((void**)&aK,   g_accK);
    cudaGetSymbolAddress((void**)&qph,  g_qph);
    cudaGetSymbolAddress((void**)&qpl,  g_qpl);
    cudaGetSymbolAddress((void**)&kph,  g_kph);
    cudaGetSymbolAddress((void**)&kpl,  g_kpl);
    cudaGetSymbolAddress((void**)&lq,   g_logit_q);
    cudaGetSymbolAddress((void**)&lk,   g_logit_k);

    cudaFuncSetAttribute(qw_mma_kernel,    cudaFuncAttributeMaxDynamicSharedMemorySize, SMEM_MMA);
    cudaFuncSetAttribute(proj_slim_kernel, cudaFuncAttributeMaxDynamicSharedMemorySize, SMEM_SLIM);
    cudaFuncSetAttribute(rel_fused_kernel, cudaFuncAttributeMaxDynamicSharedMemorySize, SMEM_FUSED);

    const dim3 blk(256);
    // compact [hi|lo] splits of inputs + weight transposes
    split_kernel<<<dim3((BN * LN * DN) / 4 / 256, 2), blk>>>(Q, Km, q2, k2);
    prep_w2t<<<256, blk>>>(Wrel, w2t);
    prep_wp<<<128, blk>>>(Wq, Wk, wp2t);
    // projections -> accumulator base values + bf16 hi/lo copies
    proj_slim_kernel<<<dim3(512, 2), blk, SMEM_SLIM>>>(
        q2, k2, wp2t, aQ, aK, qph, qpl, kph, kpl);
    // Qw (MMA, epilogue re-splits to compact bf16 hi/lo)
    qw_mma_kernel<<<dim3(512, 2), blk, SMEM_MMA>>>(q2, w2t, qw2);
    // fused rel + both score GEMMs -> RED into accumulators
    rel_fused_kernel<<<dim3(4, 4, BN), blk, SMEM_FUSED>>>(qw2, k2, kph, kpl, qph, qpl, aQ, aK);
    // tanh + @W_att -> logits
    att_reduce_kernel<<<dim3(BN * LN / 8, 2), blk>>>(aQ, aK, Wqa, Wka, lq, lk);
    // softmax -> weights in d_out
    softmax_kernel<<<dim3(BN, 2), 512>>>(lq, lk, out);
    // weighted outputs
    scale_kernel<<<dim3((BN * LN * DN) / 4 / 256, 2), 256>>>(Q, Km, out);
}

// round 11
// speedup vs baseline: 2.8430x; 1.1059x over previous
#include <cuda_runtime.h>
#include <cuda_bf16.h>
#include <math.h>
#include <stdint.h>

// Problem dims
#define BN 128
#define LN 512
#define DN 256
#define AN 64
#define KS 512   // compact split storage: [hi | lo] x 256; 12-stage schedule via maps

// Output layout (concatenated, reference tuple order)
#define OFF_WQ  ((size_t)0)
#define OFF_WK  ((size_t)BN * LN * DN)
#define OFF_QW  ((size_t)2 * BN * LN * DN)
#define OFF_KW  (OFF_QW + (size_t)BN * LN)

// -------- scratch (device globals; no allocation allowed) --------
__device__ __nv_bfloat16 g_Q2 [(size_t)BN * LN * KS];    // [hi|lo] of Q
__device__ __nv_bfloat16 g_K2 [(size_t)BN * LN * KS];    // [hi|lo] of K
__device__ __nv_bfloat16 g_Qw2[(size_t)BN * LN * KS];    // [hi|lo] of Qw
__device__ __nv_bfloat16 g_W2t[(size_t)DN * KS];         // W_rel^T [hi|lo]
__device__ __nv_bfloat16 g_Wp2t[2 * 64 * KS];            // Wq^T / Wk^T [hi|lo]
// accumulators: proj writes base value; rel_fused REDs score-GEMM terms on top
__device__ float g_accQ[(size_t)BN * LN * AN];           // q_proj + rel@kp
__device__ float g_accK[(size_t)BN * LN * AN];           // k_proj + relT@qp
__device__ __nv_bfloat16 g_qph[(size_t)BN * LN * AN], g_qpl[(size_t)BN * LN * AN];
__device__ __nv_bfloat16 g_kph[(size_t)BN * LN * AN], g_kpl[(size_t)BN * LN * AN];
__device__ float g_logit_q[BN * LN];
__device__ float g_logit_k[BN * LN];

// ======================= helpers (baseline PTX only) =======================
__device__ __forceinline__ uint32_t smem_to_u32(const void* p) {
    uint32_t a;
    asm("{ .reg .u64 t; cvta.to.shared.u64 t, %1; cvt.u32.u64 %0, t; }" : "=r"(a) : "l"(p));
    return a;
}
#define SMEM_SWIZZLE_128B(o) ((o) ^ (((o) >> 3) & 0x70))

__device__ __forceinline__ void cp_async16(uint32_t saddr, const void* g) {
    asm volatile("cp.async.cg.shared.global [%0], [%1], 16;" :: "r"(saddr), "l"(g));
}
#define CP_COMMIT  asm volatile("cp.async.commit_group;" ::: "memory")
#define CP_WAIT(n) asm volatile("cp.async.wait_group %0;" :: "n"(n) : "memory")

__device__ __forceinline__ void ldmatrix_x4(uint32_t& r0, uint32_t& r1, uint32_t& r2,
                                            uint32_t& r3, uint32_t addr) {
    asm volatile("ldmatrix.sync.aligned.m8n8.x4.shared.b16 {%0,%1,%2,%3}, [%4];"
                 : "=r"(r0), "=r"(r1), "=r"(r2), "=r"(r3) : "r"(addr));
}
__device__ __forceinline__ void ldmatrix_x4_trans(uint32_t& r0, uint32_t& r1, uint32_t& r2,
                                                  uint32_t& r3, uint32_t addr) {
    asm volatile("ldmatrix.sync.aligned.m8n8.x4.trans.shared.b16 {%0,%1,%2,%3}, [%4];"
                 : "=r"(r0), "=r"(r1), "=r"(r2), "=r"(r3) : "r"(addr));
}
__device__ __forceinline__ void mma_bf16(float* c, uint32_t a0, uint32_t a1, uint32_t a2,
                                         uint32_t a3, uint32_t b0, uint32_t b1) {
    asm volatile(
        "mma.sync.aligned.m16n8k16.row.col.f32.bf16.bf16.f32 "
        "{%0,%1,%2,%3}, {%4,%5,%6,%7}, {%8,%9}, {%0,%1,%2,%3};"
        : "+f"(c[0]), "+f"(c[1]), "+f"(c[2]), "+f"(c[3])
        : "r"(a0), "r"(a1), "r"(a2), "r"(a3), "r"(b0), "r"(b1));
}
// vector fp32 reduction (sm_90+ baseline PTX feature)
__device__ __forceinline__ void red_add_v2(float* addr, float a, float b) {
    asm volatile("red.global.add.v2.f32 [%0], {%1, %2};"
                 :: "l"(addr), "f"(a), "f"(b) : "memory");
}

__device__ __forceinline__ void split2(float x, __nv_bfloat16& hi, __nv_bfloat16& lo) {
    hi = __float2bfloat16(x);
    lo = __float2bfloat16(x - __bfloat162float(hi));
}
union BF2 { __nv_bfloat16 h[2]; uint32_t u; };

// Stage maps: logical stage s (0..11) -> physical 64-col chunk in [hi|lo] storage.
// Pairing: s 0-3 hi*hi, 4-7 lo*hi, 8-11 hi*lo.
__device__ __forceinline__ int amap(int s) { return s < 8 ? s : s - 8; }
__device__ __forceinline__ int bmap(int s) { return s < 4 ? s : s - 4; }

// ======================= warp-MMA mainloop (128x128 tile) =======================
// 3-stage cp.async ring, ONE __syncthreads per stage.
#define NSTAGE  12
#define STAGE_BYTES 32768
#define SMEM_MMA (3 * STAGE_BYTES)

__device__ __forceinline__ void load_stage(uint32_t sbase,
    const __nv_bfloat16* __restrict__ A, const __nv_bfloat16* __restrict__ B,
    int s, int tid)
{
    const __nv_bfloat16* Ak = A + amap(s) * 64;
    const __nv_bfloat16* Bk = B + bmap(s) * 64;
#pragma unroll
    for (int i = 0; i < 4; ++i) {
        const int idx = tid + i * 256;            // 0..1023 16B chunks
        const int r = idx >> 3, c = idx & 7;
        const uint32_t off = SMEM_SWIZZLE_128B((uint32_t)(r * 128 + c * 16));
        cp_async16(sbase + off, Ak + (size_t)r * KS + c * 8);
        cp_async16(sbase + 16384 + off, Bk + (size_t)r * KS + c * 8);
    }
}

__device__ __forceinline__ void warp_mma_main(
    const __nv_bfloat16* __restrict__ A, const __nv_bfloat16* __restrict__ B,
    uint32_t smem_base, int tid, float acc[4][4][4])
{
    const int wid = tid >> 5, lane = tid & 31;
    const int mw = (wid >> 2) * 64, nw = (wid & 3) * 32;

    load_stage(smem_base + 0 * STAGE_BYTES, A, B, 0, tid); CP_COMMIT;
    load_stage(smem_base + 1 * STAGE_BYTES, A, B, 1, tid); CP_COMMIT;

    for (int s = 0; s < NSTAGE; ++s) {
        CP_WAIT(1);            // stage s group complete (groups retire in order)
        __syncthreads();       // publish stage s; fences reuse of buf[(s+2)%3]
        if (s + 2 < NSTAGE)
            load_stage(smem_base + ((s + 2) % 3) * STAGE_BYTES, A, B, s + 2, tid);
        CP_COMMIT;

        const uint32_t sA = smem_base + (s % 3) * STAGE_BYTES;
        const uint32_t sB = sA + 16384;
#pragma unroll
        for (int kk = 0; kk < 64; kk += 16) {
            uint32_t a[4][4], b[4][2];
#pragma unroll
            for (int mf = 0; mf < 4; ++mf) {
                const uint32_t off = SMEM_SWIZZLE_128B((uint32_t)(
                    (mw + mf * 16 + (lane & 15)) * 128 + kk * 2 + ((lane >> 4) << 4)));
                ldmatrix_x4(a[mf][0], a[mf][1], a[mf][2], a[mf][3], sA + off);
            }
#pragma unroll
            for (int nb = 0; nb < 2; ++nb) {
                const int row = nw + nb * 16 + ((lane >> 4) & 1) * 8 + (lane & 7);
                const int kof = kk * 2 + (((lane >> 3) & 1) << 4);
                const uint32_t off = SMEM_SWIZZLE_128B((uint32_t)(row * 128 + kof));
                ldmatrix_x4(b[nb * 2][0], b[nb * 2][1], b[nb * 2 + 1][0], b[nb * 2 + 1][1],
                            sB + off);
            }
#pragma unroll
            for (int mf = 0; mf < 4; ++mf)
#pragma unroll
                for (int nf = 0; nf < 4; ++nf)
                    mma_bf16(acc[mf][nf], a[mf][0], a[mf][1], a[mf][2], a[mf][3],
                             b[nf][0], b[nf][1]);
        }
    }
    __syncthreads();   // all warps done with ring before caller reuses smem
}

// ======================= fused rel + att-score kernel =======================
#define R_PITCH  272          // 128 cols bf16 (256B) + 16B pad
#define P_PITCH  144          // 64 cols bf16 (128B) + 16B pad
#define RH_OFF   0
#define RL_OFF   34816
#define PJH_OFF  69632
#define PJL_OFF  88064
#define SMEM_FUSED 106496     // >= 3*STAGE_BYTES mainloop ring

__global__ void __launch_bounds__(256, 2) rel_fused_kernel(
    const __nv_bfloat16* __restrict__ Qw2, const __nv_bfloat16* __restrict__ K2,
    const __nv_bfloat16* __restrict__ kph, const __nv_bfloat16* __restrict__ kpl,
    const __nv_bfloat16* __restrict__ qph, const __nv_bfloat16* __restrict__ qpl,
    float* __restrict__ accQ, float* __restrict__ accK)
{
    extern __shared__ char smem[];
    const uint32_t sb = smem_to_u32(smem);
    const int tid = threadIdx.x, wid = tid >> 5, lane = tid & 31;
    const int mt = blockIdx.x, nt = blockIdx.y, b = blockIdx.z;
    const int m0 = mt * 128, n0 = nt * 128;

    float acc[4][4][4] = {};
    warp_mma_main(Qw2 + ((size_t)b * LN + m0) * KS,
                  K2  + ((size_t)b * LN + n0) * KS, sb, tid, acc);

    // prefetch kp hi/lo tiles (rows n0..n0+127) while storing rel to smem
    {
        const __nv_bfloat16* kh = kph + ((size_t)b * LN + n0) * AN;
        const __nv_bfloat16* kl = kpl + ((size_t)b * LN + n0) * AN;
#pragma unroll
        for (int i = 0; i < 4; ++i) {
            const int idx = tid + i * 256, r = idx >> 3, c = idx & 7;
            cp_async16(sb + PJH_OFF + r * P_PITCH + c * 16, kh + (size_t)r * AN + c * 8);
            cp_async16(sb + PJL_OFF + r * P_PITCH + c * 16, kl + (size_t)r * AN + c * 8);
        }
        CP_COMMIT;
    }

    // tanh + hi/lo split -> smem rel tiles
    const int mw = (wid >> 2) * 64, nw = (wid & 3) * 32;
    const int lr = lane >> 2, lc = (lane & 3) * 2;
#pragma unroll
    for (int mf = 0; mf < 4; ++mf)
#pragma unroll
        for (int nf = 0; nf < 4; ++nf)
#pragma unroll
            for (int p = 0; p < 2; ++p) {
                const int rr = mw + mf * 16 + lr + p * 8;
                const int cc = nw + nf * 8 + lc;
                BF2 H, L;
                split2(tanhf(acc[mf][nf][2 * p + 0]), H.h[0], L.h[0]);
                split2(tanhf(acc[mf][nf][2 * p + 1]), H.h[1], L.h[1]);
                *(uint32_t*)(smem + RH_OFF + rr * R_PITCH + cc * 2) = H.u;
                *(uint32_t*)(smem + RL_OFF + rr * R_PITCH + cc * 2) = L.u;
            }
    CP_WAIT(0);
    __syncthreads();

    // ---- C2[m][a] = sum_n rel[m][n] * kp[n0+n][a]
    // 3-term split with frags loaded ONCE per kk: aH*bH + aL*bH + aH*bL
    float c2[8][4] = {};
#pragma unroll
    for (int kk = 0; kk < 128; kk += 16) {
        uint32_t aH0, aH1, aH2, aH3, aL0, aL1, aL2, aL3;
        const uint32_t aoff = (16 * wid + (lane & 15)) * R_PITCH
                            + (kk + ((lane >> 4) << 3)) * 2;
        ldmatrix_x4(aH0, aH1, aH2, aH3, sb + RH_OFF + aoff);
        ldmatrix_x4(aL0, aL1, aL2, aL3, sb + RL_OFF + aoff);
#pragma unroll
        for (int ab = 0; ab < 4; ++ab) {
            uint32_t h0, h1, h2, h3, l0, l1, l2, l3;
            const uint32_t boff = (kk + (lane & 15)) * P_PITCH
                                + (ab * 16 + ((lane >> 4) << 3)) * 2;
            ldmatrix_x4_trans(h0, h1, h2, h3, sb + PJH_OFF + boff);
            ldmatrix_x4_trans(l0, l1, l2, l3, sb + PJL_OFF + boff);
            mma_bf16(c2[2 * ab],     aH0, aH1, aH2, aH3, h0, h1);
            mma_bf16(c2[2 * ab],     aL0, aL1, aL2, aL3, h0, h1);
            mma_bf16(c2[2 * ab],     aH0, aH1, aH2, aH3, l0, l1);
            mma_bf16(c2[2 * ab + 1], aH0, aH1, aH2, aH3, h2, h3);
            mma_bf16(c2[2 * ab + 1], aL0, aL1, aL2, aL3, h2, h3);
            mma_bf16(c2[2 * ab + 1], aH0, aH1, aH2, aH3, l2, l3);
        }
    }
    {
        float* base = accQ + ((size_t)b * LN + m0 + 16 * wid) * AN;
#pragma unroll
        for (int j = 0; j < 8; ++j) {
            const int col = j * 8 + lc;
            red_add_v2(base + (size_t)lr * AN + col,       c2[j][0], c2[j][1]);
            red_add_v2(base + (size_t)(lr + 8) * AN + col, c2[j][2], c2[j][3]);
        }
    }
    __syncthreads();   // all warps done reading kp tiles

    // load qp hi/lo tiles (rows m0..m0+127) into same region
    {
        const __nv_bfloat16* qh = qph + ((size_t)b * LN + m0) * AN;
        const __nv_bfloat16* ql = qpl + ((size_t)b * LN + m0) * AN;
#pragma unroll
        for (int i = 0; i < 4; ++i) {
            const int idx = tid + i * 256, r = idx >> 3, c = idx & 7;
            cp_async16(sb + PJH_OFF + r * P_PITCH + c * 16, qh + (size_t)r * AN + c * 8);
            cp_async16(sb + PJL_OFF + r * P_PITCH + c * 16, ql + (size_t)r * AN + c * 8);
        }
        CP_COMMIT; CP_WAIT(0);
    }
    __syncthreads();

    // ---- C3[n][a] = sum_m rel[m][n] * qp[m0+m][a]  (A = rel^T via ldmatrix.trans)
    float c3[8][4] = {};
    const int g = lane >> 3;
#pragma unroll
    for (int kk = 0; kk < 128; kk += 16) {
        uint32_t aH0, aH1, aH2, aH3, aL0, aL1, aL2, aL3;
        const uint32_t aoff = (kk + ((g >> 1) << 3) + (lane & 7)) * R_PITCH
                            + (16 * wid + ((g & 1) << 3)) * 2;
        ldmatrix_x4_trans(aH0, aH1, aH2, aH3, sb + RH_OFF + aoff);
        ldmatrix_x4_trans(aL0, aL1, aL2, aL3, sb + RL_OFF + aoff);
#pragma unroll
        for (int ab = 0; ab < 4; ++ab) {
            uint32_t h0, h1, h2, h3, l0, l1, l2, l3;
            const uint32_t boff = (kk + (lane & 15)) * P_PITCH
                                + (ab * 16 + ((lane >> 4) << 3)) * 2;
            ldmatrix_x4_trans(h0, h1, h2, h3, sb + PJH_OFF + boff);
            ldmatrix_x4_trans(l0, l1, l2, l3, sb + PJL_OFF + boff);
            mma_bf16(c3[2 * ab],     aH0, aH1, aH2, aH3, h0, h1);
            mma_bf16(c3[2 * ab],     aL0, aL1, aL2, aL3, h0, h1);
            mma_bf16(c3[2 * ab],     aH0, aH1, aH2, aH3, l0, l1);
            mma_bf16(c3[2 * ab + 1], aH0, aH1, aH2, aH3, h2, h3);
            mma_bf16(c3[2 * ab + 1], aL0, aL1, aL2, aL3, h2, h3);
            mma_bf16(c3[2 * ab + 1], aH0, aH1, aH2, aH3, l2, l3);
        }
    }
    {
        float* base = accK + ((size_t)b * LN + n0 + 16 * wid) * AN;
#pragma unroll
        for (int j = 0; j < 8; ++j) {
            const int col = j * 8 + lc;
            red_add_v2(base + (size_t)lr * AN + col,       c3[j][0], c3[j][1]);
            red_add_v2(base + (size_t)(lr + 8) * AN + col, c3[j][2], c3[j][3]);
        }
    }
}

// ======================= Qw2 = split(Q2 @ W2t^T) =======================
__global__ void __launch_bounds__(256, 2) qw_mma_kernel(
    const __nv_bfloat16* __restrict__ Q2, const __nv_bfloat16* __restrict__ W2t,
    __nv_bfloat16* __restrict__ Qw2)
{
    extern __shared__ char smem[];
    const uint32_t smem_base = smem_to_u32(smem);
    const int tid = threadIdx.x;
    const int m0 = blockIdx.x * 128, n0 = blockIdx.y * 128;

    float acc[4][4][4] = {};
    warp_mma_main(Q2 + (size_t)m0 * KS, W2t + (size_t)n0 * KS, smem_base, tid, acc);

    const int wid = tid >> 5, lane = tid & 31;
    const int mw = (wid >> 2) * 64, nw = (wid & 3) * 32;
    const int lr = lane >> 2, lc = (lane & 3) * 2;
#pragma unroll
    for (int mf = 0; mf < 4; ++mf) {
        const int row = m0 + mw + mf * 16 + lr;
#pragma unroll
        for (int nf = 0; nf < 4; ++nf) {
            const int col = n0 + nw + nf * 8 + lc;
#pragma unroll
            for (int p = 0; p < 2; ++p) {
                const int rr = row + p * 8;
                BF2 H, L;
                split2(acc[mf][nf][2 * p + 0], H.h[0], L.h[0]);
                split2(acc[mf][nf][2 * p + 1], H.h[1], L.h[1]);
                __nv_bfloat16* o = Qw2 + (size_t)rr * KS + col;
                *(uint32_t*)(o)       = H.u;
                *(uint32_t*)(o + 256) = L.u;
            }
        }
    }
}

// ======================= slim projection kernel (N=64) ======================
// 3-stage ring. Stage = A(16KB) + W(8KB) = 24KB.
#define SLIM_STAGE 24576
#define SMEM_SLIM  (3 * SLIM_STAGE)

__device__ __forceinline__ void load_stage_slim(uint32_t sbase,
    const __nv_bfloat16* __restrict__ A, const __nv_bfloat16* __restrict__ W,
    int s, int tid)
{
    const __nv_bfloat16* Ak = A + amap(s) * 64;
    const __nv_bfloat16* Wk = W + bmap(s) * 64;
#pragma unroll
    for (int i = 0; i < 4; ++i) {
        const int idx = tid + i * 256;            // 1024 chunks: A 128 rows x 8
        const int r = idx >> 3, c = idx & 7;
        const uint32_t off = SMEM_SWIZZLE_128B((uint32_t)(r * 128 + c * 16));
        cp_async16(sbase + off, Ak + (size_t)r * KS + c * 8);
    }
#pragma unroll
    for (int i = 0; i < 2; ++i) {
        const int idx = tid + i * 256;            // 512 chunks: W 64 rows x 8
        const int r = idx >> 3, c = idx & 7;
        const uint32_t off = SMEM_SWIZZLE_128B((uint32_t)(r * 128 + c * 16));
        cp_async16(sbase + 16384 + off, Wk + (size_t)r * KS + c * 8);
    }
}

__global__ void __launch_bounds__(256, 3) proj_slim_kernel(
    const __nv_bfloat16* __restrict__ Q2, const __nv_bfloat16* __restrict__ K2,
    const __nv_bfloat16* __restrict__ Wp2t,
    float* __restrict__ accQ, float* __restrict__ accK,
    __nv_bfloat16* __restrict__ qph, __nv_bfloat16* __restrict__ qpl,
    __nv_bfloat16* __restrict__ kph, __nv_bfloat16* __restrict__ kpl)
{
    extern __shared__ char smem[];
    const uint32_t sb = smem_to_u32(smem);
    const int tid = threadIdx.x, wid = tid >> 5, lane = tid & 31;
    const int side = blockIdx.y;
    const int m0 = blockIdx.x * 128;
    const __nv_bfloat16* A = (side ? K2 : Q2) + (size_t)m0 * KS;
    const __nv_bfloat16* W = Wp2t + (size_t)side * 64 * KS;
    float* pf = side ? accK : accQ;
    __nv_bfloat16* ph = side ? kph : qph;
    __nv_bfloat16* pl = side ? kpl : qpl;

    const int mw = (wid >> 1) * 32, nw = (wid & 1) * 32;

    float acc[2][4][4] = {};
    load_stage_slim(sb + 0 * SLIM_STAGE, A, W, 0, tid); CP_COMMIT;
    load_stage_slim(sb + 1 * SLIM_STAGE, A, W, 1, tid); CP_COMMIT;

    for (int s = 0; s < NSTAGE; ++s) {
        CP_WAIT(1);
        __syncthreads();
        if (s + 2 < NSTAGE)
            load_stage_slim(sb + ((s + 2) % 3) * SLIM_STAGE, A, W, s + 2, tid);
        CP_COMMIT;

        const uint32_t sA = sb + (s % 3) * SLIM_STAGE;
        const uint32_t sW = sA + 16384;
#pragma unroll
        for (int kk = 0; kk < 64; kk += 16) {
            uint32_t a[2][4], b[4][2];
#pragma unroll
            for (int mf = 0; mf < 2; ++mf) {
                const uint32_t off = SMEM_SWIZZLE_128B((uint32_t)(
                    (mw + mf * 16 + (lane & 15)) * 128 + kk * 2 + ((lane >> 4) << 4)));
                ldmatrix_x4(a[mf][0], a[mf][1], a[mf][2], a[mf][3], sA + off);
            }
#pragma unroll
            for (int nb = 0; nb < 2; ++nb) {
                const int row = nw + nb * 16 + ((lane >> 4) & 1) * 8 + (lane & 7);
                const int kof = kk * 2 + (((lane >> 3) & 1) << 4);
                const uint32_t off = SMEM_SWIZZLE_128B((uint32_t)(row * 128 + kof));
                ldmatrix_x4(b[nb * 2][0], b[nb * 2][1], b[nb * 2 + 1][0], b[nb * 2 + 1][1],
                            sW + off);
            }
#pragma unroll
            for (int mf = 0; mf < 2; ++mf)
#pragma unroll
                for (int nf = 0; nf < 4; ++nf)
                    mma_bf16(acc[mf][nf], a[mf][0], a[mf][1], a[mf][2], a[mf][3],
                             b[nf][0], b[nf][1]);
        }
    }

    const int lr = lane >> 2, lc = (lane & 3) * 2;
#pragma unroll
    for (int mf = 0; mf < 2; ++mf) {
#pragma unroll
        for (int nf = 0; nf < 4; ++nf) {
            const int col = nw + nf * 8 + lc;
#pragma unroll
            for (int p = 0; p < 2; ++p) {
                const int row = m0 + mw + mf * 16 + lr + p * 8;
                const float v0 = acc[mf][nf][2 * p + 0];
                const float v1 = acc[mf][nf][2 * p + 1];
                *(float2*)(pf + (size_t)row * AN + col) = make_float2(v0, v1);
                BF2 H, L;
                split2(v0, H.h[0], L.h[0]);
                split2(v1, H.h[1], L.h[1]);
                *(uint32_t*)(ph + (size_t)row * AN + col) = H.u;
                *(uint32_t*)(pl + (size_t)row * AN + col) = L.u;
            }
        }
    }
}

// ======================= split / prep kernels =======================
__global__ void __launch_bounds__(256) split_kernel(
    const float* __restrict__ Q, const float* __restrict__ Kmat,
    __nv_bfloat16* __restrict__ Q2, __nv_bfloat16* __restrict__ K2)
{
    const int sel = blockIdx.y;
    const float* src = sel ? Kmat : Q;
    __nv_bfloat16* dst = sel ? K2 : Q2;
    const size_t i4 = (size_t)blockIdx.x * 256 + threadIdx.x;
    const size_t row = i4 >> 6;
    const int c = (int)(i4 & 63) * 4;
    float4 v = ((const float4*)src)[i4];
    union { __nv_bfloat16 b[4]; uint2 u; } h, l;
    split2(v.x, h.b[0], l.b[0]); split2(v.y, h.b[1], l.b[1]);
    split2(v.z, h.b[2], l.b[2]); split2(v.w, h.b[3], l.b[3]);
    __nv_bfloat16* o = dst + row * KS + c;
    *(uint2*)(o)       = h.u;
    *(uint2*)(o + 256) = l.u;
}

__global__ void __launch_bounds__(256) prep_w2t(
    const float* __restrict__ Wrel, __nv_bfloat16* __restrict__ W2t)
{
    const int idx = blockIdx.x * 256 + threadIdx.x;   // 65536
    const int d = idx >> 8, n = idx & 255;
    __nv_bfloat16 hi, lo;
    split2(Wrel[d * 256 + n], hi, lo);
    W2t[(size_t)n * KS + d]       = hi;
    W2t[(size_t)n * KS + 256 + d] = lo;
}

__global__ void __launch_bounds__(256) prep_wp(
    const float* __restrict__ Wq, const float* __restrict__ Wk,
    __nv_bfloat16* __restrict__ Wp2t)
{
    const int idx = blockIdx.x * 256 + threadIdx.x;   // 32768
    const int side = idx >> 14;
    const int d = (idx >> 6) & 255, a = idx & 63;
    const float* W = side ? Wk : Wq;
    __nv_bfloat16 hi, lo;
    split2(W[d * 64 + a], hi, lo);
    __nv_bfloat16* slab = Wp2t + (size_t)side * 64 * KS;
    slab[(size_t)a * KS + d]       = hi;
    slab[(size_t)a * KS + 256 + d] = lo;
}

// ======================= tanh + dot reduce (reads accumulators) =============
__global__ void __launch_bounds__(256) att_reduce_kernel(
    const float* __restrict__ accQ, const float* __restrict__ accK,
    const float* __restrict__ Wqa, const float* __restrict__ Wka,
    float* __restrict__ lq, float* __restrict__ lk)
{
    const int side = blockIdx.y;
    const int wid = threadIdx.x >> 5, lane = threadIdx.x & 31;
    const size_t gm = (size_t)blockIdx.x * 8 + wid;   // b*LN + m
    const float* acc = side ? accK : accQ;
    const float* w   = side ? Wka  : Wqa;
    float* out       = side ? lk   : lq;

    float s = 0.f;
#pragma unroll
    for (int h = 0; h < 2; ++h) {
        const int a = lane + h * 32;
        s += tanhf(acc[gm * AN + a]) * w[a];
    }
#pragma unroll
    for (int o = 16; o; o >>= 1) s += __shfl_xor_sync(0xFFFFFFFFu, s, o);
    if (lane == 0) out[gm] = s;
}

// ============================================================================
__global__ void __launch_bounds__(512) softmax_kernel(
    const float* __restrict__ lq, const float* __restrict__ lk,
    float* __restrict__ out)
{
    __shared__ float red[512];
    const int b = blockIdx.x, sel = blockIdx.y, t = threadIdx.x;
    const float* l = (sel ? lk : lq) + (size_t)b * LN;
    float* o = out + (sel ? OFF_KW : OFF_QW) + (size_t)b * LN;

    float v = l[t];
    red[t] = v; __syncthreads();
    for (int s = 256; s > 0; s >>= 1) {
        if (t < s) red[t] = fmaxf(red[t], red[t + s]);
        __syncthreads();
    }
    const float mx = red[0];
    __syncthreads();
    const float e = expf(v - mx);
    red[t] = e; __syncthreads();
    for (int s = 256; s > 0; s >>= 1) {
        if (t < s) red[t] += red[t + s];
        __syncthreads();
    }
    o[t] = e / red[0];
}

__global__ void __launch_bounds__(256) scale_kernel(
    const float* __restrict__ Q, const float* __restrict__ Kmat,
    float* __restrict__ out)
{
    const int sel = blockIdx.y;
    const size_t i4 = (size_t)blockIdx.x * 256 + threadIdx.x;
    const float4* src = (const float4*)(sel ? Kmat : Q);
    const float*  w   = out + (sel ? OFF_KW : OFF_QW);
    float4*       dst = (float4*)(out + (sel ? OFF_WK : OFF_WQ));

    const size_t e = i4 * 4;
    const int b = (int)(e >> 17);
    const int l = (int)((e >> 8) & 511);
    const float s = w[b * LN + l];
    float4 v = src[i4];
    v.x *= s; v.y *= s; v.z *= s; v.w *= s;
    dst[i4] = v;
}

// ============================================================================
extern "C" void kernel_launch(void* const* d_in, const int* in_sizes, int n_in,
                              void* d_out, int out_size)
{
    (void)in_sizes; (void)n_in; (void)out_size;
    const float* Q    = (const float*)d_in[0];
    const float* Km   = (const float*)d_in[1];
    const float* Wrel = (const float*)d_in[2];
    const float* Wq   = (const float*)d_in[3];
    const float* Wk   = (const float*)d_in[4];
    const float* Wqa  = (const float*)d_in[5];
    const float* Wka  = (const float*)d_in[6];
    float* out = (float*)d_out;

    __nv_bfloat16 *q2, *k2, *qw2, *w2t, *wp2t, *qph, *qpl, *kph, *kpl;
    float *aQ, *aK, *lq, *lk;
    cudaGetSymbolAddress((void**)&q2,   g_Q2);
    cudaGetSymbolAddress((void**)&k2,   g_K2);
    cudaGetSymbolAddress((void**)&qw2,  g_Qw2);
    cudaGetSymbolAddress((void**)&w2t,  g_W2t);
    cudaGetSymbolAddress((void**)&wp2t, g_Wp2t);
    cudaGetSymbolAddress((void**)&aQ,   g_accQ);
    cudaGetSymbolAddress((void**)&aK,   g_accK);
    cudaGetSymbolAddress((void**)&qph,  g_qph);
    cudaGetSymbolAddress((void**)&qpl,  g_qpl);
    cudaGetSymbolAddress((void**)&kph,  g_kph);
    cudaGetSymbolAddress((void**)&kpl,  g_kpl);
    cudaGetSymbolAddress((void**)&lq,   g_logit_q);
    cudaGetSymbolAddress((void**)&lk,   g_logit_k);

    cudaFuncSetAttribute(qw_mma_kernel,    cudaFuncAttributeMaxDynamicSharedMemorySize, SMEM_MMA);
    cudaFuncSetAttribute(proj_slim_kernel, cudaFuncAttributeMaxDynamicSharedMemorySize, SMEM_SLIM);
    cudaFuncSetAttribute(rel_fused_kernel, cudaFuncAttributeMaxDynamicSharedMemorySize, SMEM_FUSED);

    const dim3 blk(256);
    // compact [hi|lo] splits of inputs + weight transposes
    split_kernel<<<dim3((BN * LN * DN) / 4 / 256, 2), blk>>>(Q, Km, q2, k2);
    prep_w2t<<<256, blk>>>(Wrel, w2t);
    prep_wp<<<128, blk>>>(Wq, Wk, wp2t);
    // projections -> accumulator base values + bf16 hi/lo copies
    proj_slim_kernel<<<dim3(512, 2), blk, SMEM_SLIM>>>(
        q2, k2, wp2t, aQ, aK, qph, qpl, kph, kpl);
    // Qw (MMA, epilogue re-splits to compact bf16 hi/lo)
    qw_mma_kernel<<<dim3(512, 2), blk, SMEM_MMA>>>(q2, w2t, qw2);
    // fused rel + both score GEMMs -> vector REDs into accumulators
    rel_fused_kernel<<<dim3(4, 4, BN), blk, SMEM_FUSED>>>(qw2, k2, kph, kpl, qph, qpl, aQ, aK);
    // tanh + @W_att -> logits
    att_reduce_kernel<<<dim3(BN * LN / 8, 2), blk>>>(aQ, aK, Wqa, Wka, lq, lk);
    // softmax -> weights in d_out
    softmax_kernel<<<dim3(BN, 2), 512>>>(lq, lk, out);
    // weighted outputs
    scale_kernel<<<dim3((BN * LN * DN) / 4 / 256, 2), 256>>>(Q, Km, out);
}

// round 12
// speedup vs baseline: 2.8502x; 1.0025x over previous
#include <cuda_runtime.h>
#include <cuda_bf16.h>
#include <math.h>
#include <stdint.h>

// Problem dims
#define BN 128
#define LN 512
#define DN 256
#define AN 64
#define KS 512   // compact split storage: [hi | lo] x 256; 12-stage schedule via maps

// Output layout (concatenated, reference tuple order)
#define OFF_WQ  ((size_t)0)
#define OFF_WK  ((size_t)BN * LN * DN)
#define OFF_QW  ((size_t)2 * BN * LN * DN)
#define OFF_KW  (OFF_QW + (size_t)BN * LN)

// -------- scratch (device globals; no allocation allowed) --------
__device__ __nv_bfloat16 g_Q2 [(size_t)BN * LN * KS];    // [hi|lo] of Q
__device__ __nv_bfloat16 g_K2 [(size_t)BN * LN * KS];    // [hi|lo] of K
__device__ __nv_bfloat16 g_Qw2[(size_t)BN * LN * KS];    // [hi|lo] of Qw
__device__ __nv_bfloat16 g_W2t[(size_t)DN * KS];         // W_rel^T [hi|lo]
__device__ __nv_bfloat16 g_Wp2t[2 * 64 * KS];            // Wq^T / Wk^T [hi|lo]
// accumulators: proj writes base value; rel_fused REDs score-GEMM terms on top
__device__ float g_accQ[(size_t)BN * LN * AN];           // q_proj + rel@kp
__device__ float g_accK[(size_t)BN * LN * AN];           // k_proj + relT@qp
__device__ __nv_bfloat16 g_qph[(size_t)BN * LN * AN], g_qpl[(size_t)BN * LN * AN];
__device__ __nv_bfloat16 g_kph[(size_t)BN * LN * AN], g_kpl[(size_t)BN * LN * AN];
__device__ float g_logit_q[BN * LN];
__device__ float g_logit_k[BN * LN];

// ======================= helpers (baseline PTX only) =======================
__device__ __forceinline__ uint32_t smem_to_u32(const void* p) {
    uint32_t a;
    asm("{ .reg .u64 t; cvta.to.shared.u64 t, %1; cvt.u32.u64 %0, t; }" : "=r"(a) : "l"(p));
    return a;
}
#define SMEM_SWIZZLE_128B(o) ((o) ^ (((o) >> 3) & 0x70))

__device__ __forceinline__ void cp_async16(uint32_t saddr, const void* g) {
    asm volatile("cp.async.cg.shared.global [%0], [%1], 16;" :: "r"(saddr), "l"(g));
}
#define CP_COMMIT  asm volatile("cp.async.commit_group;" ::: "memory")
#define CP_WAIT(n) asm volatile("cp.async.wait_group %0;" :: "n"(n) : "memory")

__device__ __forceinline__ void ldmatrix_x4(uint32_t& r0, uint32_t& r1, uint32_t& r2,
                                            uint32_t& r3, uint32_t addr) {
    asm volatile("ldmatrix.sync.aligned.m8n8.x4.shared.b16 {%0,%1,%2,%3}, [%4];"
                 : "=r"(r0), "=r"(r1), "=r"(r2), "=r"(r3) : "r"(addr));
}
__device__ __forceinline__ void ldmatrix_x4_trans(uint32_t& r0, uint32_t& r1, uint32_t& r2,
                                                  uint32_t& r3, uint32_t addr) {
    asm volatile("ldmatrix.sync.aligned.m8n8.x4.trans.shared.b16 {%0,%1,%2,%3}, [%4];"
                 : "=r"(r0), "=r"(r1), "=r"(r2), "=r"(r3) : "r"(addr));
}
__device__ __forceinline__ void mma_bf16(float* c, uint32_t a0, uint32_t a1, uint32_t a2,
                                         uint32_t a3, uint32_t b0, uint32_t b1) {
    asm volatile(
        "mma.sync.aligned.m16n8k16.row.col.f32.bf16.bf16.f32 "
        "{%0,%1,%2,%3}, {%4,%5,%6,%7}, {%8,%9}, {%0,%1,%2,%3};"
        : "+f"(c[0]), "+f"(c[1]), "+f"(c[2]), "+f"(c[3])
        : "r"(a0), "r"(a1), "r"(a2), "r"(a3), "r"(b0), "r"(b1));
}
// vector fp32 reduction (sm_90+ baseline PTX feature)
__device__ __forceinline__ void red_add_v2(float* addr, float a, float b) {
    asm volatile("red.global.add.v2.f32 [%0], {%1, %2};"
                 :: "l"(addr), "f"(a), "f"(b) : "memory");
}

__device__ __forceinline__ void split2(float x, __nv_bfloat16& hi, __nv_bfloat16& lo) {
    hi = __float2bfloat16(x);
    lo = __float2bfloat16(x - __bfloat162float(hi));
}
union BF2 { __nv_bfloat16 h[2]; uint32_t u; };

// Stage maps: logical stage s (0..11) -> physical 64-col chunk in [hi|lo] storage.
// Pairing: s 0-3 hi*hi, 4-7 lo*hi, 8-11 hi*lo.
__device__ __forceinline__ int amap(int s) { return s < 8 ? s : s - 8; }
__device__ __forceinline__ int bmap(int s) { return s < 4 ? s : s - 4; }

// ======================= warp-MMA mainloop (128x128 tile) =======================
// 3-stage cp.async ring, ONE __syncthreads per stage.
#define NSTAGE  12
#define STAGE_BYTES 32768
#define SMEM_MMA (3 * STAGE_BYTES)

__device__ __forceinline__ void load_stage(uint32_t sbase,
    const __nv_bfloat16* __restrict__ A, const __nv_bfloat16* __restrict__ B,
    int s, int tid)
{
    const __nv_bfloat16* Ak = A + amap(s) * 64;
    const __nv_bfloat16* Bk = B + bmap(s) * 64;
#pragma unroll
    for (int i = 0; i < 4; ++i) {
        const int idx = tid + i * 256;            // 0..1023 16B chunks
        const int r = idx >> 3, c = idx & 7;
        const uint32_t off = SMEM_SWIZZLE_128B((uint32_t)(r * 128 + c * 16));
        cp_async16(sbase + off, Ak + (size_t)r * KS + c * 8);
        cp_async16(sbase + 16384 + off, Bk + (size_t)r * KS + c * 8);
    }
}

__device__ __forceinline__ void warp_mma_main(
    const __nv_bfloat16* __restrict__ A, const __nv_bfloat16* __restrict__ B,
    uint32_t smem_base, int tid, float acc[4][4][4])
{
    const int wid = tid >> 5, lane = tid & 31;
    const int mw = (wid >> 2) * 64, nw = (wid & 3) * 32;

    load_stage(smem_base + 0 * STAGE_BYTES, A, B, 0, tid); CP_COMMIT;
    load_stage(smem_base + 1 * STAGE_BYTES, A, B, 1, tid); CP_COMMIT;

    for (int s = 0; s < NSTAGE; ++s) {
        CP_WAIT(1);            // stage s group complete (groups retire in order)
        __syncthreads();       // publish stage s; fences reuse of buf[(s+2)%3]
        if (s + 2 < NSTAGE)
            load_stage(smem_base + ((s + 2) % 3) * STAGE_BYTES, A, B, s + 2, tid);
        CP_COMMIT;

        const uint32_t sA = smem_base + (s % 3) * STAGE_BYTES;
        const uint32_t sB = sA + 16384;
#pragma unroll
        for (int kk = 0; kk < 64; kk += 16) {
            uint32_t a[4][4], b[4][2];
#pragma unroll
            for (int mf = 0; mf < 4; ++mf) {
                const uint32_t off = SMEM_SWIZZLE_128B((uint32_t)(
                    (mw + mf * 16 + (lane & 15)) * 128 + kk * 2 + ((lane >> 4) << 4)));
                ldmatrix_x4(a[mf][0], a[mf][1], a[mf][2], a[mf][3], sA + off);
            }
#pragma unroll
            for (int nb = 0; nb < 2; ++nb) {
                const int row = nw + nb * 16 + ((lane >> 4) & 1) * 8 + (lane & 7);
                const int kof = kk * 2 + (((lane >> 3) & 1) << 4);
                const uint32_t off = SMEM_SWIZZLE_128B((uint32_t)(row * 128 + kof));
                ldmatrix_x4(b[nb * 2][0], b[nb * 2][1], b[nb * 2 + 1][0], b[nb * 2 + 1][1],
                            sB + off);
            }
#pragma unroll
            for (int mf = 0; mf < 4; ++mf)
#pragma unroll
                for (int nf = 0; nf < 4; ++nf)
                    mma_bf16(acc[mf][nf], a[mf][0], a[mf][1], a[mf][2], a[mf][3],
                             b[nf][0], b[nf][1]);
        }
    }
    __syncthreads();   // all warps done with ring before caller reuses smem
}

// ======================= fused rel + att-score kernel =======================
#define R_PITCH  272          // 128 cols bf16 (256B) + 16B pad
#define P_PITCH  144          // 64 cols bf16 (128B) + 16B pad
#define RH_OFF   0
#define RL_OFF   34816
#define PJH_OFF  69632
#define PJL_OFF  88064
#define SMEM_FUSED 106496     // >= 3*STAGE_BYTES mainloop ring

__global__ void __launch_bounds__(256, 2) rel_fused_kernel(
    const __nv_bfloat16* __restrict__ Qw2, const __nv_bfloat16* __restrict__ K2,
    const __nv_bfloat16* __restrict__ kph, const __nv_bfloat16* __restrict__ kpl,
    const __nv_bfloat16* __restrict__ qph, const __nv_bfloat16* __restrict__ qpl,
    float* __restrict__ accQ, float* __restrict__ accK)
{
    extern __shared__ char smem[];
    const uint32_t sb = smem_to_u32(smem);
    const int tid = threadIdx.x, wid = tid >> 5, lane = tid & 31;
    const int mt = blockIdx.x, nt = blockIdx.y, b = blockIdx.z;
    const int m0 = mt * 128, n0 = nt * 128;

    float acc[4][4][4] = {};
    warp_mma_main(Qw2 + ((size_t)b * LN + m0) * KS,
                  K2  + ((size_t)b * LN + n0) * KS, sb, tid, acc);

    // prefetch kp hi/lo tiles (rows n0..n0+127) while storing rel to smem
    {
        const __nv_bfloat16* kh = kph + ((size_t)b * LN + n0) * AN;
        const __nv_bfloat16* kl = kpl + ((size_t)b * LN + n0) * AN;
#pragma unroll
        for (int i = 0; i < 4; ++i) {
            const int idx = tid + i * 256, r = idx >> 3, c = idx & 7;
            cp_async16(sb + PJH_OFF + r * P_PITCH + c * 16, kh + (size_t)r * AN + c * 8);
            cp_async16(sb + PJL_OFF + r * P_PITCH + c * 16, kl + (size_t)r * AN + c * 8);
        }
        CP_COMMIT;
    }

    // tanh + hi/lo split -> smem rel tiles
    const int mw = (wid >> 2) * 64, nw = (wid & 3) * 32;
    const int lr = lane >> 2, lc = (lane & 3) * 2;
#pragma unroll
    for (int mf = 0; mf < 4; ++mf)
#pragma unroll
        for (int nf = 0; nf < 4; ++nf)
#pragma unroll
            for (int p = 0; p < 2; ++p) {
                const int rr = mw + mf * 16 + lr + p * 8;
                const int cc = nw + nf * 8 + lc;
                BF2 H, L;
                split2(tanhf(acc[mf][nf][2 * p + 0]), H.h[0], L.h[0]);
                split2(tanhf(acc[mf][nf][2 * p + 1]), H.h[1], L.h[1]);
                *(uint32_t*)(smem + RH_OFF + rr * R_PITCH + cc * 2) = H.u;
                *(uint32_t*)(smem + RL_OFF + rr * R_PITCH + cc * 2) = L.u;
            }
    CP_WAIT(0);
    __syncthreads();

    // ---- C2[m][a] = sum_n rel[m][n] * kp[n0+n][a]
    // 3-term split with frags loaded ONCE per kk: aH*bH + aL*bH + aH*bL
    float c2[8][4] = {};
#pragma unroll
    for (int kk = 0; kk < 128; kk += 16) {
        uint32_t aH0, aH1, aH2, aH3, aL0, aL1, aL2, aL3;
        const uint32_t aoff = (16 * wid + (lane & 15)) * R_PITCH
                            + (kk + ((lane >> 4) << 3)) * 2;
        ldmatrix_x4(aH0, aH1, aH2, aH3, sb + RH_OFF + aoff);
        ldmatrix_x4(aL0, aL1, aL2, aL3, sb + RL_OFF + aoff);
#pragma unroll
        for (int ab = 0; ab < 4; ++ab) {
            uint32_t h0, h1, h2, h3, l0, l1, l2, l3;
            const uint32_t boff = (kk + (lane & 15)) * P_PITCH
                                + (ab * 16 + ((lane >> 4) << 3)) * 2;
            ldmatrix_x4_trans(h0, h1, h2, h3, sb + PJH_OFF + boff);
            ldmatrix_x4_trans(l0, l1, l2, l3, sb + PJL_OFF + boff);
            mma_bf16(c2[2 * ab],     aH0, aH1, aH2, aH3, h0, h1);
            mma_bf16(c2[2 * ab],     aL0, aL1, aL2, aL3, h0, h1);
            mma_bf16(c2[2 * ab],     aH0, aH1, aH2, aH3, l0, l1);
            mma_bf16(c2[2 * ab + 1], aH0, aH1, aH2, aH3, h2, h3);
            mma_bf16(c2[2 * ab + 1], aL0, aL1, aL2, aL3, h2, h3);
            mma_bf16(c2[2 * ab + 1], aH0, aH1, aH2, aH3, l2, l3);
        }
    }
    {
        float* base = accQ + ((size_t)b * LN + m0 + 16 * wid) * AN;
#pragma unroll
        for (int j = 0; j < 8; ++j) {
            const int col = j * 8 + lc;
            red_add_v2(base + (size_t)lr * AN + col,       c2[j][0], c2[j][1]);
            red_add_v2(base + (size_t)(lr + 8) * AN + col, c2[j][2], c2[j][3]);
        }
    }
    __syncthreads();   // all warps done reading kp tiles

    // load qp hi/lo tiles (rows m0..m0+127) into same region
    {
        const __nv_bfloat16* qh = qph + ((size_t)b * LN + m0) * AN;
        const __nv_bfloat16* ql = qpl + ((size_t)b * LN + m0) * AN;
#pragma unroll
        for (int i = 0; i < 4; ++i) {
            const int idx = tid + i * 256, r = idx >> 3, c = idx & 7;
            cp_async16(sb + PJH_OFF + r * P_PITCH + c * 16, qh + (size_t)r * AN + c * 8);
            cp_async16(sb + PJL_OFF + r * P_PITCH + c * 16, ql + (size_t)r * AN + c * 8);
        }
        CP_COMMIT; CP_WAIT(0);
    }
    __syncthreads();

    // ---- C3[n][a] = sum_m rel[m][n] * qp[m0+m][a]  (A = rel^T via ldmatrix.trans)
    float c3[8][4] = {};
    const int g = lane >> 3;
#pragma unroll
    for (int kk = 0; kk < 128; kk += 16) {
        uint32_t aH0, aH1, aH2, aH3, aL0, aL1, aL2, aL3;
        const uint32_t aoff = (kk + ((g >> 1) << 3) + (lane & 7)) * R_PITCH
                            + (16 * wid + ((g & 1) << 3)) * 2;
        ldmatrix_x4_trans(aH0, aH1, aH2, aH3, sb + RH_OFF + aoff);
        ldmatrix_x4_trans(aL0, aL1, aL2, aL3, sb + RL_OFF + aoff);
#pragma unroll
        for (int ab = 0; ab < 4; ++ab) {
            uint32_t h0, h1, h2, h3, l0, l1, l2, l3;
            const uint32_t boff = (kk + (lane & 15)) * P_PITCH
                                + (ab * 16 + ((lane >> 4) << 3)) * 2;
            ldmatrix_x4_trans(h0, h1, h2, h3, sb + PJH_OFF + boff);
            ldmatrix_x4_trans(l0, l1, l2, l3, sb + PJL_OFF + boff);
            mma_bf16(c3[2 * ab],     aH0, aH1, aH2, aH3, h0, h1);
            mma_bf16(c3[2 * ab],     aL0, aL1, aL2, aL3, h0, h1);
            mma_bf16(c3[2 * ab],     aH0, aH1, aH2, aH3, l0, l1);
            mma_bf16(c3[2 * ab + 1], aH0, aH1, aH2, aH3, h2, h3);
            mma_bf16(c3[2 * ab + 1], aL0, aL1, aL2, aL3, h2, h3);
            mma_bf16(c3[2 * ab + 1], aH0, aH1, aH2, aH3, l2, l3);
        }
    }
    {
        float* base = accK + ((size_t)b * LN + n0 + 16 * wid) * AN;
#pragma unroll
        for (int j = 0; j < 8; ++j) {
            const int col = j * 8 + lc;
            red_add_v2(base + (size_t)lr * AN + col,       c3[j][0], c3[j][1]);
            red_add_v2(base + (size_t)(lr + 8) * AN + col, c3[j][2], c3[j][3]);
        }
    }
}

// ======================= Qw2 = split(Q2 @ W2t^T) =======================
// grid (2, 512): n-tile varies FASTEST so the two CTAs sharing one Q2 m-tile
// are wave-adjacent -> second Q2 read is an L2 hit.
__global__ void __launch_bounds__(256, 2) qw_mma_kernel(
    const __nv_bfloat16* __restrict__ Q2, const __nv_bfloat16* __restrict__ W2t,
    __nv_bfloat16* __restrict__ Qw2)
{
    extern __shared__ char smem[];
    const uint32_t smem_base = smem_to_u32(smem);
    const int tid = threadIdx.x;
    const int m0 = blockIdx.y * 128, n0 = blockIdx.x * 128;

    float acc[4][4][4] = {};
    warp_mma_main(Q2 + (size_t)m0 * KS, W2t + (size_t)n0 * KS, smem_base, tid, acc);

    const int wid = tid >> 5, lane = tid & 31;
    const int mw = (wid >> 2) * 64, nw = (wid & 3) * 32;
    const int lr = lane >> 2, lc = (lane & 3) * 2;
#pragma unroll
    for (int mf = 0; mf < 4; ++mf) {
        const int row = m0 + mw + mf * 16 + lr;
#pragma unroll
        for (int nf = 0; nf < 4; ++nf) {
            const int col = n0 + nw + nf * 8 + lc;
#pragma unroll
            for (int p = 0; p < 2; ++p) {
                const int rr = row + p * 8;
                BF2 H, L;
                split2(acc[mf][nf][2 * p + 0], H.h[0], L.h[0]);
                split2(acc[mf][nf][2 * p + 1], H.h[1], L.h[1]);
                __nv_bfloat16* o = Qw2 + (size_t)rr * KS + col;
                *(uint32_t*)(o)       = H.u;
                *(uint32_t*)(o + 256) = L.u;
            }
        }
    }
}

// ======================= slim projection kernel (N=64) ======================
// 3-stage ring. Stage = A(16KB) + W(8KB) = 24KB.
#define SLIM_STAGE 24576
#define SMEM_SLIM  (3 * SLIM_STAGE)

__device__ __forceinline__ void load_stage_slim(uint32_t sbase,
    const __nv_bfloat16* __restrict__ A, const __nv_bfloat16* __restrict__ W,
    int s, int tid)
{
    const __nv_bfloat16* Ak = A + amap(s) * 64;
    const __nv_bfloat16* Wk = W + bmap(s) * 64;
#pragma unroll
    for (int i = 0; i < 4; ++i) {
        const int idx = tid + i * 256;            // 1024 chunks: A 128 rows x 8
        const int r = idx >> 3, c = idx & 7;
        const uint32_t off = SMEM_SWIZZLE_128B((uint32_t)(r * 128 + c * 16));
        cp_async16(sbase + off, Ak + (size_t)r * KS + c * 8);
    }
#pragma unroll
    for (int i = 0; i < 2; ++i) {
        const int idx = tid + i * 256;            // 512 chunks: W 64 rows x 8
        const int r = idx >> 3, c = idx & 7;
        const uint32_t off = SMEM_SWIZZLE_128B((uint32_t)(r * 128 + c * 16));
        cp_async16(sbase + 16384 + off, Wk + (size_t)r * KS + c * 8);
    }
}

__global__ void __launch_bounds__(256, 3) proj_slim_kernel(
    const __nv_bfloat16* __restrict__ Q2, const __nv_bfloat16* __restrict__ K2,
    const __nv_bfloat16* __restrict__ Wp2t,
    float* __restrict__ accQ, float* __restrict__ accK,
    __nv_bfloat16* __restrict__ qph, __nv_bfloat16* __restrict__ qpl,
    __nv_bfloat16* __restrict__ kph, __nv_bfloat16* __restrict__ kpl)
{
    extern __shared__ char smem[];
    const uint32_t sb = smem_to_u32(smem);
    const int tid = threadIdx.x, wid = tid >> 5, lane = tid & 31;
    const int side = blockIdx.y;
    const int m0 = blockIdx.x * 128;
    const __nv_bfloat16* A = (side ? K2 : Q2) + (size_t)m0 * KS;
    const __nv_bfloat16* W = Wp2t + (size_t)side * 64 * KS;
    float* pf = side ? accK : accQ;
    __nv_bfloat16* ph = side ? kph : qph;
    __nv_bfloat16* pl = side ? kpl : qpl;

    const int mw = (wid >> 1) * 32, nw = (wid & 1) * 32;

    float acc[2][4][4] = {};
    load_stage_slim(sb + 0 * SLIM_STAGE, A, W, 0, tid); CP_COMMIT;
    load_stage_slim(sb + 1 * SLIM_STAGE, A, W, 1, tid); CP_COMMIT;

    for (int s = 0; s < NSTAGE; ++s) {
        CP_WAIT(1);
        __syncthreads();
        if (s + 2 < NSTAGE)
            load_stage_slim(sb + ((s + 2) % 3) * SLIM_STAGE, A, W, s + 2, tid);
        CP_COMMIT;

        const uint32_t sA = sb + (s % 3) * SLIM_STAGE;
        const uint32_t sW = sA + 16384;
#pragma unroll
        for (int kk = 0; kk < 64; kk += 16) {
            uint32_t a[2][4], b[4][2];
#pragma unroll
            for (int mf = 0; mf < 2; ++mf) {
                const uint32_t off = SMEM_SWIZZLE_128B((uint32_t)(
                    (mw + mf * 16 + (lane & 15)) * 128 + kk * 2 + ((lane >> 4) << 4)));
                ldmatrix_x4(a[mf][0], a[mf][1], a[mf][2], a[mf][3], sA + off);
            }
#pragma unroll
            for (int nb = 0; nb < 2; ++nb) {
                const int row = nw + nb * 16 + ((lane >> 4) & 1) * 8 + (lane & 7);
                const int kof = kk * 2 + (((lane >> 3) & 1) << 4);
                const uint32_t off = SMEM_SWIZZLE_128B((uint32_t)(row * 128 + kof));
                ldmatrix_x4(b[nb * 2][0], b[nb * 2][1], b[nb * 2 + 1][0], b[nb * 2 + 1][1],
                            sW + off);
            }
#pragma unroll
            for (int mf = 0; mf < 2; ++mf)
#pragma unroll
                for (int nf = 0; nf < 4; ++nf)
                    mma_bf16(acc[mf][nf], a[mf][0], a[mf][1], a[mf][2], a[mf][3],
                             b[nf][0], b[nf][1]);
        }
    }

    const int lr = lane >> 2, lc = (lane & 3) * 2;
#pragma unroll
    for (int mf = 0; mf < 2; ++mf) {
#pragma unroll
        for (int nf = 0; nf < 4; ++nf) {
            const int col = nw + nf * 8 + lc;
#pragma unroll
            for (int p = 0; p < 2; ++p) {
                const int row = m0 + mw + mf * 16 + lr + p * 8;
                const float v0 = acc[mf][nf][2 * p + 0];
                const float v1 = acc[mf][nf][2 * p + 1];
                *(float2*)(pf + (size_t)row * AN + col) = make_float2(v0, v1);
                BF2 H, L;
                split2(v0, H.h[0], L.h[0]);
                split2(v1, H.h[1], L.h[1]);
                *(uint32_t*)(ph + (size_t)row * AN + col) = H.u;
                *(uint32_t*)(pl + (size_t)row * AN + col) = L.u;
            }
        }
    }
}

// ======================= split / prep kernels =======================
__global__ void __launch_bounds__(256) split_kernel(
    const float* __restrict__ Q, const float* __restrict__ Kmat,
    __nv_bfloat16* __restrict__ Q2, __nv_bfloat16* __restrict__ K2)
{
    const int sel = blockIdx.y;
    const float* src = sel ? Kmat : Q;
    __nv_bfloat16* dst = sel ? K2 : Q2;
    const size_t i4 = (size_t)blockIdx.x * 256 + threadIdx.x;
    const size_t row = i4 >> 6;
    const int c = (int)(i4 & 63) * 4;
    float4 v = ((const float4*)src)[i4];
    union { __nv_bfloat16 b[4]; uint2 u; } h, l;
    split2(v.x, h.b[0], l.b[0]); split2(v.y, h.b[1], l.b[1]);
    split2(v.z, h.b[2], l.b[2]); split2(v.w, h.b[3], l.b[3]);
    __nv_bfloat16* o = dst + row * KS + c;
    *(uint2*)(o)       = h.u;
    *(uint2*)(o + 256) = l.u;
}

__global__ void __launch_bounds__(256) prep_w2t(
    const float* __restrict__ Wrel, __nv_bfloat16* __restrict__ W2t)
{
    const int idx = blockIdx.x * 256 + threadIdx.x;   // 65536
    const int d = idx >> 8, n = idx & 255;
    __nv_bfloat16 hi, lo;
    split2(Wrel[d * 256 + n], hi, lo);
    W2t[(size_t)n * KS + d]       = hi;
    W2t[(size_t)n * KS + 256 + d] = lo;
}

__global__ void __launch_bounds__(256) prep_wp(
    const float* __restrict__ Wq, const float* __restrict__ Wk,
    __nv_bfloat16* __restrict__ Wp2t)
{
    const int idx = blockIdx.x * 256 + threadIdx.x;   // 32768
    const int side = idx >> 14;
    const int d = (idx >> 6) & 255, a = idx & 63;
    const float* W = side ? Wk : Wq;
    __nv_bfloat16 hi, lo;
    split2(W[d * 64 + a], hi, lo);
    __nv_bfloat16* slab = Wp2t + (size_t)side * 64 * KS;
    slab[(size_t)a * KS + d]       = hi;
    slab[(size_t)a * KS + 256 + d] = lo;
}

// ======================= tanh + dot reduce (reads accumulators) =============
__global__ void __launch_bounds__(256) att_reduce_kernel(
    const float* __restrict__ accQ, const float* __restrict__ accK,
    const float* __restrict__ Wqa, const float* __restrict__ Wka,
    float* __restrict__ lq, float* __restrict__ lk)
{
    const int side = blockIdx.y;
    const int wid = threadIdx.x >> 5, lane = threadIdx.x & 31;
    const size_t gm = (size_t)blockIdx.x * 8 + wid;   // b*LN + m
    const float* acc = side ? accK : accQ;
    const float* w   = side ? Wka  : Wqa;
    float* out       = side ? lk   : lq;

    float s = 0.f;
#pragma unroll
    for (int h = 0; h < 2; ++h) {
        const int a = lane + h * 32;
        s += tanhf(acc[gm * AN + a]) * w[a];
    }
#pragma unroll
    for (int o = 16; o; o >>= 1) s += __shfl_xor_sync(0xFFFFFFFFu, s, o);
    if (lane == 0) out[gm] = s;
}

// ============================================================================
__global__ void __launch_bounds__(512) softmax_kernel(
    const float* __restrict__ lq, const float* __restrict__ lk,
    float* __restrict__ out)
{
    __shared__ float red[512];
    const int b = blockIdx.x, sel = blockIdx.y, t = threadIdx.x;
    const float* l = (sel ? lk : lq) + (size_t)b * LN;
    float* o = out + (sel ? OFF_KW : OFF_QW) + (size_t)b * LN;

    float v = l[t];
    red[t] = v; __syncthreads();
    for (int s = 256; s > 0; s >>= 1) {
        if (t < s) red[t] = fmaxf(red[t], red[t + s]);
        __syncthreads();
    }
    const float mx = red[0];
    __syncthreads();
    const float e = expf(v - mx);
    red[t] = e; __syncthreads();
    for (int s = 256; s > 0; s >>= 1) {
        if (t < s) red[t] += red[t + s];
        __syncthreads();
    }
    o[t] = e / red[0];
}

// weighted outputs from compact bf16 [hi|lo] (exact to ~1e-5): q = hi + lo
__global__ void __launch_bounds__(256) scale_kernel(
    const __nv_bfloat16* __restrict__ Q2, const __nv_bfloat16* __restrict__ K2,
    float* __restrict__ out)
{
    const int sel = blockIdx.y;
    const size_t i4 = (size_t)blockIdx.x * 256 + threadIdx.x;
    const __nv_bfloat16* src = sel ? K2 : Q2;
    const float* w = out + (sel ? OFF_KW : OFF_QW);
    float4* dst = (float4*)(out + (sel ? OFF_WK : OFF_WQ));

    const size_t e = i4 * 4;
    const size_t row = e >> 8;            // b*LN + l
    const int c = (int)(e & 255);
    const float s = w[row];

    const __nv_bfloat16* p = src + row * KS + c;
    union { __nv_bfloat16 b[4]; uint2 u; } h, l;
    h.u = *(const uint2*)(p);
    l.u = *(const uint2*)(p + 256);
    float4 v;
    v.x = (__bfloat162float(h.b[0]) + __bfloat162float(l.b[0])) * s;
    v.y = (__bfloat162float(h.b[1]) + __bfloat162float(l.b[1])) * s;
    v.z = (__bfloat162float(h.b[2]) + __bfloat162float(l.b[2])) * s;
    v.w = (__bfloat162float(h.b[3]) + __bfloat162float(l.b[3])) * s;
    dst[i4] = v;
}

// ============================================================================
extern "C" void kernel_launch(void* const* d_in, const int* in_sizes, int n_in,
                              void* d_out, int out_size)
{
    (void)in_sizes; (void)n_in; (void)out_size;
    const float* Q    = (const float*)d_in[0];
    const float* Km   = (const float*)d_in[1];
    const float* Wrel = (const float*)d_in[2];
    const float* Wq   = (const float*)d_in[3];
    const float* Wk   = (const float*)d_in[4];
    const float* Wqa  = (const float*)d_in[5];
    const float* Wka  = (const float*)d_in[6];
    float* out = (float*)d_out;

    __nv_bfloat16 *q2, *k2, *qw2, *w2t, *wp2t, *qph, *qpl, *kph, *kpl;
    float *aQ, *aK, *lq, *lk;
    cudaGetSymbolAddress((void**)&q2,   g_Q2);
    cudaGetSymbolAddress((void**)&k2,   g_K2);
    cudaGetSymbolAddress((void**)&qw2,  g_Qw2);
    cudaGetSymbolAddress((void**)&w2t,  g_W2t);
    cudaGetSymbolAddress((void**)&wp2t, g_Wp2t);
    cudaGetSymbolAddress((void**)&aQ,   g_accQ);
    cudaGetSymbolAddress((void**)&aK,   g_accK);
    cudaGetSymbolAddress((void**)&qph,  g_qph);
    cudaGetSymbolAddress((void**)&qpl,  g_qpl);
    cudaGetSymbolAddress((void**)&kph,  g_kph);
    cudaGetSymbolAddress((void**)&kpl,  g_kpl);
    cudaGetSymbolAddress((void**)&lq,   g_logit_q);
    cudaGetSymbolAddress((void**)&lk,   g_logit_k);

    cudaFuncSetAttribute(qw_mma_kernel,    cudaFuncAttributeMaxDynamicSharedMemorySize, SMEM_MMA);
    cudaFuncSetAttribute(proj_slim_kernel, cudaFuncAttributeMaxDynamicSharedMemorySize, SMEM_SLIM);
    cudaFuncSetAttribute(rel_fused_kernel, cudaFuncAttributeMaxDynamicSharedMemorySize, SMEM_FUSED);

    const dim3 blk(256);
    // compact [hi|lo] splits of inputs + weight transposes
    split_kernel<<<dim3((BN * LN * DN) / 4 / 256, 2), blk>>>(Q, Km, q2, k2);
    prep_w2t<<<256, blk>>>(Wrel, w2t);
    prep_wp<<<128, blk>>>(Wq, Wk, wp2t);
    // projections -> accumulator base values + bf16 hi/lo copies
    proj_slim_kernel<<<dim3(512, 2), blk, SMEM_SLIM>>>(
        q2, k2, wp2t, aQ, aK, qph, qpl, kph, kpl);
    // Qw (n-tile-fastest grid for L2 reuse of Q2)
    qw_mma_kernel<<<dim3(2, 512), blk, SMEM_MMA>>>(q2, w2t, qw2);
    // fused rel + both score GEMMs -> vector REDs into accumulators
    rel_fused_kernel<<<dim3(4, 4, BN), blk, SMEM_FUSED>>>(qw2, k2, kph, kpl, qph, qpl, aQ, aK);
    // tanh + @W_att -> logits
    att_reduce_kernel<<<dim3(BN * LN / 8, 2), blk>>>(aQ, aK, Wqa, Wka, lq, lk);
    // softmax -> weights in d_out
    softmax_kernel<<<dim3(BN, 2), 512>>>(lq, lk, out);
    // weighted outputs from compact bf16
    scale_kernel<<<dim3((BN * LN * DN) / 4 / 256, 2), 256>>>(q2, k2, out);
}